// round 7
// baseline (speedup 1.0000x reference)
#include <cuda_runtime.h>
#include <cstdint>

#define B_   4
#define T_   2048
#define D_   512
#define H_   8
#define DK_  64
#define BT_  (B_ * T_)
#define DFF_ 2048

// ---------------- scratch (static device globals; no allocations) ----------
__device__ float g_h [BT_ * D_];
__device__ float g_q [BT_ * D_];   // [B,T,H,DK] flattened = [BT, 512]
__device__ float g_k [BT_ * D_];
__device__ float g_v [BT_ * D_];
__device__ float g_o [BT_ * D_];   // attention output, concat-head layout
__device__ float g_x1[BT_ * D_];
__device__ float g_h2[BT_ * D_];
__device__ float g_ff[BT_ * DFF_];

// ---------------- LayerNorm: one block per row of 512 ----------------------
__global__ __launch_bounds__(128) void ln_kernel(
    const float* __restrict__ x, const float* __restrict__ g,
    const float* __restrict__ b, float* __restrict__ out)
{
    const int row = blockIdx.x;
    const int tid = threadIdx.x;                 // 128 threads * float4 = 512
    float4 v = ((const float4*)(x + (size_t)row * D_))[tid];
    float s  = v.x + v.y + v.z + v.w;
    float ss = v.x * v.x + v.y * v.y + v.z * v.z + v.w * v.w;
    #pragma unroll
    for (int o = 16; o > 0; o >>= 1) {
        s  += __shfl_xor_sync(0xffffffffu, s,  o);
        ss += __shfl_xor_sync(0xffffffffu, ss, o);
    }
    __shared__ float sh_s[4], sh_ss[4];
    if ((tid & 31) == 0) { sh_s[tid >> 5] = s; sh_ss[tid >> 5] = ss; }
    __syncthreads();
    const float tot  = sh_s[0] + sh_s[1] + sh_s[2] + sh_s[3];
    const float tots = sh_ss[0] + sh_ss[1] + sh_ss[2] + sh_ss[3];
    const float mu   = tot  * (1.0f / D_);
    const float var  = tots * (1.0f / D_) - mu * mu;
    const float rstd = rsqrtf(var + 1e-5f);
    float4 gv = ((const float4*)g)[tid];
    float4 bv = ((const float4*)b)[tid];
    float4 r;
    r.x = (v.x - mu) * rstd * gv.x + bv.x;
    r.y = (v.y - mu) * rstd * gv.y + bv.y;
    r.z = (v.z - mu) * rstd * gv.z + bv.z;
    r.w = (v.w - mu) * rstd * gv.w + bv.w;
    ((float4*)(out + (size_t)row * D_))[tid] = r;
}

// ---------------- tf32 helpers ----------------------------------------------
__device__ __forceinline__ uint32_t f2tf32(float x) {
    uint32_t u;
    asm("cvt.rna.tf32.f32 %0, %1;" : "=r"(u) : "f"(x));
    return u;
}

__device__ __forceinline__ uint4 f2tf32x4(float4 v) {
    uint4 u;
    u.x = f2tf32(v.x); u.y = f2tf32(v.y);
    u.z = f2tf32(v.z); u.w = f2tf32(v.w);
    return u;
}

__device__ __forceinline__ void mma_tf32(float* d, const uint32_t* a,
                                         const uint32_t* b) {
    asm volatile(
        "mma.sync.aligned.m16n8k8.row.col.f32.tf32.tf32.f32 "
        "{%0,%1,%2,%3}, {%4,%5,%6,%7}, {%8,%9}, {%0,%1,%2,%3};"
        : "+f"(d[0]), "+f"(d[1]), "+f"(d[2]), "+f"(d[3])
        : "r"(a[0]), "r"(a[1]), "r"(a[2]), "r"(a[3]),
          "r"(b[0]), "r"(b[1]));
}

// ---------------- tf32 tensor-core GEMM, 128x128 tile, pipelined -----------
// C[row, col] = sum_k A[row, k] * B(k, col) (+bias[col]) (+res[row,col]) (relu)
// Weight addressing: addr(k, col) = Bw + (col>>6)*cstride + k*ldb + (col&63)
// 8 warps: warp tile 64x32; mma m16n8k8, BK=32, 2-stage smem double buffer
// with register-staged global loads (LDG for stage i+1 issued before mma i).
#define PAD_A 36
#define PAD_B 136
#define GEMM_SMEM ((2 * 128 * PAD_A + 2 * 32 * PAD_B) * 4)

__global__ __launch_bounds__(256, 2) void gemm_kernel(
    const float* __restrict__ A, int lda,
    const float* __restrict__ Bw, int cstride, int ldb,
    const float* __restrict__ bias,
    const float* __restrict__ res,
    float* __restrict__ C, int ldc,
    int K, int relu)
{
    extern __shared__ float smg[];
    float* As = smg;                          // [2][128][PAD_A]
    float* Bs = smg + 2 * 128 * PAD_A;        // [2][32][PAD_B]

    const int tid  = threadIdx.x;
    const int lane = tid & 31;
    const int wid  = tid >> 5;
    const int wm   = wid & 1;        // row block of 64
    const int wn   = wid >> 1;       // col block of 32
    const int row0 = blockIdx.y * 128;
    const int col0 = blockIdx.x * 128;
    const float* B0 = Bw + (size_t)(col0 >> 6) * cstride;  // cols [col0, +64)
    const float* B1 = B0 + cstride;                        // cols [+64, +128)

    const int r = lane >> 2;         // 0..7
    const int c = lane & 3;          // 0..3

    float acc[4][4][4];
    #pragma unroll
    for (int mi = 0; mi < 4; mi++)
        #pragma unroll
        for (int ni = 0; ni < 4; ni++)
            acc[mi][ni][0] = acc[mi][ni][1] = acc[mi][ni][2] = acc[mi][ni][3] = 0.f;

    // per-thread staged tile (A: 4 float4, B: 4 float4)
    float4 areg[4], breg[4];

    auto ldg_stage = [&](int k0) {
        #pragma unroll
        for (int i = 0; i < 4; i++) {
            int idx = tid + i * 256;            // A: 0..1023 float4s
            int m   = idx >> 3;                 // 0..127
            int kk  = (idx & 7) * 4;            // 0..28
            areg[i] = *(const float4*)(A + (size_t)(row0 + m) * lda + k0 + kk);
        }
        #pragma unroll
        for (int i = 0; i < 4; i++) {
            int idx = tid + i * 256;            // B: 0..1023 float4s
            int kk  = idx >> 5;                 // 0..31
            int n4  = (idx & 31) * 4;           // 0..124
            const float* src = (n4 < 64)
                ? (B0 + (size_t)(k0 + kk) * ldb + n4)
                : (B1 + (size_t)(k0 + kk) * ldb + (n4 - 64));
            breg[i] = *(const float4*)src;
        }
    };

    ldg_stage(0);
    const int niter = K >> 5;

    for (int it = 0; it < niter; it++) {
        const int cur = it & 1;
        float* Ac = As + cur * 128 * PAD_A;
        float* Bc = Bs + cur * 32 * PAD_B;

        __syncthreads();                        // buffer cur free (reads done)
        #pragma unroll
        for (int i = 0; i < 4; i++) {
            int idx = tid + i * 256;
            int m   = idx >> 3;
            int kk  = (idx & 7) * 4;
            *(uint4*)&Ac[m * PAD_A + kk] = f2tf32x4(areg[i]);
        }
        #pragma unroll
        for (int i = 0; i < 4; i++) {
            int idx = tid + i * 256;
            int kk  = idx >> 5;
            int n4  = (idx & 31) * 4;
            *(uint4*)&Bc[kk * PAD_B + n4] = f2tf32x4(breg[i]);
        }
        __syncthreads();

        if (it + 1 < niter) ldg_stage((it + 1) * 32);   // hidden under mma

        #pragma unroll
        for (int ks = 0; ks < 32; ks += 8) {
            uint32_t af[4][4], bf[4][2];
            #pragma unroll
            for (int mi = 0; mi < 4; mi++) {
                int m = wm * 64 + mi * 16 + r;
                af[mi][0] = __float_as_uint(Ac[m * PAD_A + ks + c]);
                af[mi][1] = __float_as_uint(Ac[(m + 8) * PAD_A + ks + c]);
                af[mi][2] = __float_as_uint(Ac[m * PAD_A + ks + c + 4]);
                af[mi][3] = __float_as_uint(Ac[(m + 8) * PAD_A + ks + c + 4]);
            }
            #pragma unroll
            for (int ni = 0; ni < 4; ni++) {
                int n = wn * 32 + ni * 8 + r;
                bf[ni][0] = __float_as_uint(Bc[(ks + c) * PAD_B + n]);
                bf[ni][1] = __float_as_uint(Bc[(ks + c + 4) * PAD_B + n]);
            }
            #pragma unroll
            for (int mi = 0; mi < 4; mi++)
                #pragma unroll
                for (int ni = 0; ni < 4; ni++)
                    mma_tf32(acc[mi][ni], af[mi], bf[ni]);
        }
    }

    // --- epilogue: bias (+res) (relu) ---
    #pragma unroll
    for (int mi = 0; mi < 4; mi++) {
        const int row_a = row0 + wm * 64 + mi * 16 + r;
        const size_t ro0 = (size_t)row_a * ldc;
        const size_t ro1 = (size_t)(row_a + 8) * ldc;
        #pragma unroll
        for (int ni = 0; ni < 4; ni++) {
            const int col_a = col0 + wn * 32 + ni * 8 + 2 * c;
            float2 bb = *(const float2*)(bias + col_a);
            float v0 = acc[mi][ni][0] + bb.x;
            float v1 = acc[mi][ni][1] + bb.y;
            float v2 = acc[mi][ni][2] + bb.x;
            float v3 = acc[mi][ni][3] + bb.y;
            if (res) {
                float2 r0v = *(const float2*)(res + ro0 + col_a);
                float2 r1v = *(const float2*)(res + ro1 + col_a);
                v0 += r0v.x; v1 += r0v.y; v2 += r1v.x; v3 += r1v.y;
            }
            if (relu) {
                v0 = fmaxf(v0, 0.f); v1 = fmaxf(v1, 0.f);
                v2 = fmaxf(v2, 0.f); v3 = fmaxf(v3, 0.f);
            }
            *(float2*)(C + ro0 + col_a) = make_float2(v0, v1);
            *(float2*)(C + ro1 + col_a) = make_float2(v2, v3);
        }
    }
}

// ---------------- tf32 tensor-core causal flash attention, pipelined --------
// grid: (T/128 q-tiles, B*H). block 256 = 8 warps; warp w owns query rows
// [w*16, w*16+16). k-tile = 64 keys. Q fragments live in registers for the
// whole block. P has a dedicated (warp-private) smem region. Next tile's
// K/V are prefetched into registers during the current tile's O-mma.
#define QP 68
#define VP 72
#define ATTN_SMEM ((64 * QP + 64 * VP + 128 * QP) * 4)

__global__ __launch_bounds__(256, 2) void attn_kernel(
    const float* __restrict__ Q, const float* __restrict__ Km,
    const float* __restrict__ V, float* __restrict__ O)
{
    extern __shared__ float sm[];
    float* Ks = sm;                        // [64][QP]  K tile (tf32 bits)
    float* Vs = sm + 64 * QP;              // [64][VP]  V tile (tf32 bits)
    float* Pp = sm + 64 * QP + 64 * VP;    // [128][QP] Q staging, then P

    const int tid  = threadIdx.x;
    const int lane = tid & 31;
    const int w    = tid >> 5;       // warp id: query rows w*16..w*16+15
    const int r    = lane >> 2;      // 0..7
    const int c    = lane & 3;       // 0..3
    const int qt   = blockIdx.x;
    const int bh   = blockIdx.y;
    const int b    = bh >> 3, h = bh & 7;
    const int q0   = qt * 128;
    const size_t base = ((size_t)b * T_) * D_ + h * DK_;
    const float* Qg = Q  + base;
    const float* Kg = Km + base;
    const float* Vg = V  + base;

    // ---- stage Q tile through Pp (tf32), then hoist fragments to regs ----
    #pragma unroll
    for (int i = 0; i < 8; i++) {
        int fidx = tid + i * 256;            // 0..2047 float4s
        int row  = fidx >> 4;                // 0..127
        int d4   = (fidx & 15) * 4;          // 0..60
        float4 qv = *(const float4*)(Qg + (size_t)(q0 + row) * D_ + d4);
        *(uint4*)&Pp[row * QP + d4] = f2tf32x4(qv);
    }
    __syncthreads();
    uint32_t qf[8][4];
    #pragma unroll
    for (int ks = 0; ks < 8; ks++) {
        const int qa = (w * 16 + r) * QP + ks * 8 + c;
        qf[ks][0] = __float_as_uint(Pp[qa]);
        qf[ks][1] = __float_as_uint(Pp[qa + 8 * QP]);
        qf[ks][2] = __float_as_uint(Pp[qa + 4]);
        qf[ks][3] = __float_as_uint(Pp[qa + 8 * QP + 4]);
    }

    // online-softmax state: thread owns rows (w*16+r) and (w*16+r+8)
    float m_[2] = {-1e30f, -1e30f};
    float l_[2] = {0.0f, 0.0f};
    float oacc[8][4];
    #pragma unroll
    for (int ni = 0; ni < 8; ni++)
        oacc[ni][0] = oacc[ni][1] = oacc[ni][2] = oacc[ni][3] = 0.0f;

    // register-staged K/V (4 float4 each per thread)
    float4 kreg[4], vreg[4];
    auto ldg_kv = [&](int kt) {
        const int j0 = kt * 64;
        #pragma unroll
        for (int i = 0; i < 4; i++) {
            int idx = tid + i * 256;           // 0..1023 float4s
            int s   = idx >> 4;                // 0..63
            int d4  = (idx & 15) * 4;
            kreg[i] = *(const float4*)(Kg + (size_t)(j0 + s) * D_ + d4);
            vreg[i] = *(const float4*)(Vg + (size_t)(j0 + s) * D_ + d4);
        }
    };

    ldg_kv(0);
    const int ntile = (q0 >> 6) + 2;          // causal: key tiles 0..(q0+127)/64

    for (int kt = 0; kt < ntile; kt++) {
        const int j0 = kt * 64;
        __syncthreads();                       // K/V smem free (all reads done)
        #pragma unroll
        for (int i = 0; i < 4; i++) {
            int idx = tid + i * 256;
            int s   = idx >> 4;
            int d4  = (idx & 15) * 4;
            *(uint4*)&Ks[s * QP + d4] = f2tf32x4(kreg[i]);
            *(uint4*)&Vs[s * VP + d4] = f2tf32x4(vreg[i]);
        }
        __syncthreads();

        // ---- S = Q K^T : [16 q] x [64 s], contraction over d=64 ----
        float sacc[8][4];
        #pragma unroll
        for (int ni = 0; ni < 8; ni++)
            sacc[ni][0] = sacc[ni][1] = sacc[ni][2] = sacc[ni][3] = 0.0f;
        #pragma unroll
        for (int ks = 0; ks < 8; ks++) {
            #pragma unroll
            for (int ni = 0; ni < 8; ni++) {
                uint32_t bf[2];
                const int kb = (ni * 8 + r) * QP + ks * 8 + c;
                bf[0] = __float_as_uint(Ks[kb]);
                bf[1] = __float_as_uint(Ks[kb + 4]);
                mma_tf32(sacc[ni], qf[ks], bf);
            }
        }

        // ---- causal mask (pre-scale, matches ref) + online softmax ----
        #pragma unroll
        for (int ri = 0; ri < 2; ri++) {
            const int tg = q0 + w * 16 + r + ri * 8;
            float rm = -1e30f;
            #pragma unroll
            for (int ni = 0; ni < 8; ni++) {
                #pragma unroll
                for (int jj = 0; jj < 2; jj++) {
                    int sg = j0 + ni * 8 + 2 * c + jj;
                    float v = (sg <= tg) ? sacc[ni][ri * 2 + jj] * 0.125f
                                         : -1e30f;
                    sacc[ni][ri * 2 + jj] = v;
                    rm = fmaxf(rm, v);
                }
            }
            rm = fmaxf(rm, __shfl_xor_sync(0xffffffffu, rm, 1));
            rm = fmaxf(rm, __shfl_xor_sync(0xffffffffu, rm, 2));
            const float mn    = fmaxf(m_[ri], rm);
            const float alpha = __expf(m_[ri] - mn);
            m_[ri] = mn;
            float ps = 0.0f;
            #pragma unroll
            for (int ni = 0; ni < 8; ni++) {
                #pragma unroll
                for (int jj = 0; jj < 2; jj++) {
                    float p = __expf(sacc[ni][ri * 2 + jj] - mn);
                    sacc[ni][ri * 2 + jj] = p;
                    ps += p;
                }
            }
            ps += __shfl_xor_sync(0xffffffffu, ps, 1);
            ps += __shfl_xor_sync(0xffffffffu, ps, 2);
            l_[ri] = l_[ri] * alpha + ps;
            #pragma unroll
            for (int ni = 0; ni < 8; ni++) {
                oacc[ni][ri * 2 + 0] *= alpha;
                oacc[ni][ri * 2 + 1] *= alpha;
            }
        }

        // ---- stage P (tf32) into warp-private rows of Pp ----
        #pragma unroll
        for (int ni = 0; ni < 8; ni++) {
            float2 p0, p1;
            p0.x = __uint_as_float(f2tf32(sacc[ni][0]));
            p0.y = __uint_as_float(f2tf32(sacc[ni][1]));
            p1.x = __uint_as_float(f2tf32(sacc[ni][2]));
            p1.y = __uint_as_float(f2tf32(sacc[ni][3]));
            *(float2*)&Pp[(w * 16 + r)     * QP + ni * 8 + 2 * c] = p0;
            *(float2*)&Pp[(w * 16 + r + 8) * QP + ni * 8 + 2 * c] = p1;
        }
        __syncwarp();

        if (kt + 1 < ntile) ldg_kv(kt + 1);    // hidden under O-mma

        // ---- O += P V : contraction over s=64, output cols d=64 ----
        #pragma unroll
        for (int ks = 0; ks < 8; ks++) {
            uint32_t af[4];
            const int pa = (w * 16 + r) * QP + ks * 8 + c;
            af[0] = __float_as_uint(Pp[pa]);
            af[1] = __float_as_uint(Pp[pa + 8 * QP]);
            af[2] = __float_as_uint(Pp[pa + 4]);
            af[3] = __float_as_uint(Pp[pa + 8 * QP + 4]);
            #pragma unroll
            for (int ni = 0; ni < 8; ni++) {
                uint32_t bf[2];
                bf[0] = __float_as_uint(Vs[(ks * 8 + c)     * VP + ni * 8 + r]);
                bf[1] = __float_as_uint(Vs[(ks * 8 + c + 4) * VP + ni * 8 + r]);
                mma_tf32(oacc[ni], af, bf);
            }
        }
    }

    // ---- normalize and write out (concat-head layout) ----
    const float inv0 = 1.0f / l_[0];
    const float inv1 = 1.0f / l_[1];
    const int row0g = q0 + w * 16 + r;
    #pragma unroll
    for (int ni = 0; ni < 8; ni++) {
        const int col = ni * 8 + 2 * c;
        *(float2*)(O + base + (size_t)row0g * D_ + col) =
            make_float2(oacc[ni][0] * inv0, oacc[ni][1] * inv0);
        *(float2*)(O + base + (size_t)(row0g + 8) * D_ + col) =
            make_float2(oacc[ni][2] * inv1, oacc[ni][3] * inv1);
    }
}

// ---------------- launcher ---------------------------------------------------
extern "C" void kernel_launch(void* const* d_in, const int* in_sizes, int n_in,
                              void* d_out, int out_size)
{
    const float* x   = (const float*)d_in[0];
    const float* Wq  = (const float*)d_in[1];
    const float* bq  = (const float*)d_in[2];
    const float* Wk  = (const float*)d_in[3];
    const float* bk  = (const float*)d_in[4];
    const float* Wv  = (const float*)d_in[5];
    const float* bv  = (const float*)d_in[6];
    const float* Wp  = (const float*)d_in[7];
    const float* bp  = (const float*)d_in[8];
    const float* W1  = (const float*)d_in[9];
    const float* b1  = (const float*)d_in[10];
    const float* W2  = (const float*)d_in[11];
    const float* b2  = (const float*)d_in[12];
    const float* g1  = (const float*)d_in[13];
    const float* be1 = (const float*)d_in[14];
    const float* g2  = (const float*)d_in[15];
    const float* be2 = (const float*)d_in[16];
    float* out = (float*)d_out;

    float *h, *q, *k, *v, *o, *x1, *h2, *ff;
    cudaGetSymbolAddress((void**)&h,  g_h);
    cudaGetSymbolAddress((void**)&q,  g_q);
    cudaGetSymbolAddress((void**)&k,  g_k);
    cudaGetSymbolAddress((void**)&v,  g_v);
    cudaGetSymbolAddress((void**)&o,  g_o);
    cudaGetSymbolAddress((void**)&x1, g_x1);
    cudaGetSymbolAddress((void**)&h2, g_h2);
    cudaGetSymbolAddress((void**)&ff, g_ff);

    cudaFuncSetAttribute(attn_kernel,
                         cudaFuncAttributeMaxDynamicSharedMemorySize, ATTN_SMEM);
    cudaFuncSetAttribute(gemm_kernel,
                         cudaFuncAttributeMaxDynamicSharedMemorySize, GEMM_SMEM);

    // LN1
    ln_kernel<<<BT_, 128>>>(x, g1, be1, h);

    // QKV projections (head-stacked weights: cstride = D*DK, ldb = DK)
    dim3 g512(D_ / 128, BT_ / 128);
    gemm_kernel<<<g512, 256, GEMM_SMEM>>>(h, D_, Wq, D_ * DK_, DK_, bq, nullptr, q, D_, D_, 0);
    gemm_kernel<<<g512, 256, GEMM_SMEM>>>(h, D_, Wk, D_ * DK_, DK_, bk, nullptr, k, D_, D_, 0);
    gemm_kernel<<<g512, 256, GEMM_SMEM>>>(h, D_, Wv, D_ * DK_, DK_, bv, nullptr, v, D_, D_, 0);

    // causal attention (tensor-core, pipelined)
    attn_kernel<<<dim3(T_ / 128, B_ * H_), 256, ATTN_SMEM>>>(q, k, v, o);

    // output projection + residual (row-major weights: cstride = 64, ldb = N)
    gemm_kernel<<<g512, 256, GEMM_SMEM>>>(o, D_, Wp, 64, D_, bp, x, x1, D_, D_, 0);

    // LN2
    ln_kernel<<<BT_, 128>>>(x1, g2, be2, h2);

    // FFN
    gemm_kernel<<<dim3(DFF_ / 128, BT_ / 128), 256, GEMM_SMEM>>>(
        h2, D_, W1, 64, DFF_, b1, nullptr, ff, DFF_, D_, 1);
    gemm_kernel<<<g512, 256, GEMM_SMEM>>>(ff, DFF_, W2, 64, D_, b2, x1, out, D_, DFF_, 0);
}

// round 8
// speedup vs baseline: 1.1200x; 1.1200x over previous
#include <cuda_runtime.h>
#include <cstdint>

#define B_   4
#define T_   2048
#define D_   512
#define H_   8
#define DK_  64
#define BT_  (B_ * T_)
#define DFF_ 2048
#define LDQ  1536      // fused QKV row stride

// ---------------- scratch (static device globals; no allocations) ----------
__device__ float g_h  [BT_ * D_];
__device__ float g_qkv[BT_ * LDQ];  // [BT, 1536]: Q | K | V each 512 cols
__device__ float g_o  [BT_ * D_];   // attention output, concat-head layout
__device__ float g_x1 [BT_ * D_];
__device__ float g_h2 [BT_ * D_];
__device__ float g_ff [BT_ * DFF_];

// ---------------- LayerNorm: one block per row of 512 ----------------------
__global__ __launch_bounds__(128) void ln_kernel(
    const float* __restrict__ x, const float* __restrict__ g,
    const float* __restrict__ b, float* __restrict__ out)
{
    const int row = blockIdx.x;
    const int tid = threadIdx.x;                 // 128 threads * float4 = 512
    float4 v = ((const float4*)(x + (size_t)row * D_))[tid];
    float s  = v.x + v.y + v.z + v.w;
    float ss = v.x * v.x + v.y * v.y + v.z * v.z + v.w * v.w;
    #pragma unroll
    for (int o = 16; o > 0; o >>= 1) {
        s  += __shfl_xor_sync(0xffffffffu, s,  o);
        ss += __shfl_xor_sync(0xffffffffu, ss, o);
    }
    __shared__ float sh_s[4], sh_ss[4];
    if ((tid & 31) == 0) { sh_s[tid >> 5] = s; sh_ss[tid >> 5] = ss; }
    __syncthreads();
    const float tot  = sh_s[0] + sh_s[1] + sh_s[2] + sh_s[3];
    const float tots = sh_ss[0] + sh_ss[1] + sh_ss[2] + sh_ss[3];
    const float mu   = tot  * (1.0f / D_);
    const float var  = tots * (1.0f / D_) - mu * mu;
    const float rstd = rsqrtf(var + 1e-5f);
    float4 gv = ((const float4*)g)[tid];
    float4 bv = ((const float4*)b)[tid];
    float4 r;
    r.x = (v.x - mu) * rstd * gv.x + bv.x;
    r.y = (v.y - mu) * rstd * gv.y + bv.y;
    r.z = (v.z - mu) * rstd * gv.z + bv.z;
    r.w = (v.w - mu) * rstd * gv.w + bv.w;
    ((float4*)(out + (size_t)row * D_))[tid] = r;
}

// ---------------- tf32 helpers ----------------------------------------------
__device__ __forceinline__ uint32_t f2tf32(float x) {
    uint32_t u;
    asm("cvt.rna.tf32.f32 %0, %1;" : "=r"(u) : "f"(x));
    return u;
}

__device__ __forceinline__ uint4 f2tf32x4(float4 v) {
    uint4 u;
    u.x = f2tf32(v.x); u.y = f2tf32(v.y);
    u.z = f2tf32(v.z); u.w = f2tf32(v.w);
    return u;
}

__device__ __forceinline__ void mma_tf32(float* d, const uint32_t* a,
                                         const uint32_t* b) {
    asm volatile(
        "mma.sync.aligned.m16n8k8.row.col.f32.tf32.tf32.f32 "
        "{%0,%1,%2,%3}, {%4,%5,%6,%7}, {%8,%9}, {%0,%1,%2,%3};"
        : "+f"(d[0]), "+f"(d[1]), "+f"(d[2]), "+f"(d[3])
        : "r"(a[0]), "r"(a[1]), "r"(a[2]), "r"(a[3]),
          "r"(b[0]), "r"(b[1]));
}

// ---------------- tf32 tensor-core GEMM, 128x128 tile (R5 body) -------------
// C[row, col] = sum_k A[row, k] * B(k, col) (+bias[col]) (+res[row,col]) (relu)
// Weight addressing within a group: addr(k, col) = W + (col>>6)*cstride
//                                                  + k*ldb + (col&63)
// qkv mode: cols [0,512) use W0/b0, [512,1024) W1/b1, [1024,1536) W2/b2.
#define PAD_A 36
#define PAD_B 136
__global__ __launch_bounds__(256) void gemm_kernel(
    const float* __restrict__ A, int lda,
    const float* __restrict__ W0, const float* __restrict__ W1g,
    const float* __restrict__ W2g, int cstride, int ldb,
    const float* __restrict__ b0, const float* __restrict__ b1g,
    const float* __restrict__ b2g,
    const float* __restrict__ res,
    float* __restrict__ C, int ldc,
    int K, int relu, int qkv)
{
    __shared__ __align__(16) float As[128][PAD_A];  // m-major (tf32 bits)
    __shared__ __align__(16) float Bs[32][PAD_B];   // k-major (tf32 bits)

    const int tid  = threadIdx.x;
    const int lane = tid & 31;
    const int wid  = tid >> 5;
    const int wm   = wid & 1;        // row block of 64
    const int wn   = wid >> 1;       // col block of 32
    const int row0 = blockIdx.y * 128;
    const int col0 = blockIdx.x * 128;

    const int grp = qkv ? (col0 >> 9) : 0;
    const float* Wsel = (grp == 0) ? W0 : ((grp == 1) ? W1g : W2g);
    const float* bsel = (grp == 0) ? b0 : ((grp == 1) ? b1g : b2g);
    const int col0g = qkv ? (col0 & 511) : col0;
    const float* B0 = Wsel + (size_t)(col0g >> 6) * cstride; // cols [col0,+64)
    const float* B1 = B0 + cstride;                          // cols [+64,+128)

    const int r = lane >> 2;         // 0..7
    const int c = lane & 3;          // 0..3

    float acc[4][4][4];
    #pragma unroll
    for (int mi = 0; mi < 4; mi++)
        #pragma unroll
        for (int ni = 0; ni < 4; ni++)
            acc[mi][ni][0] = acc[mi][ni][1] = acc[mi][ni][2] = acc[mi][ni][3] = 0.f;

    for (int k0 = 0; k0 < K; k0 += 32) {
        // --- load A tile 128 rows x 32 k ---
        #pragma unroll
        for (int i = 0; i < 4; i++) {
            int idx = tid + i * 256;            // 0..1023 float4s
            int m   = idx >> 3;                 // 0..127
            int kk  = (idx & 7) * 4;            // 0..28
            float4 a = *(const float4*)(A + (size_t)(row0 + m) * lda + k0 + kk);
            *(uint4*)&As[m][kk] = f2tf32x4(a);
        }
        // --- load B tile 32 k x 128 n ---
        #pragma unroll
        for (int i = 0; i < 4; i++) {
            int idx = tid + i * 256;            // 0..1023 float4s
            int kk  = idx >> 5;                 // 0..31
            int n4  = (idx & 31) * 4;           // 0..124
            const float* src = (n4 < 64)
                ? (B0 + (size_t)(k0 + kk) * ldb + n4)
                : (B1 + (size_t)(k0 + kk) * ldb + (n4 - 64));
            *(uint4*)&Bs[kk][n4] = f2tf32x4(*(const float4*)src);
        }
        __syncthreads();

        #pragma unroll
        for (int ks = 0; ks < 32; ks += 8) {
            uint32_t af[4][4], bf[4][2];
            #pragma unroll
            for (int mi = 0; mi < 4; mi++) {
                int m = wm * 64 + mi * 16 + r;
                af[mi][0] = __float_as_uint(As[m    ][ks + c]);
                af[mi][1] = __float_as_uint(As[m + 8][ks + c]);
                af[mi][2] = __float_as_uint(As[m    ][ks + c + 4]);
                af[mi][3] = __float_as_uint(As[m + 8][ks + c + 4]);
            }
            #pragma unroll
            for (int ni = 0; ni < 4; ni++) {
                int n = wn * 32 + ni * 8 + r;
                bf[ni][0] = __float_as_uint(Bs[ks + c    ][n]);
                bf[ni][1] = __float_as_uint(Bs[ks + c + 4][n]);
            }
            #pragma unroll
            for (int mi = 0; mi < 4; mi++)
                #pragma unroll
                for (int ni = 0; ni < 4; ni++)
                    mma_tf32(acc[mi][ni], af[mi], bf[ni]);
        }
        __syncthreads();
    }

    // --- epilogue: bias (+res) (relu) ---
    #pragma unroll
    for (int mi = 0; mi < 4; mi++) {
        const int row_a = row0 + wm * 64 + mi * 16 + r;
        const size_t ro0 = (size_t)row_a * ldc;
        const size_t ro1 = (size_t)(row_a + 8) * ldc;
        #pragma unroll
        for (int ni = 0; ni < 4; ni++) {
            const int col_a = col0 + wn * 32 + ni * 8 + 2 * c;
            const int col_b = qkv ? (col_a & 511) : col_a;
            float2 bb = *(const float2*)(bsel + col_b);
            float v0 = acc[mi][ni][0] + bb.x;
            float v1 = acc[mi][ni][1] + bb.y;
            float v2 = acc[mi][ni][2] + bb.x;
            float v3 = acc[mi][ni][3] + bb.y;
            if (res) {
                float2 r0v = *(const float2*)(res + ro0 + col_a);
                float2 r1v = *(const float2*)(res + ro1 + col_a);
                v0 += r0v.x; v1 += r0v.y; v2 += r1v.x; v3 += r1v.y;
            }
            if (relu) {
                v0 = fmaxf(v0, 0.f); v1 = fmaxf(v1, 0.f);
                v2 = fmaxf(v2, 0.f); v3 = fmaxf(v3, 0.f);
            }
            *(float2*)(C + ro0 + col_a) = make_float2(v0, v1);
            *(float2*)(C + ro1 + col_a) = make_float2(v2, v3);
        }
    }
}

// ---------------- tf32 tensor-core causal flash attention -------------------
// grid: (T/128 q-tiles reversed, B*H). block 256 = 8 warps; warp w owns query
// rows [w*16, w*16+16). k-tile = 64 keys, DOUBLE-BUFFERED in smem: one
// __syncthreads per tile. Q fragments in registers for the whole block.
// P region is warp-private (no block sync before P store).
#define QP 68
#define VP 72
#define ATTN_SMEM ((128 * QP + 2 * (64 * QP + 64 * VP)) * 4)

__global__ __launch_bounds__(256, 2) void attn_kernel(
    const float* __restrict__ QKV, float* __restrict__ O)
{
    extern __shared__ float sm[];
    float* Pp  = sm;                         // [128][QP] Q staging, then P
    float* KV0 = sm + 128 * QP;              // Ks0 [64][QP] | Vs0 [64][VP]
    float* KV1 = KV0 + 64 * QP + 64 * VP;    // Ks1 | Vs1

    const int tid  = threadIdx.x;
    const int lane = tid & 31;
    const int w    = tid >> 5;       // warp id: query rows w*16..w*16+15
    const int r    = lane >> 2;      // 0..7
    const int c    = lane & 3;       // 0..3
    const int qt   = (gridDim.x - 1) - blockIdx.x;   // big tiles first
    const int bh   = blockIdx.y;
    const int b    = bh >> 3, h = bh & 7;
    const int q0   = qt * 128;
    const size_t base  = ((size_t)b * T_) * LDQ + h * DK_;
    const size_t obase = ((size_t)b * T_) * D_  + h * DK_;
    const float* Qg = QKV + base;
    const float* Kg = QKV + base + 512;
    const float* Vg = QKV + base + 1024;

    // ---- stage Q tile through Pp (tf32), then hoist fragments to regs ----
    #pragma unroll
    for (int i = 0; i < 8; i++) {
        int fidx = tid + i * 256;            // 0..2047 float4s
        int row  = fidx >> 4;                // 0..127
        int d4   = (fidx & 15) * 4;          // 0..60
        float4 qv = *(const float4*)(Qg + (size_t)(q0 + row) * LDQ + d4);
        *(uint4*)&Pp[row * QP + d4] = f2tf32x4(qv);
    }
    __syncthreads();
    uint32_t qf[8][4];
    #pragma unroll
    for (int ks = 0; ks < 8; ks++) {
        const int qa = (w * 16 + r) * QP + ks * 8 + c;
        qf[ks][0] = __float_as_uint(Pp[qa]);
        qf[ks][1] = __float_as_uint(Pp[qa + 8 * QP]);
        qf[ks][2] = __float_as_uint(Pp[qa + 4]);
        qf[ks][3] = __float_as_uint(Pp[qa + 8 * QP + 4]);
    }

    // online-softmax state: thread owns rows (w*16+r) and (w*16+r+8)
    float m_[2] = {-1e30f, -1e30f};
    float l_[2] = {0.0f, 0.0f};
    float oacc[8][4];
    #pragma unroll
    for (int ni = 0; ni < 8; ni++)
        oacc[ni][0] = oacc[ni][1] = oacc[ni][2] = oacc[ni][3] = 0.0f;

    const int ntile = (q0 >> 6) + 2;          // causal: key tiles 0..(q0+127)/64

    for (int kt = 0; kt < ntile; kt++) {
        const int j0 = kt * 64;
        float* Ks = (kt & 1) ? KV1 : KV0;
        float* Vs = Ks + 64 * QP;

        // ---- load K/V tile into this iteration's buffer (tf32) ----
        // Safe: all reads of this buffer ended before the previous sync.
        #pragma unroll
        for (int i = 0; i < 4; i++) {
            int idx = tid + i * 256;           // 0..1023 float4s
            int s   = idx >> 4;                // 0..63
            int d4  = (idx & 15) * 4;
            float4 kv = *(const float4*)(Kg + (size_t)(j0 + s) * LDQ + d4);
            *(uint4*)&Ks[s * QP + d4] = f2tf32x4(kv);
            float4 vv = *(const float4*)(Vg + (size_t)(j0 + s) * LDQ + d4);
            *(uint4*)&Vs[s * VP + d4] = f2tf32x4(vv);
        }
        __syncthreads();                       // single sync per tile

        // ---- S = Q K^T : [16 q] x [64 s], contraction over d=64 ----
        float sacc[8][4];
        #pragma unroll
        for (int ni = 0; ni < 8; ni++)
            sacc[ni][0] = sacc[ni][1] = sacc[ni][2] = sacc[ni][3] = 0.0f;
        #pragma unroll
        for (int ks = 0; ks < 8; ks++) {
            #pragma unroll
            for (int ni = 0; ni < 8; ni++) {
                uint32_t bf[2];
                const int kb = (ni * 8 + r) * QP + ks * 8 + c;
                bf[0] = __float_as_uint(Ks[kb]);
                bf[1] = __float_as_uint(Ks[kb + 4]);
                mma_tf32(sacc[ni], qf[ks], bf);
            }
        }

        // ---- causal mask (pre-scale, matches ref) + online softmax ----
        const bool full = (j0 + 64 <= q0 + w * 16);   // warp-uniform
        #pragma unroll
        for (int ri = 0; ri < 2; ri++) {
            const int tg = q0 + w * 16 + r + ri * 8;
            float rm = -1e30f;
            if (full) {
                #pragma unroll
                for (int ni = 0; ni < 8; ni++) {
                    #pragma unroll
                    for (int jj = 0; jj < 2; jj++) {
                        float v = sacc[ni][ri * 2 + jj] * 0.125f;
                        sacc[ni][ri * 2 + jj] = v;
                        rm = fmaxf(rm, v);
                    }
                }
            } else {
                #pragma unroll
                for (int ni = 0; ni < 8; ni++) {
                    #pragma unroll
                    for (int jj = 0; jj < 2; jj++) {
                        int sg = j0 + ni * 8 + 2 * c + jj;
                        float v = (sg <= tg) ? sacc[ni][ri * 2 + jj] * 0.125f
                                             : -1e30f;
                        sacc[ni][ri * 2 + jj] = v;
                        rm = fmaxf(rm, v);
                    }
                }
            }
            rm = fmaxf(rm, __shfl_xor_sync(0xffffffffu, rm, 1));
            rm = fmaxf(rm, __shfl_xor_sync(0xffffffffu, rm, 2));
            const float mn    = fmaxf(m_[ri], rm);
            const float alpha = __expf(m_[ri] - mn);
            m_[ri] = mn;
            float ps = 0.0f;
            #pragma unroll
            for (int ni = 0; ni < 8; ni++) {
                #pragma unroll
                for (int jj = 0; jj < 2; jj++) {
                    float p = __expf(sacc[ni][ri * 2 + jj] - mn);
                    sacc[ni][ri * 2 + jj] = p;
                    ps += p;
                }
            }
            ps += __shfl_xor_sync(0xffffffffu, ps, 1);
            ps += __shfl_xor_sync(0xffffffffu, ps, 2);
            l_[ri] = l_[ri] * alpha + ps;
            #pragma unroll
            for (int ni = 0; ni < 8; ni++) {
                oacc[ni][ri * 2 + 0] *= alpha;
                oacc[ni][ri * 2 + 1] *= alpha;
            }
        }

        // ---- stage P (tf32) into warp-private rows of Pp ----
        #pragma unroll
        for (int ni = 0; ni < 8; ni++) {
            float2 p0, p1;
            p0.x = __uint_as_float(f2tf32(sacc[ni][0]));
            p0.y = __uint_as_float(f2tf32(sacc[ni][1]));
            p1.x = __uint_as_float(f2tf32(sacc[ni][2]));
            p1.y = __uint_as_float(f2tf32(sacc[ni][3]));
            *(float2*)&Pp[(w * 16 + r)     * QP + ni * 8 + 2 * c] = p0;
            *(float2*)&Pp[(w * 16 + r + 8) * QP + ni * 8 + 2 * c] = p1;
        }
        __syncwarp();

        // ---- O += P V : contraction over s=64, output cols d=64 ----
        #pragma unroll
        for (int ks = 0; ks < 8; ks++) {
            uint32_t af[4];
            const int pa = (w * 16 + r) * QP + ks * 8 + c;
            af[0] = __float_as_uint(Pp[pa]);
            af[1] = __float_as_uint(Pp[pa + 8 * QP]);
            af[2] = __float_as_uint(Pp[pa + 4]);
            af[3] = __float_as_uint(Pp[pa + 8 * QP + 4]);
            #pragma unroll
            for (int ni = 0; ni < 8; ni++) {
                uint32_t bf[2];
                bf[0] = __float_as_uint(Vs[(ks * 8 + c)     * VP + ni * 8 + r]);
                bf[1] = __float_as_uint(Vs[(ks * 8 + c + 4) * VP + ni * 8 + r]);
                mma_tf32(oacc[ni], af, bf);
            }
        }
    }

    // ---- normalize and write out (concat-head layout, stride D_) ----
    const float inv0 = 1.0f / l_[0];
    const float inv1 = 1.0f / l_[1];
    const int row0g = q0 + w * 16 + r;
    #pragma unroll
    for (int ni = 0; ni < 8; ni++) {
        const int col = ni * 8 + 2 * c;
        *(float2*)(O + obase + (size_t)row0g * D_ + col) =
            make_float2(oacc[ni][0] * inv0, oacc[ni][1] * inv0);
        *(float2*)(O + obase + (size_t)(row0g + 8) * D_ + col) =
            make_float2(oacc[ni][2] * inv1, oacc[ni][3] * inv1);
    }
}

// ---------------- launcher ---------------------------------------------------
extern "C" void kernel_launch(void* const* d_in, const int* in_sizes, int n_in,
                              void* d_out, int out_size)
{
    const float* x   = (const float*)d_in[0];
    const float* Wq  = (const float*)d_in[1];
    const float* bq  = (const float*)d_in[2];
    const float* Wk  = (const float*)d_in[3];
    const float* bk  = (const float*)d_in[4];
    const float* Wv  = (const float*)d_in[5];
    const float* bv  = (const float*)d_in[6];
    const float* Wp  = (const float*)d_in[7];
    const float* bp  = (const float*)d_in[8];
    const float* W1  = (const float*)d_in[9];
    const float* b1  = (const float*)d_in[10];
    const float* W2  = (const float*)d_in[11];
    const float* b2  = (const float*)d_in[12];
    const float* g1  = (const float*)d_in[13];
    const float* be1 = (const float*)d_in[14];
    const float* g2  = (const float*)d_in[15];
    const float* be2 = (const float*)d_in[16];
    float* out = (float*)d_out;

    float *h, *qkv, *o, *x1, *h2, *ff;
    cudaGetSymbolAddress((void**)&h,   g_h);
    cudaGetSymbolAddress((void**)&qkv, g_qkv);
    cudaGetSymbolAddress((void**)&o,   g_o);
    cudaGetSymbolAddress((void**)&x1,  g_x1);
    cudaGetSymbolAddress((void**)&h2,  g_h2);
    cudaGetSymbolAddress((void**)&ff,  g_ff);

    cudaFuncSetAttribute(attn_kernel,
                         cudaFuncAttributeMaxDynamicSharedMemorySize, ATTN_SMEM);

    // LN1
    ln_kernel<<<BT_, 128>>>(x, g1, be1, h);

    // fused QKV projection (head-stacked weights: cstride = D*DK, ldb = DK)
    gemm_kernel<<<dim3(LDQ / 128, BT_ / 128), 256>>>(
        h, D_, Wq, Wk, Wv, D_ * DK_, DK_, bq, bk, bv,
        nullptr, qkv, LDQ, D_, 0, 1);

    // causal attention (tensor-core, double-buffered)
    attn_kernel<<<dim3(T_ / 128, B_ * H_), 256, ATTN_SMEM>>>(qkv, o);

    // output projection + residual (row-major weights: cstride = 64, ldb = N)
    dim3 g512(D_ / 128, BT_ / 128);
    gemm_kernel<<<g512, 256>>>(o, D_, Wp, Wp, Wp, 64, D_, bp, bp, bp,
                               x, x1, D_, D_, 0, 0);

    // LN2
    ln_kernel<<<BT_, 128>>>(x1, g2, be2, h2);

    // FFN
    gemm_kernel<<<dim3(DFF_ / 128, BT_ / 128), 256>>>(
        h2, D_, W1, W1, W1, 64, DFF_, b1, b1, b1, nullptr, ff, DFF_, D_, 1, 0);
    gemm_kernel<<<g512, 256>>>(ff, DFF_, W2, W2, W2, 64, D_, b2, b2, b2,
                               x1, out, D_, DFF_, 0, 0);
}

// round 9
// speedup vs baseline: 1.2223x; 1.0914x over previous
#include <cuda_runtime.h>
#include <cstdint>

#define B_   4
#define T_   2048
#define D_   512
#define H_   8
#define DK_  64
#define BT_  (B_ * T_)
#define DFF_ 2048
#define LDQ  1536      // fused QKV row stride

// ---------------- scratch (static device globals; no allocations) ----------
__device__ float g_h  [BT_ * D_];
__device__ float g_qkv[BT_ * LDQ];  // [BT, 1536]: Q | K | V each 512 cols
__device__ float g_o  [BT_ * D_];   // attention output, concat-head layout
__device__ float g_x1 [BT_ * D_];
__device__ float g_h2 [BT_ * D_];
__device__ float g_ff [BT_ * DFF_];
__device__ float g_w  [4 * 262144 + 2 * 1048576];  // tf32-rounded weights

// ---------------- tf32 helpers ----------------------------------------------
__device__ __forceinline__ uint32_t f2tf32(float x) {
    uint32_t u;
    asm("cvt.rna.tf32.f32 %0, %1;" : "=r"(u) : "f"(x));
    return u;
}

__device__ __forceinline__ void mma_tf32(float* d, const uint32_t* a,
                                         const uint32_t* b) {
    asm volatile(
        "mma.sync.aligned.m16n8k8.row.col.f32.tf32.tf32.f32 "
        "{%0,%1,%2,%3}, {%4,%5,%6,%7}, {%8,%9}, {%0,%1,%2,%3};"
        : "+f"(d[0]), "+f"(d[1]), "+f"(d[2]), "+f"(d[3])
        : "r"(a[0]), "r"(a[1]), "r"(a[2]), "r"(a[3]),
          "r"(b[0]), "r"(b[1]));
}

__device__ __forceinline__ void cp16(uint32_t dst_smem, const void* src) {
    asm volatile("cp.async.cg.shared.global [%0], [%1], 16;"
                 :: "r"(dst_smem), "l"(src) : "memory");
}
#define CP_COMMIT() asm volatile("cp.async.commit_group;" ::: "memory")

// ---------------- weight pre-rounding (rna to tf32, raw copy) ---------------
__global__ __launch_bounds__(256) void round_kernel(
    const float* __restrict__ src, float* __restrict__ dst)
{
    const int i = blockIdx.x * 256 + threadIdx.x;
    float4 v = ((const float4*)src)[i];
    float4 r;
    r.x = __uint_as_float(f2tf32(v.x));
    r.y = __uint_as_float(f2tf32(v.y));
    r.z = __uint_as_float(f2tf32(v.z));
    r.w = __uint_as_float(f2tf32(v.w));
    ((float4*)dst)[i] = r;
}

// ---------------- LayerNorm: one block per row of 512 -----------------------
// Output is tf32-rounded (it is consumed only by tensor-core GEMMs).
__global__ __launch_bounds__(128) void ln_kernel(
    const float* __restrict__ x, const float* __restrict__ g,
    const float* __restrict__ b, float* __restrict__ out)
{
    const int row = blockIdx.x;
    const int tid = threadIdx.x;                 // 128 threads * float4 = 512
    float4 v = ((const float4*)(x + (size_t)row * D_))[tid];
    float s  = v.x + v.y + v.z + v.w;
    float ss = v.x * v.x + v.y * v.y + v.z * v.z + v.w * v.w;
    #pragma unroll
    for (int o = 16; o > 0; o >>= 1) {
        s  += __shfl_xor_sync(0xffffffffu, s,  o);
        ss += __shfl_xor_sync(0xffffffffu, ss, o);
    }
    __shared__ float sh_s[4], sh_ss[4];
    if ((tid & 31) == 0) { sh_s[tid >> 5] = s; sh_ss[tid >> 5] = ss; }
    __syncthreads();
    const float tot  = sh_s[0] + sh_s[1] + sh_s[2] + sh_s[3];
    const float tots = sh_ss[0] + sh_ss[1] + sh_ss[2] + sh_ss[3];
    const float mu   = tot  * (1.0f / D_);
    const float var  = tots * (1.0f / D_) - mu * mu;
    const float rstd = rsqrtf(var + 1e-5f);
    float4 gv = ((const float4*)g)[tid];
    float4 bv = ((const float4*)b)[tid];
    float4 r;
    r.x = __uint_as_float(f2tf32((v.x - mu) * rstd * gv.x + bv.x));
    r.y = __uint_as_float(f2tf32((v.y - mu) * rstd * gv.y + bv.y));
    r.z = __uint_as_float(f2tf32((v.z - mu) * rstd * gv.z + bv.z));
    r.w = __uint_as_float(f2tf32((v.w - mu) * rstd * gv.w + bv.w));
    ((float4*)(out + (size_t)row * D_))[tid] = r;
}

// ---------------- tf32 tensor-core GEMM, 128x128 tile, cp.async 3-stage -----
// C[row, col] = sum_k A[row, k] * B(k, col) (+bias[col]) (+res[row,col])
//               (relu) (rnd: tf32-round the stored result)
// A and B(weights) must already be tf32-rounded values in fp32 format.
// Weight addressing within a group: addr(k, col) = W + (col>>6)*cstride
//                                                  + k*ldb + (col&63)
// qkv mode: cols [0,512) use W0/b0, [512,1024) W1/b1, [1024,1536) W2/b2.
#define PAD_A 36
#define PAD_B 136
#define ASTAGE (128 * PAD_A)                 // 4608 floats
#define STAGE  (ASTAGE + 32 * PAD_B)         // 8960 floats
#define GEMM_SMEM (3 * STAGE * 4)            // 107520 bytes

__global__ __launch_bounds__(256, 2) void gemm_kernel(
    const float* __restrict__ A, int lda,
    const float* __restrict__ W0, const float* __restrict__ W1g,
    const float* __restrict__ W2g, int cstride, int ldb,
    const float* __restrict__ b0, const float* __restrict__ b1g,
    const float* __restrict__ b2g,
    const float* __restrict__ res,
    float* __restrict__ C, int ldc,
    int K, int relu, int qkv, int rnd)
{
    extern __shared__ float smg[];
    const uint32_t sbase = (uint32_t)__cvta_generic_to_shared(smg);

    const int tid  = threadIdx.x;
    const int lane = tid & 31;
    const int wid  = tid >> 5;
    const int wm   = wid & 1;        // row block of 64
    const int wn   = wid >> 1;       // col block of 32
    const int row0 = blockIdx.y * 128;
    const int col0 = blockIdx.x * 128;

    const int grp = qkv ? (col0 >> 9) : 0;
    const float* Wsel = (grp == 0) ? W0 : ((grp == 1) ? W1g : W2g);
    const float* bsel = (grp == 0) ? b0 : ((grp == 1) ? b1g : b2g);
    const int col0g = qkv ? (col0 & 511) : col0;
    const float* B0 = Wsel + (size_t)(col0g >> 6) * cstride; // cols [col0,+64)
    const float* B1 = B0 + cstride;                          // cols [+64,+128)

    const int r = lane >> 2;         // 0..7
    const int c = lane & 3;          // 0..3

    float acc[4][4][4];
    #pragma unroll
    for (int mi = 0; mi < 4; mi++)
        #pragma unroll
        for (int ni = 0; ni < 4; ni++)
            acc[mi][ni][0] = acc[mi][ni][1] = acc[mi][ni][2] = acc[mi][ni][3] = 0.f;

    const int niter = K >> 5;

    auto issue_stage = [&](int it) {
        const int k0 = it * 32;
        const uint32_t ab = sbase + (uint32_t)((it % 3) * STAGE) * 4;
        const uint32_t bb = ab + ASTAGE * 4;
        #pragma unroll
        for (int i = 0; i < 4; i++) {
            int idx = tid + i * 256;            // A: 0..1023 float4s
            int m   = idx >> 3;                 // 0..127
            int kk  = (idx & 7) * 4;            // 0..28
            cp16(ab + (uint32_t)(m * PAD_A + kk) * 4,
                 A + (size_t)(row0 + m) * lda + k0 + kk);
        }
        #pragma unroll
        for (int i = 0; i < 4; i++) {
            int idx = tid + i * 256;            // B: 0..1023 float4s
            int kk  = idx >> 5;                 // 0..31
            int n4  = (idx & 31) * 4;           // 0..124
            const float* src = (n4 < 64)
                ? (B0 + (size_t)(k0 + kk) * ldb + n4)
                : (B1 + (size_t)(k0 + kk) * ldb + (n4 - 64));
            cp16(bb + (uint32_t)(kk * PAD_B + n4) * 4, src);
        }
        CP_COMMIT();
    };

    issue_stage(0);
    issue_stage(1);

    for (int it = 0; it < niter; it++) {
        if (it < niter - 1)
            asm volatile("cp.async.wait_group 1;" ::: "memory");
        else
            asm volatile("cp.async.wait_group 0;" ::: "memory");
        __syncthreads();
        if (it + 2 < niter) issue_stage(it + 2);

        const float* Ac = smg + (it % 3) * STAGE;
        const float* Bc = Ac + ASTAGE;

        #pragma unroll
        for (int ks = 0; ks < 32; ks += 8) {
            uint32_t af[4][4], bf[4][2];
            #pragma unroll
            for (int mi = 0; mi < 4; mi++) {
                int m = wm * 64 + mi * 16 + r;
                af[mi][0] = __float_as_uint(Ac[m * PAD_A + ks + c]);
                af[mi][1] = __float_as_uint(Ac[(m + 8) * PAD_A + ks + c]);
                af[mi][2] = __float_as_uint(Ac[m * PAD_A + ks + c + 4]);
                af[mi][3] = __float_as_uint(Ac[(m + 8) * PAD_A + ks + c + 4]);
            }
            #pragma unroll
            for (int ni = 0; ni < 4; ni++) {
                int n = wn * 32 + ni * 8 + r;
                bf[ni][0] = __float_as_uint(Bc[(ks + c) * PAD_B + n]);
                bf[ni][1] = __float_as_uint(Bc[(ks + c + 4) * PAD_B + n]);
            }
            #pragma unroll
            for (int mi = 0; mi < 4; mi++)
                #pragma unroll
                for (int ni = 0; ni < 4; ni++)
                    mma_tf32(acc[mi][ni], af[mi], bf[ni]);
        }
    }

    // --- epilogue: bias (+res) (relu) (rnd) ---
    #pragma unroll
    for (int mi = 0; mi < 4; mi++) {
        const int row_a = row0 + wm * 64 + mi * 16 + r;
        const size_t ro0 = (size_t)row_a * ldc;
        const size_t ro1 = (size_t)(row_a + 8) * ldc;
        #pragma unroll
        for (int ni = 0; ni < 4; ni++) {
            const int col_a = col0 + wn * 32 + ni * 8 + 2 * c;
            const int col_b = qkv ? (col_a & 511) : col_a;
            float2 bb = *(const float2*)(bsel + col_b);
            float v0 = acc[mi][ni][0] + bb.x;
            float v1 = acc[mi][ni][1] + bb.y;
            float v2 = acc[mi][ni][2] + bb.x;
            float v3 = acc[mi][ni][3] + bb.y;
            if (res) {
                float2 r0v = *(const float2*)(res + ro0 + col_a);
                float2 r1v = *(const float2*)(res + ro1 + col_a);
                v0 += r0v.x; v1 += r0v.y; v2 += r1v.x; v3 += r1v.y;
            }
            if (relu) {
                v0 = fmaxf(v0, 0.f); v1 = fmaxf(v1, 0.f);
                v2 = fmaxf(v2, 0.f); v3 = fmaxf(v3, 0.f);
            }
            if (rnd) {
                v0 = __uint_as_float(f2tf32(v0));
                v1 = __uint_as_float(f2tf32(v1));
                v2 = __uint_as_float(f2tf32(v2));
                v3 = __uint_as_float(f2tf32(v3));
            }
            *(float2*)(C + ro0 + col_a) = make_float2(v0, v1);
            *(float2*)(C + ro1 + col_a) = make_float2(v2, v3);
        }
    }
}

// ---------------- tf32 tensor-core causal flash attention -------------------
// grid: (T/128 q-tiles reversed, B*H). block 256 = 8 warps; warp w owns query
// rows [w*16, w*16+16). k-tile = 64 keys, double-buffered via cp.async with
// one-tile prefetch; one __syncthreads per tile. Q fragments in registers.
// Q/K/V are pre-rounded to tf32 by the QKV GEMM epilogue.
#define QP 68
#define VP 72
#define KVSTAGE (64 * QP + 64 * VP)
#define ATTN_SMEM ((128 * QP + 2 * KVSTAGE) * 4)

__global__ __launch_bounds__(256, 2) void attn_kernel(
    const float* __restrict__ QKV, float* __restrict__ O)
{
    extern __shared__ float sm[];
    float* Pp = sm;                          // [128][QP] Q staging, then P
    const uint32_t sbase = (uint32_t)__cvta_generic_to_shared(sm);

    const int tid  = threadIdx.x;
    const int lane = tid & 31;
    const int w    = tid >> 5;       // warp id: query rows w*16..w*16+15
    const int r    = lane >> 2;      // 0..7
    const int c    = lane & 3;       // 0..3
    const int qt   = (gridDim.x - 1) - blockIdx.x;   // big tiles first
    const int bh   = blockIdx.y;
    const int b    = bh >> 3, h = bh & 7;
    const int q0   = qt * 128;
    const size_t base  = ((size_t)b * T_) * LDQ + h * DK_;
    const size_t obase = ((size_t)b * T_) * D_  + h * DK_;
    const float* Qg = QKV + base;
    const float* Kg = QKV + base + 512;
    const float* Vg = QKV + base + 1024;

    auto issue_kv = [&](int kt) {
        const int j0 = kt * 64;
        const uint32_t kb = sbase + (uint32_t)(128 * QP + (kt & 1) * KVSTAGE) * 4;
        const uint32_t vb = kb + 64 * QP * 4;
        #pragma unroll
        for (int i = 0; i < 4; i++) {
            int idx = tid + i * 256;           // 0..1023 float4s
            int s   = idx >> 4;                // 0..63
            int d4  = (idx & 15) * 4;
            cp16(kb + (uint32_t)(s * QP + d4) * 4,
                 Kg + (size_t)(j0 + s) * LDQ + d4);
            cp16(vb + (uint32_t)(s * VP + d4) * 4,
                 Vg + (size_t)(j0 + s) * LDQ + d4);
        }
        CP_COMMIT();
    };

    issue_kv(0);                              // overlaps Q staging below

    // ---- stage Q tile (already tf32-rounded), hoist fragments to regs ----
    #pragma unroll
    for (int i = 0; i < 8; i++) {
        int fidx = tid + i * 256;            // 0..2047 float4s
        int row  = fidx >> 4;                // 0..127
        int d4   = (fidx & 15) * 4;          // 0..60
        float4 qv = *(const float4*)(Qg + (size_t)(q0 + row) * LDQ + d4);
        *(float4*)&Pp[row * QP + d4] = qv;
    }
    __syncthreads();
    uint32_t qf[8][4];
    #pragma unroll
    for (int ks = 0; ks < 8; ks++) {
        const int qa = (w * 16 + r) * QP + ks * 8 + c;
        qf[ks][0] = __float_as_uint(Pp[qa]);
        qf[ks][1] = __float_as_uint(Pp[qa + 8 * QP]);
        qf[ks][2] = __float_as_uint(Pp[qa + 4]);
        qf[ks][3] = __float_as_uint(Pp[qa + 8 * QP + 4]);
    }

    // online-softmax state: thread owns rows (w*16+r) and (w*16+r+8)
    float m_[2] = {-1e30f, -1e30f};
    float l_[2] = {0.0f, 0.0f};
    float oacc[8][4];
    #pragma unroll
    for (int ni = 0; ni < 8; ni++)
        oacc[ni][0] = oacc[ni][1] = oacc[ni][2] = oacc[ni][3] = 0.0f;

    const int ntile = (q0 >> 6) + 2;          // causal: key tiles 0..(q0+127)/64

    for (int kt = 0; kt < ntile; kt++) {
        const int j0 = kt * 64;
        const float* Ks = sm + 128 * QP + (kt & 1) * KVSTAGE;
        const float* Vs = Ks + 64 * QP;

        asm volatile("cp.async.wait_group 0;" ::: "memory");
        __syncthreads();                      // tile kt visible to all
        if (kt + 1 < ntile) issue_kv(kt + 1); // prefetch (buffer safe: its
                                              // readers finished pre-sync)

        // ---- S = Q K^T : [16 q] x [64 s], contraction over d=64 ----
        float sacc[8][4];
        #pragma unroll
        for (int ni = 0; ni < 8; ni++)
            sacc[ni][0] = sacc[ni][1] = sacc[ni][2] = sacc[ni][3] = 0.0f;
        #pragma unroll
        for (int ks = 0; ks < 8; ks++) {
            #pragma unroll
            for (int ni = 0; ni < 8; ni++) {
                uint32_t bf[2];
                const int kb = (ni * 8 + r) * QP + ks * 8 + c;
                bf[0] = __float_as_uint(Ks[kb]);
                bf[1] = __float_as_uint(Ks[kb + 4]);
                mma_tf32(sacc[ni], qf[ks], bf);
            }
        }

        // ---- causal mask (pre-scale, matches ref) + online softmax ----
        const bool full = (j0 + 64 <= q0 + w * 16);   // warp-uniform
        #pragma unroll
        for (int ri = 0; ri < 2; ri++) {
            const int tg = q0 + w * 16 + r + ri * 8;
            float rm = -1e30f;
            if (full) {
                #pragma unroll
                for (int ni = 0; ni < 8; ni++) {
                    #pragma unroll
                    for (int jj = 0; jj < 2; jj++) {
                        float v = sacc[ni][ri * 2 + jj] * 0.125f;
                        sacc[ni][ri * 2 + jj] = v;
                        rm = fmaxf(rm, v);
                    }
                }
            } else {
                #pragma unroll
                for (int ni = 0; ni < 8; ni++) {
                    #pragma unroll
                    for (int jj = 0; jj < 2; jj++) {
                        int sg = j0 + ni * 8 + 2 * c + jj;
                        float v = (sg <= tg) ? sacc[ni][ri * 2 + jj] * 0.125f
                                             : -1e30f;
                        sacc[ni][ri * 2 + jj] = v;
                        rm = fmaxf(rm, v);
                    }
                }
            }
            rm = fmaxf(rm, __shfl_xor_sync(0xffffffffu, rm, 1));
            rm = fmaxf(rm, __shfl_xor_sync(0xffffffffu, rm, 2));
            const float mn    = fmaxf(m_[ri], rm);
            const float alpha = __expf(m_[ri] - mn);
            m_[ri] = mn;
            float ps = 0.0f;
            #pragma unroll
            for (int ni = 0; ni < 8; ni++) {
                #pragma unroll
                for (int jj = 0; jj < 2; jj++) {
                    float p = __expf(sacc[ni][ri * 2 + jj] - mn);
                    sacc[ni][ri * 2 + jj] = p;
                    ps += p;
                }
            }
            ps += __shfl_xor_sync(0xffffffffu, ps, 1);
            ps += __shfl_xor_sync(0xffffffffu, ps, 2);
            l_[ri] = l_[ri] * alpha + ps;
            #pragma unroll
            for (int ni = 0; ni < 8; ni++) {
                oacc[ni][ri * 2 + 0] *= alpha;
                oacc[ni][ri * 2 + 1] *= alpha;
            }
        }

        // ---- stage P (tf32) into warp-private rows of Pp ----
        #pragma unroll
        for (int ni = 0; ni < 8; ni++) {
            float2 p0, p1;
            p0.x = __uint_as_float(f2tf32(sacc[ni][0]));
            p0.y = __uint_as_float(f2tf32(sacc[ni][1]));
            p1.x = __uint_as_float(f2tf32(sacc[ni][2]));
            p1.y = __uint_as_float(f2tf32(sacc[ni][3]));
            *(float2*)&Pp[(w * 16 + r)     * QP + ni * 8 + 2 * c] = p0;
            *(float2*)&Pp[(w * 16 + r + 8) * QP + ni * 8 + 2 * c] = p1;
        }
        __syncwarp();

        // ---- O += P V : contraction over s=64, output cols d=64 ----
        #pragma unroll
        for (int ks = 0; ks < 8; ks++) {
            uint32_t af[4];
            const int pa = (w * 16 + r) * QP + ks * 8 + c;
            af[0] = __float_as_uint(Pp[pa]);
            af[1] = __float_as_uint(Pp[pa + 8 * QP]);
            af[2] = __float_as_uint(Pp[pa + 4]);
            af[3] = __float_as_uint(Pp[pa + 8 * QP + 4]);
            #pragma unroll
            for (int ni = 0; ni < 8; ni++) {
                uint32_t bf[2];
                bf[0] = __float_as_uint(Vs[(ks * 8 + c)     * VP + ni * 8 + r]);
                bf[1] = __float_as_uint(Vs[(ks * 8 + c + 4) * VP + ni * 8 + r]);
                mma_tf32(oacc[ni], af, bf);
            }
        }
    }

    // ---- normalize, tf32-round (consumed only by proj GEMM), write out ----
    const float inv0 = 1.0f / l_[0];
    const float inv1 = 1.0f / l_[1];
    const int row0g = q0 + w * 16 + r;
    #pragma unroll
    for (int ni = 0; ni < 8; ni++) {
        const int col = ni * 8 + 2 * c;
        float2 a0, a1;
        a0.x = __uint_as_float(f2tf32(oacc[ni][0] * inv0));
        a0.y = __uint_as_float(f2tf32(oacc[ni][1] * inv0));
        a1.x = __uint_as_float(f2tf32(oacc[ni][2] * inv1));
        a1.y = __uint_as_float(f2tf32(oacc[ni][3] * inv1));
        *(float2*)(O + obase + (size_t)row0g * D_ + col) = a0;
        *(float2*)(O + obase + (size_t)(row0g + 8) * D_ + col) = a1;
    }
}

// ---------------- launcher ---------------------------------------------------
extern "C" void kernel_launch(void* const* d_in, const int* in_sizes, int n_in,
                              void* d_out, int out_size)
{
    const float* x   = (const float*)d_in[0];
    const float* Wq  = (const float*)d_in[1];
    const float* bq  = (const float*)d_in[2];
    const float* Wk  = (const float*)d_in[3];
    const float* bk  = (const float*)d_in[4];
    const float* Wv  = (const float*)d_in[5];
    const float* bv  = (const float*)d_in[6];
    const float* Wp  = (const float*)d_in[7];
    const float* bp  = (const float*)d_in[8];
    const float* W1  = (const float*)d_in[9];
    const float* b1  = (const float*)d_in[10];
    const float* W2  = (const float*)d_in[11];
    const float* b2  = (const float*)d_in[12];
    const float* g1  = (const float*)d_in[13];
    const float* be1 = (const float*)d_in[14];
    const float* g2  = (const float*)d_in[15];
    const float* be2 = (const float*)d_in[16];
    float* out = (float*)d_out;

    float *h, *qkv, *o, *x1, *h2, *ff, *wr;
    cudaGetSymbolAddress((void**)&h,   g_h);
    cudaGetSymbolAddress((void**)&qkv, g_qkv);
    cudaGetSymbolAddress((void**)&o,   g_o);
    cudaGetSymbolAddress((void**)&x1,  g_x1);
    cudaGetSymbolAddress((void**)&h2,  g_h2);
    cudaGetSymbolAddress((void**)&ff,  g_ff);
    cudaGetSymbolAddress((void**)&wr,  g_w);

    float* wq = wr;                    // 262144 each
    float* wk = wr + 262144;
    float* wv = wr + 524288;
    float* wp = wr + 786432;
    float* w1 = wr + 1048576;          // 1048576
    float* w2 = wr + 2097152;          // 1048576

    cudaFuncSetAttribute(attn_kernel,
                         cudaFuncAttributeMaxDynamicSharedMemorySize, ATTN_SMEM);
    cudaFuncSetAttribute(gemm_kernel,
                         cudaFuncAttributeMaxDynamicSharedMemorySize, GEMM_SMEM);

    // pre-round weights to tf32 (rna), raw-copied by cp.async later
    round_kernel<<<256,  256>>>(Wq, wq);
    round_kernel<<<256,  256>>>(Wk, wk);
    round_kernel<<<256,  256>>>(Wv, wv);
    round_kernel<<<256,  256>>>(Wp, wp);
    round_kernel<<<1024, 256>>>(W1, w1);
    round_kernel<<<1024, 256>>>(W2, w2);

    // LN1 (tf32-rounded output)
    ln_kernel<<<BT_, 128>>>(x, g1, be1, h);

    // fused QKV projection (head-stacked weights: cstride = D*DK, ldb = DK)
    gemm_kernel<<<dim3(LDQ / 128, BT_ / 128), 256, GEMM_SMEM>>>(
        h, D_, wq, wk, wv, D_ * DK_, DK_, bq, bk, bv,
        nullptr, qkv, LDQ, D_, 0, 1, 1);

    // causal attention (tensor-core, cp.async double-buffered)
    attn_kernel<<<dim3(T_ / 128, B_ * H_), 256, ATTN_SMEM>>>(qkv, o);

    // output projection + residual (row-major weights: cstride = 64, ldb = N)
    dim3 g512(D_ / 128, BT_ / 128);
    gemm_kernel<<<g512, 256, GEMM_SMEM>>>(o, D_, wp, wp, wp, 64, D_,
                                          bp, bp, bp, x, x1, D_, D_, 0, 0, 0);

    // LN2 (tf32-rounded output)
    ln_kernel<<<BT_, 128>>>(x1, g2, be2, h2);

    // FFN
    gemm_kernel<<<dim3(DFF_ / 128, BT_ / 128), 256, GEMM_SMEM>>>(
        h2, D_, w1, w1, w1, 64, DFF_, b1, b1, b1,
        nullptr, ff, DFF_, D_, 1, 0, 1);
    gemm_kernel<<<g512, 256, GEMM_SMEM>>>(ff, DFF_, w2, w2, w2, 64, D_,
                                          b2, b2, b2, x1, out, D_, DFF_, 0, 0, 0);
}

// round 10
// speedup vs baseline: 1.2562x; 1.0278x over previous
#include <cuda_runtime.h>
#include <cstdint>

#define B_   4
#define T_   2048
#define D_   512
#define H_   8
#define DK_  64
#define BT_  (B_ * T_)
#define DFF_ 2048
#define LDQ  1536      // fused QKV row stride

// 0.125 * log2(e): folds the 1/sqrt(64) scale and base-e->base-2 conversion
#define SCL2 0.18033688011111772f

// ---------------- scratch (static device globals; no allocations) ----------
__device__ float g_h  [BT_ * D_];
__device__ float g_qkv[BT_ * LDQ];  // [BT, 1536]: Q | K | V each 512 cols
__device__ float g_o  [BT_ * D_];   // attention output, concat-head layout
__device__ float g_x1 [BT_ * D_];
__device__ float g_h2 [BT_ * D_];
__device__ float g_ff [BT_ * DFF_];
__device__ float g_w  [4 * 262144 + 2 * 1048576];  // tf32-rounded weights

// ---------------- tf32 helpers ----------------------------------------------
__device__ __forceinline__ uint32_t f2tf32(float x) {
    uint32_t u;
    asm("cvt.rna.tf32.f32 %0, %1;" : "=r"(u) : "f"(x));
    return u;
}

__device__ __forceinline__ void mma_tf32(float* d, const uint32_t* a,
                                         const uint32_t* b) {
    asm volatile(
        "mma.sync.aligned.m16n8k8.row.col.f32.tf32.tf32.f32 "
        "{%0,%1,%2,%3}, {%4,%5,%6,%7}, {%8,%9}, {%0,%1,%2,%3};"
        : "+f"(d[0]), "+f"(d[1]), "+f"(d[2]), "+f"(d[3])
        : "r"(a[0]), "r"(a[1]), "r"(a[2]), "r"(a[3]),
          "r"(b[0]), "r"(b[1]));
}

__device__ __forceinline__ void cp16(uint32_t dst_smem, const void* src) {
    asm volatile("cp.async.cg.shared.global [%0], [%1], 16;"
                 :: "r"(dst_smem), "l"(src) : "memory");
}
#define CP_COMMIT() asm volatile("cp.async.commit_group;" ::: "memory")

// ---------------- fused weight pre-rounding (rna to tf32) -------------------
// One launch covers all six weight tensors (dst = g_w, contiguous).
__global__ __launch_bounds__(256) void round_all_kernel(
    const float* __restrict__ Wq, const float* __restrict__ Wk,
    const float* __restrict__ Wv, const float* __restrict__ Wp,
    const float* __restrict__ W1, const float* __restrict__ W2,
    float* __restrict__ dst)
{
    const int i = blockIdx.x * 256 + threadIdx.x;   // float4 index, 0..786431
    const float4* src;
    int off;
    if      (i <  65536) { src = (const float4*)Wq; off = i; }
    else if (i < 131072) { src = (const float4*)Wk; off = i - 65536; }
    else if (i < 196608) { src = (const float4*)Wv; off = i - 131072; }
    else if (i < 262144) { src = (const float4*)Wp; off = i - 196608; }
    else if (i < 524288) { src = (const float4*)W1; off = i - 262144; }
    else                 { src = (const float4*)W2; off = i - 524288; }
    float4 v = src[off];
    float4 r;
    r.x = __uint_as_float(f2tf32(v.x));
    r.y = __uint_as_float(f2tf32(v.y));
    r.z = __uint_as_float(f2tf32(v.z));
    r.w = __uint_as_float(f2tf32(v.w));
    ((float4*)dst)[i] = r;
}

// ---------------- LayerNorm: one block per row of 512 -----------------------
// Output is tf32-rounded (it is consumed only by tensor-core GEMMs).
__global__ __launch_bounds__(128) void ln_kernel(
    const float* __restrict__ x, const float* __restrict__ g,
    const float* __restrict__ b, float* __restrict__ out)
{
    const int row = blockIdx.x;
    const int tid = threadIdx.x;                 // 128 threads * float4 = 512
    float4 v = ((const float4*)(x + (size_t)row * D_))[tid];
    float s  = v.x + v.y + v.z + v.w;
    float ss = v.x * v.x + v.y * v.y + v.z * v.z + v.w * v.w;
    #pragma unroll
    for (int o = 16; o > 0; o >>= 1) {
        s  += __shfl_xor_sync(0xffffffffu, s,  o);
        ss += __shfl_xor_sync(0xffffffffu, ss, o);
    }
    __shared__ float sh_s[4], sh_ss[4];
    if ((tid & 31) == 0) { sh_s[tid >> 5] = s; sh_ss[tid >> 5] = ss; }
    __syncthreads();
    const float tot  = sh_s[0] + sh_s[1] + sh_s[2] + sh_s[3];
    const float tots = sh_ss[0] + sh_ss[1] + sh_ss[2] + sh_ss[3];
    const float mu   = tot  * (1.0f / D_);
    const float var  = tots * (1.0f / D_) - mu * mu;
    const float rstd = rsqrtf(var + 1e-5f);
    float4 gv = ((const float4*)g)[tid];
    float4 bv = ((const float4*)b)[tid];
    float4 r;
    r.x = __uint_as_float(f2tf32((v.x - mu) * rstd * gv.x + bv.x));
    r.y = __uint_as_float(f2tf32((v.y - mu) * rstd * gv.y + bv.y));
    r.z = __uint_as_float(f2tf32((v.z - mu) * rstd * gv.z + bv.z));
    r.w = __uint_as_float(f2tf32((v.w - mu) * rstd * gv.w + bv.w));
    ((float4*)(out + (size_t)row * D_))[tid] = r;
}

// ---------------- tf32 tensor-core GEMM, 128x128 tile, cp.async 3-stage -----
// C[row, col] = sum_k A[row, k] * B(k, col) (+bias[col]) (+res[row,col])
//               (relu) (rnd: tf32-round the stored result)
// A and B(weights) must already be tf32-rounded values in fp32 format.
// Weight addressing within a group: addr(k, col) = W + (col>>6)*cstride
//                                                  + k*ldb + (col&63)
// qkv mode: cols [0,512) use W0/b0, [512,1024) W1/b1, [1024,1536) W2/b2.
#define PAD_A 36
#define PAD_B 136
#define ASTAGE (128 * PAD_A)                 // 4608 floats
#define STAGE  (ASTAGE + 32 * PAD_B)         // 8960 floats
#define GEMM_SMEM (3 * STAGE * 4)            // 107520 bytes

__global__ __launch_bounds__(256, 2) void gemm_kernel(
    const float* __restrict__ A, int lda,
    const float* __restrict__ W0, const float* __restrict__ W1g,
    const float* __restrict__ W2g, int cstride, int ldb,
    const float* __restrict__ b0, const float* __restrict__ b1g,
    const float* __restrict__ b2g,
    const float* __restrict__ res,
    float* __restrict__ C, int ldc,
    int K, int relu, int qkv, int rnd)
{
    extern __shared__ float smg[];
    const uint32_t sbase = (uint32_t)__cvta_generic_to_shared(smg);

    const int tid  = threadIdx.x;
    const int lane = tid & 31;
    const int wid  = tid >> 5;
    const int wm   = wid & 1;        // row block of 64
    const int wn   = wid >> 1;       // col block of 32
    const int row0 = blockIdx.y * 128;
    const int col0 = blockIdx.x * 128;

    const int grp = qkv ? (col0 >> 9) : 0;
    const float* Wsel = (grp == 0) ? W0 : ((grp == 1) ? W1g : W2g);
    const float* bsel = (grp == 0) ? b0 : ((grp == 1) ? b1g : b2g);
    const int col0g = qkv ? (col0 & 511) : col0;
    const float* B0 = Wsel + (size_t)(col0g >> 6) * cstride; // cols [col0,+64)
    const float* B1 = B0 + cstride;                          // cols [+64,+128)

    const int r = lane >> 2;         // 0..7
    const int c = lane & 3;          // 0..3

    float acc[4][4][4];
    #pragma unroll
    for (int mi = 0; mi < 4; mi++)
        #pragma unroll
        for (int ni = 0; ni < 4; ni++)
            acc[mi][ni][0] = acc[mi][ni][1] = acc[mi][ni][2] = acc[mi][ni][3] = 0.f;

    const int niter = K >> 5;

    auto issue_stage = [&](int it) {
        const int k0 = it * 32;
        const uint32_t ab = sbase + (uint32_t)((it % 3) * STAGE) * 4;
        const uint32_t bb = ab + ASTAGE * 4;
        #pragma unroll
        for (int i = 0; i < 4; i++) {
            int idx = tid + i * 256;            // A: 0..1023 float4s
            int m   = idx >> 3;                 // 0..127
            int kk  = (idx & 7) * 4;            // 0..28
            cp16(ab + (uint32_t)(m * PAD_A + kk) * 4,
                 A + (size_t)(row0 + m) * lda + k0 + kk);
        }
        #pragma unroll
        for (int i = 0; i < 4; i++) {
            int idx = tid + i * 256;            // B: 0..1023 float4s
            int kk  = idx >> 5;                 // 0..31
            int n4  = (idx & 31) * 4;           // 0..124
            const float* src = (n4 < 64)
                ? (B0 + (size_t)(k0 + kk) * ldb + n4)
                : (B1 + (size_t)(k0 + kk) * ldb + (n4 - 64));
            cp16(bb + (uint32_t)(kk * PAD_B + n4) * 4, src);
        }
        CP_COMMIT();
    };

    issue_stage(0);
    issue_stage(1);

    for (int it = 0; it < niter; it++) {
        if (it < niter - 1)
            asm volatile("cp.async.wait_group 1;" ::: "memory");
        else
            asm volatile("cp.async.wait_group 0;" ::: "memory");
        __syncthreads();
        if (it + 2 < niter) issue_stage(it + 2);

        const float* Ac = smg + (it % 3) * STAGE;
        const float* Bc = Ac + ASTAGE;

        #pragma unroll
        for (int ks = 0; ks < 32; ks += 8) {
            uint32_t af[4][4], bf[4][2];
            #pragma unroll
            for (int mi = 0; mi < 4; mi++) {
                int m = wm * 64 + mi * 16 + r;
                af[mi][0] = __float_as_uint(Ac[m * PAD_A + ks + c]);
                af[mi][1] = __float_as_uint(Ac[(m + 8) * PAD_A + ks + c]);
                af[mi][2] = __float_as_uint(Ac[m * PAD_A + ks + c + 4]);
                af[mi][3] = __float_as_uint(Ac[(m + 8) * PAD_A + ks + c + 4]);
            }
            #pragma unroll
            for (int ni = 0; ni < 4; ni++) {
                int n = wn * 32 + ni * 8 + r;
                bf[ni][0] = __float_as_uint(Bc[(ks + c) * PAD_B + n]);
                bf[ni][1] = __float_as_uint(Bc[(ks + c + 4) * PAD_B + n]);
            }
            #pragma unroll
            for (int mi = 0; mi < 4; mi++)
                #pragma unroll
                for (int ni = 0; ni < 4; ni++)
                    mma_tf32(acc[mi][ni], af[mi], bf[ni]);
        }
    }

    // --- epilogue: bias (+res) (relu) (rnd) ---
    #pragma unroll
    for (int mi = 0; mi < 4; mi++) {
        const int row_a = row0 + wm * 64 + mi * 16 + r;
        const size_t ro0 = (size_t)row_a * ldc;
        const size_t ro1 = (size_t)(row_a + 8) * ldc;
        #pragma unroll
        for (int ni = 0; ni < 4; ni++) {
            const int col_a = col0 + wn * 32 + ni * 8 + 2 * c;
            const int col_b = qkv ? (col_a & 511) : col_a;
            float2 bb = *(const float2*)(bsel + col_b);
            float v0 = acc[mi][ni][0] + bb.x;
            float v1 = acc[mi][ni][1] + bb.y;
            float v2 = acc[mi][ni][2] + bb.x;
            float v3 = acc[mi][ni][3] + bb.y;
            if (res) {
                float2 r0v = *(const float2*)(res + ro0 + col_a);
                float2 r1v = *(const float2*)(res + ro1 + col_a);
                v0 += r0v.x; v1 += r0v.y; v2 += r1v.x; v3 += r1v.y;
            }
            if (relu) {
                v0 = fmaxf(v0, 0.f); v1 = fmaxf(v1, 0.f);
                v2 = fmaxf(v2, 0.f); v3 = fmaxf(v3, 0.f);
            }
            if (rnd) {
                v0 = __uint_as_float(f2tf32(v0));
                v1 = __uint_as_float(f2tf32(v1));
                v2 = __uint_as_float(f2tf32(v2));
                v3 = __uint_as_float(f2tf32(v3));
            }
            *(float2*)(C + ro0 + col_a) = make_float2(v0, v1);
            *(float2*)(C + ro1 + col_a) = make_float2(v2, v3);
        }
    }
}

// ---------------- tf32 tensor-core causal flash attention -------------------
// grid: (T/128 q-tiles reversed, B*H). block 256 = 8 warps; warp w owns query
// rows [w*16, w*16+16). k-tile = 64 keys, double-buffered via cp.async with
// one-tile prefetch; one __syncthreads per tile. Q fragments in registers.
// Softmax in base-2 domain: p = exp2(fma(s, SCL2, -mn*SCL2)), m in raw units.
#define QP 68
#define VP 72
#define KVSTAGE (64 * QP + 64 * VP)
#define ATTN_SMEM ((128 * QP + 2 * KVSTAGE) * 4)

__global__ __launch_bounds__(256, 2) void attn_kernel(
    const float* __restrict__ QKV, float* __restrict__ O)
{
    extern __shared__ float sm[];
    float* Pp = sm;                          // [128][QP] Q staging, then P
    const uint32_t sbase = (uint32_t)__cvta_generic_to_shared(sm);

    const int tid  = threadIdx.x;
    const int lane = tid & 31;
    const int w    = tid >> 5;       // warp id: query rows w*16..w*16+15
    const int r    = lane >> 2;      // 0..7
    const int c    = lane & 3;       // 0..3
    const int qt   = (gridDim.x - 1) - blockIdx.x;   // big tiles first
    const int bh   = blockIdx.y;
    const int b    = bh >> 3, h = bh & 7;
    const int q0   = qt * 128;
    const size_t base  = ((size_t)b * T_) * LDQ + h * DK_;
    const size_t obase = ((size_t)b * T_) * D_  + h * DK_;
    const float* Qg = QKV + base;
    const float* Kg = QKV + base + 512;
    const float* Vg = QKV + base + 1024;

    auto issue_kv = [&](int kt) {
        const int j0 = kt * 64;
        const uint32_t kb = sbase + (uint32_t)(128 * QP + (kt & 1) * KVSTAGE) * 4;
        const uint32_t vb = kb + 64 * QP * 4;
        #pragma unroll
        for (int i = 0; i < 4; i++) {
            int idx = tid + i * 256;           // 0..1023 float4s
            int s   = idx >> 4;                // 0..63
            int d4  = (idx & 15) * 4;
            cp16(kb + (uint32_t)(s * QP + d4) * 4,
                 Kg + (size_t)(j0 + s) * LDQ + d4);
            cp16(vb + (uint32_t)(s * VP + d4) * 4,
                 Vg + (size_t)(j0 + s) * LDQ + d4);
        }
        CP_COMMIT();
    };

    issue_kv(0);                              // overlaps Q staging below

    // ---- stage Q tile (already tf32-rounded), hoist fragments to regs ----
    #pragma unroll
    for (int i = 0; i < 8; i++) {
        int fidx = tid + i * 256;            // 0..2047 float4s
        int row  = fidx >> 4;                // 0..127
        int d4   = (fidx & 15) * 4;          // 0..60
        float4 qv = *(const float4*)(Qg + (size_t)(q0 + row) * LDQ + d4);
        *(float4*)&Pp[row * QP + d4] = qv;
    }
    __syncthreads();
    uint32_t qf[8][4];
    #pragma unroll
    for (int ks = 0; ks < 8; ks++) {
        const int qa = (w * 16 + r) * QP + ks * 8 + c;
        qf[ks][0] = __float_as_uint(Pp[qa]);
        qf[ks][1] = __float_as_uint(Pp[qa + 8 * QP]);
        qf[ks][2] = __float_as_uint(Pp[qa + 4]);
        qf[ks][3] = __float_as_uint(Pp[qa + 8 * QP + 4]);
    }

    // online-softmax state (m in raw score units)
    float m_[2] = {-1e30f, -1e30f};
    float l_[2] = {0.0f, 0.0f};
    float oacc[8][4];
    #pragma unroll
    for (int ni = 0; ni < 8; ni++)
        oacc[ni][0] = oacc[ni][1] = oacc[ni][2] = oacc[ni][3] = 0.0f;

    const int ntile = (q0 >> 6) + 2;          // causal: key tiles 0..(q0+127)/64

    for (int kt = 0; kt < ntile; kt++) {
        const int j0 = kt * 64;
        const float* Ks = sm + 128 * QP + (kt & 1) * KVSTAGE;
        const float* Vs = Ks + 64 * QP;

        asm volatile("cp.async.wait_group 0;" ::: "memory");
        __syncthreads();                      // tile kt visible to all
        if (kt + 1 < ntile) issue_kv(kt + 1); // prefetch (buffer safe: its
                                              // readers finished pre-sync)

        // ---- S = Q K^T : [16 q] x [64 s], contraction over d=64 ----
        float sacc[8][4];
        #pragma unroll
        for (int ni = 0; ni < 8; ni++)
            sacc[ni][0] = sacc[ni][1] = sacc[ni][2] = sacc[ni][3] = 0.0f;
        #pragma unroll
        for (int ks = 0; ks < 8; ks++) {
            #pragma unroll
            for (int ni = 0; ni < 8; ni++) {
                uint32_t bf[2];
                const int kb = (ni * 8 + r) * QP + ks * 8 + c;
                bf[0] = __float_as_uint(Ks[kb]);
                bf[1] = __float_as_uint(Ks[kb + 4]);
                mma_tf32(sacc[ni], qf[ks], bf);
            }
        }

        // ---- causal mask (raw units) + online softmax (base-2 domain) ----
        const bool full = (j0 + 64 <= q0 + w * 16);   // warp-uniform
        if (!full) {
            #pragma unroll
            for (int ri = 0; ri < 2; ri++) {
                const int tg = q0 + w * 16 + r + ri * 8;
                #pragma unroll
                for (int ni = 0; ni < 8; ni++)
                    #pragma unroll
                    for (int jj = 0; jj < 2; jj++) {
                        int sg = j0 + ni * 8 + 2 * c + jj;
                        if (sg > tg) sacc[ni][ri * 2 + jj] = -1e30f;
                    }
            }
        }
        #pragma unroll
        for (int ri = 0; ri < 2; ri++) {
            float rm = -1e30f;
            #pragma unroll
            for (int ni = 0; ni < 8; ni++) {
                rm = fmaxf(rm, sacc[ni][ri * 2 + 0]);
                rm = fmaxf(rm, sacc[ni][ri * 2 + 1]);
            }
            rm = fmaxf(rm, __shfl_xor_sync(0xffffffffu, rm, 1));
            rm = fmaxf(rm, __shfl_xor_sync(0xffffffffu, rm, 2));
            const float mn  = fmaxf(m_[ri], rm);
            const float mnC = mn * SCL2;
            // skip oacc rescale if no lane in warp raised its max this tile
            const unsigned upd = __ballot_sync(0xffffffffu, mn != m_[ri]);
            if (upd) {
                const float alpha = exp2f((m_[ri] - mn) * SCL2);
                #pragma unroll
                for (int ni = 0; ni < 8; ni++) {
                    oacc[ni][ri * 2 + 0] *= alpha;
                    oacc[ni][ri * 2 + 1] *= alpha;
                }
                l_[ri] *= alpha;
                m_[ri] = mn;
            }
            float ps = 0.0f;
            #pragma unroll
            for (int ni = 0; ni < 8; ni++) {
                #pragma unroll
                for (int jj = 0; jj < 2; jj++) {
                    float p = exp2f(fmaf(sacc[ni][ri * 2 + jj], SCL2, -mnC));
                    sacc[ni][ri * 2 + jj] = p;
                    ps += p;
                }
            }
            ps += __shfl_xor_sync(0xffffffffu, ps, 1);
            ps += __shfl_xor_sync(0xffffffffu, ps, 2);
            l_[ri] += ps;
        }

        // ---- stage P (tf32) into warp-private rows of Pp ----
        #pragma unroll
        for (int ni = 0; ni < 8; ni++) {
            float2 p0, p1;
            p0.x = __uint_as_float(f2tf32(sacc[ni][0]));
            p0.y = __uint_as_float(f2tf32(sacc[ni][1]));
            p1.x = __uint_as_float(f2tf32(sacc[ni][2]));
            p1.y = __uint_as_float(f2tf32(sacc[ni][3]));
            *(float2*)&Pp[(w * 16 + r)     * QP + ni * 8 + 2 * c] = p0;
            *(float2*)&Pp[(w * 16 + r + 8) * QP + ni * 8 + 2 * c] = p1;
        }
        __syncwarp();

        // ---- O += P V : contraction over s=64, output cols d=64 ----
        #pragma unroll
        for (int ks = 0; ks < 8; ks++) {
            uint32_t af[4];
            const int pa = (w * 16 + r) * QP + ks * 8 + c;
            af[0] = __float_as_uint(Pp[pa]);
            af[1] = __float_as_uint(Pp[pa + 8 * QP]);
            af[2] = __float_as_uint(Pp[pa + 4]);
            af[3] = __float_as_uint(Pp[pa + 8 * QP + 4]);
            #pragma unroll
            for (int ni = 0; ni < 8; ni++) {
                uint32_t bf[2];
                bf[0] = __float_as_uint(Vs[(ks * 8 + c)     * VP + ni * 8 + r]);
                bf[1] = __float_as_uint(Vs[(ks * 8 + c + 4) * VP + ni * 8 + r]);
                mma_tf32(oacc[ni], af, bf);
            }
        }
    }

    // ---- normalize, tf32-round (consumed only by proj GEMM), write out ----
    const float inv0 = 1.0f / l_[0];
    const float inv1 = 1.0f / l_[1];
    const int row0g = q0 + w * 16 + r;
    #pragma unroll
    for (int ni = 0; ni < 8; ni++) {
        const int col = ni * 8 + 2 * c;
        float2 a0, a1;
        a0.x = __uint_as_float(f2tf32(oacc[ni][0] * inv0));
        a0.y = __uint_as_float(f2tf32(oacc[ni][1] * inv0));
        a1.x = __uint_as_float(f2tf32(oacc[ni][2] * inv1));
        a1.y = __uint_as_float(f2tf32(oacc[ni][3] * inv1));
        *(float2*)(O + obase + (size_t)row0g * D_ + col) = a0;
        *(float2*)(O + obase + (size_t)(row0g + 8) * D_ + col) = a1;
    }
}

// ---------------- launcher ---------------------------------------------------
extern "C" void kernel_launch(void* const* d_in, const int* in_sizes, int n_in,
                              void* d_out, int out_size)
{
    const float* x   = (const float*)d_in[0];
    const float* Wq  = (const float*)d_in[1];
    const float* bq  = (const float*)d_in[2];
    const float* Wk  = (const float*)d_in[3];
    const float* bk  = (const float*)d_in[4];
    const float* Wv  = (const float*)d_in[5];
    const float* bv  = (const float*)d_in[6];
    const float* Wp  = (const float*)d_in[7];
    const float* bp  = (const float*)d_in[8];
    const float* W1  = (const float*)d_in[9];
    const float* b1  = (const float*)d_in[10];
    const float* W2  = (const float*)d_in[11];
    const float* b2  = (const float*)d_in[12];
    const float* g1  = (const float*)d_in[13];
    const float* be1 = (const float*)d_in[14];
    const float* g2  = (const float*)d_in[15];
    const float* be2 = (const float*)d_in[16];
    float* out = (float*)d_out;

    float *h, *qkv, *o, *x1, *h2, *ff, *wr;
    cudaGetSymbolAddress((void**)&h,   g_h);
    cudaGetSymbolAddress((void**)&qkv, g_qkv);
    cudaGetSymbolAddress((void**)&o,   g_o);
    cudaGetSymbolAddress((void**)&x1,  g_x1);
    cudaGetSymbolAddress((void**)&h2,  g_h2);
    cudaGetSymbolAddress((void**)&ff,  g_ff);
    cudaGetSymbolAddress((void**)&wr,  g_w);

    float* wq = wr;                    // 262144 each
    float* wk = wr + 262144;
    float* wv = wr + 524288;
    float* wp = wr + 786432;
    float* w1 = wr + 1048576;          // 1048576
    float* w2 = wr + 2097152;          // 1048576

    cudaFuncSetAttribute(attn_kernel,
                         cudaFuncAttributeMaxDynamicSharedMemorySize, ATTN_SMEM);
    cudaFuncSetAttribute(gemm_kernel,
                         cudaFuncAttributeMaxDynamicSharedMemorySize, GEMM_SMEM);

    // pre-round all weights to tf32 (rna) in one launch
    round_all_kernel<<<3072, 256>>>(Wq, Wk, Wv, Wp, W1, W2, wr);

    // LN1 (tf32-rounded output)
    ln_kernel<<<BT_, 128>>>(x, g1, be1, h);

    // fused QKV projection (head-stacked weights: cstride = D*DK, ldb = DK)
    gemm_kernel<<<dim3(LDQ / 128, BT_ / 128), 256, GEMM_SMEM>>>(
        h, D_, wq, wk, wv, D_ * DK_, DK_, bq, bk, bv,
        nullptr, qkv, LDQ, D_, 0, 1, 1);

    // causal attention (tensor-core, cp.async double-buffered)
    attn_kernel<<<dim3(T_ / 128, B_ * H_), 256, ATTN_SMEM>>>(qkv, o);

    // output projection + residual (row-major weights: cstride = 64, ldb = N)
    dim3 g512(D_ / 128, BT_ / 128);
    gemm_kernel<<<g512, 256, GEMM_SMEM>>>(o, D_, wp, wp, wp, 64, D_,
                                          bp, bp, bp, x, x1, D_, D_, 0, 0, 0);

    // LN2 (tf32-rounded output)
    ln_kernel<<<BT_, 128>>>(x1, g2, be2, h2);

    // FFN
    gemm_kernel<<<dim3(DFF_ / 128, BT_ / 128), 256, GEMM_SMEM>>>(
        h2, D_, w1, w1, w1, 64, DFF_, b1, b1, b1,
        nullptr, ff, DFF_, D_, 1, 0, 1);
    gemm_kernel<<<g512, 256, GEMM_SMEM>>>(ff, DFF_, w2, w2, w2, 64, D_,
                                          b2, b2, b2, x1, out, D_, DFF_, 0, 0, 0);
}

// round 11
// speedup vs baseline: 1.2913x; 1.0279x over previous
#include <cuda_runtime.h>
#include <cstdint>

#define B_   4
#define T_   2048
#define D_   512
#define H_   8
#define DK_  64
#define BT_  (B_ * T_)
#define DFF_ 2048
#define LDQ  1536      // fused QKV row stride

// 0.125 * log2(e): folds the 1/sqrt(64) scale and base-e->base-2 conversion
#define SCL2 0.18033688011111772f

// ---------------- scratch (static device globals; no allocations) ----------
__device__ float g_h  [BT_ * D_];
__device__ float g_qkv[BT_ * LDQ];  // [BT, 1536]: Q | K | V each 512 cols
__device__ float g_o  [BT_ * D_];   // attention output, concat-head layout
__device__ float g_x1 [BT_ * D_];
__device__ float g_h2 [BT_ * D_];
__device__ float g_ff [BT_ * DFF_];
__device__ float g_w  [4 * 262144 + 2 * 1048576];  // tf32-rounded weights

// ---------------- tf32 helpers ----------------------------------------------
__device__ __forceinline__ uint32_t f2tf32(float x) {
    uint32_t u;
    asm("cvt.rna.tf32.f32 %0, %1;" : "=r"(u) : "f"(x));
    return u;
}

__device__ __forceinline__ void mma_tf32(float* d, const uint32_t* a,
                                         const uint32_t* b) {
    asm volatile(
        "mma.sync.aligned.m16n8k8.row.col.f32.tf32.tf32.f32 "
        "{%0,%1,%2,%3}, {%4,%5,%6,%7}, {%8,%9}, {%0,%1,%2,%3};"
        : "+f"(d[0]), "+f"(d[1]), "+f"(d[2]), "+f"(d[3])
        : "r"(a[0]), "r"(a[1]), "r"(a[2]), "r"(a[3]),
          "r"(b[0]), "r"(b[1]));
}

__device__ __forceinline__ void cp16(uint32_t dst_smem, const void* src) {
    asm volatile("cp.async.cg.shared.global [%0], [%1], 16;"
                 :: "r"(dst_smem), "l"(src) : "memory");
}
#define CP_COMMIT() asm volatile("cp.async.commit_group;" ::: "memory")

// ---------------- fused weight pre-rounding (rna to tf32) -------------------
__global__ __launch_bounds__(256) void round_all_kernel(
    const float* __restrict__ Wq, const float* __restrict__ Wk,
    const float* __restrict__ Wv, const float* __restrict__ Wp,
    const float* __restrict__ W1, const float* __restrict__ W2,
    float* __restrict__ dst)
{
    const int i = blockIdx.x * 256 + threadIdx.x;   // float4 index, 0..786431
    const float4* src;
    int off;
    if      (i <  65536) { src = (const float4*)Wq; off = i; }
    else if (i < 131072) { src = (const float4*)Wk; off = i - 65536; }
    else if (i < 196608) { src = (const float4*)Wv; off = i - 131072; }
    else if (i < 262144) { src = (const float4*)Wp; off = i - 196608; }
    else if (i < 524288) { src = (const float4*)W1; off = i - 262144; }
    else                 { src = (const float4*)W2; off = i - 524288; }
    float4 v = src[off];
    float4 r;
    r.x = __uint_as_float(f2tf32(v.x));
    r.y = __uint_as_float(f2tf32(v.y));
    r.z = __uint_as_float(f2tf32(v.z));
    r.w = __uint_as_float(f2tf32(v.w));
    ((float4*)dst)[i] = r;
}

// ---------------- LayerNorm: one block per row of 512 -----------------------
// Output is tf32-rounded (it is consumed only by tensor-core GEMMs).
__global__ __launch_bounds__(128) void ln_kernel(
    const float* __restrict__ x, const float* __restrict__ g,
    const float* __restrict__ b, float* __restrict__ out)
{
    const int row = blockIdx.x;
    const int tid = threadIdx.x;                 // 128 threads * float4 = 512
    float4 v = ((const float4*)(x + (size_t)row * D_))[tid];
    float s  = v.x + v.y + v.z + v.w;
    float ss = v.x * v.x + v.y * v.y + v.z * v.z + v.w * v.w;
    #pragma unroll
    for (int o = 16; o > 0; o >>= 1) {
        s  += __shfl_xor_sync(0xffffffffu, s,  o);
        ss += __shfl_xor_sync(0xffffffffu, ss, o);
    }
    __shared__ float sh_s[4], sh_ss[4];
    if ((tid & 31) == 0) { sh_s[tid >> 5] = s; sh_ss[tid >> 5] = ss; }
    __syncthreads();
    const float tot  = sh_s[0] + sh_s[1] + sh_s[2] + sh_s[3];
    const float tots = sh_ss[0] + sh_ss[1] + sh_ss[2] + sh_ss[3];
    const float mu   = tot  * (1.0f / D_);
    const float var  = tots * (1.0f / D_) - mu * mu;
    const float rstd = rsqrtf(var + 1e-5f);
    float4 gv = ((const float4*)g)[tid];
    float4 bv = ((const float4*)b)[tid];
    float4 r;
    r.x = __uint_as_float(f2tf32((v.x - mu) * rstd * gv.x + bv.x));
    r.y = __uint_as_float(f2tf32((v.y - mu) * rstd * gv.y + bv.y));
    r.z = __uint_as_float(f2tf32((v.z - mu) * rstd * gv.z + bv.z));
    r.w = __uint_as_float(f2tf32((v.w - mu) * rstd * gv.w + bv.w));
    ((float4*)(out + (size_t)row * D_))[tid] = r;
}

// ---------------- tf32 tensor-core GEMM, 128x128 tile, cp.async 3-stage -----
#define PAD_A 36
#define PAD_B 136
#define ASTAGE (128 * PAD_A)                 // 4608 floats
#define STAGE  (ASTAGE + 32 * PAD_B)         // 8960 floats
#define GEMM_SMEM (3 * STAGE * 4)            // 107520 bytes

__global__ __launch_bounds__(256, 2) void gemm_kernel(
    const float* __restrict__ A, int lda,
    const float* __restrict__ W0, const float* __restrict__ W1g,
    const float* __restrict__ W2g, int cstride, int ldb,
    const float* __restrict__ b0, const float* __restrict__ b1g,
    const float* __restrict__ b2g,
    const float* __restrict__ res,
    float* __restrict__ C, int ldc,
    int K, int relu, int qkv, int rnd)
{
    extern __shared__ float smg[];
    const uint32_t sbase = (uint32_t)__cvta_generic_to_shared(smg);

    const int tid  = threadIdx.x;
    const int lane = tid & 31;
    const int wid  = tid >> 5;
    const int wm   = wid & 1;        // row block of 64
    const int wn   = wid >> 1;       // col block of 32
    const int row0 = blockIdx.y * 128;
    const int col0 = blockIdx.x * 128;

    const int grp = qkv ? (col0 >> 9) : 0;
    const float* Wsel = (grp == 0) ? W0 : ((grp == 1) ? W1g : W2g);
    const float* bsel = (grp == 0) ? b0 : ((grp == 1) ? b1g : b2g);
    const int col0g = qkv ? (col0 & 511) : col0;
    const float* B0 = Wsel + (size_t)(col0g >> 6) * cstride; // cols [col0,+64)
    const float* B1 = B0 + cstride;                          // cols [+64,+128)

    const int r = lane >> 2;         // 0..7
    const int c = lane & 3;          // 0..3

    float acc[4][4][4];
    #pragma unroll
    for (int mi = 0; mi < 4; mi++)
        #pragma unroll
        for (int ni = 0; ni < 4; ni++)
            acc[mi][ni][0] = acc[mi][ni][1] = acc[mi][ni][2] = acc[mi][ni][3] = 0.f;

    const int niter = K >> 5;

    auto issue_stage = [&](int it) {
        const int k0 = it * 32;
        const uint32_t ab = sbase + (uint32_t)((it % 3) * STAGE) * 4;
        const uint32_t bb = ab + ASTAGE * 4;
        #pragma unroll
        for (int i = 0; i < 4; i++) {
            int idx = tid + i * 256;            // A: 0..1023 float4s
            int m   = idx >> 3;                 // 0..127
            int kk  = (idx & 7) * 4;            // 0..28
            cp16(ab + (uint32_t)(m * PAD_A + kk) * 4,
                 A + (size_t)(row0 + m) * lda + k0 + kk);
        }
        #pragma unroll
        for (int i = 0; i < 4; i++) {
            int idx = tid + i * 256;            // B: 0..1023 float4s
            int kk  = idx >> 5;                 // 0..31
            int n4  = (idx & 31) * 4;           // 0..124
            const float* src = (n4 < 64)
                ? (B0 + (size_t)(k0 + kk) * ldb + n4)
                : (B1 + (size_t)(k0 + kk) * ldb + (n4 - 64));
            cp16(bb + (uint32_t)(kk * PAD_B + n4) * 4, src);
        }
        CP_COMMIT();
    };

    issue_stage(0);
    issue_stage(1);

    for (int it = 0; it < niter; it++) {
        if (it < niter - 1)
            asm volatile("cp.async.wait_group 1;" ::: "memory");
        else
            asm volatile("cp.async.wait_group 0;" ::: "memory");
        __syncthreads();
        if (it + 2 < niter) issue_stage(it + 2);

        const float* Ac = smg + (it % 3) * STAGE;
        const float* Bc = Ac + ASTAGE;

        #pragma unroll
        for (int ks = 0; ks < 32; ks += 8) {
            uint32_t af[4][4], bf[4][2];
            #pragma unroll
            for (int mi = 0; mi < 4; mi++) {
                int m = wm * 64 + mi * 16 + r;
                af[mi][0] = __float_as_uint(Ac[m * PAD_A + ks + c]);
                af[mi][1] = __float_as_uint(Ac[(m + 8) * PAD_A + ks + c]);
                af[mi][2] = __float_as_uint(Ac[m * PAD_A + ks + c + 4]);
                af[mi][3] = __float_as_uint(Ac[(m + 8) * PAD_A + ks + c + 4]);
            }
            #pragma unroll
            for (int ni = 0; ni < 4; ni++) {
                int n = wn * 32 + ni * 8 + r;
                bf[ni][0] = __float_as_uint(Bc[(ks + c) * PAD_B + n]);
                bf[ni][1] = __float_as_uint(Bc[(ks + c + 4) * PAD_B + n]);
            }
            #pragma unroll
            for (int mi = 0; mi < 4; mi++)
                #pragma unroll
                for (int ni = 0; ni < 4; ni++)
                    mma_tf32(acc[mi][ni], af[mi], bf[ni]);
        }
    }

    // --- epilogue: bias (+res) (relu) (rnd) ---
    #pragma unroll
    for (int mi = 0; mi < 4; mi++) {
        const int row_a = row0 + wm * 64 + mi * 16 + r;
        const size_t ro0 = (size_t)row_a * ldc;
        const size_t ro1 = (size_t)(row_a + 8) * ldc;
        #pragma unroll
        for (int ni = 0; ni < 4; ni++) {
            const int col_a = col0 + wn * 32 + ni * 8 + 2 * c;
            const int col_b = qkv ? (col_a & 511) : col_a;
            float2 bb = *(const float2*)(bsel + col_b);
            float v0 = acc[mi][ni][0] + bb.x;
            float v1 = acc[mi][ni][1] + bb.y;
            float v2 = acc[mi][ni][2] + bb.x;
            float v3 = acc[mi][ni][3] + bb.y;
            if (res) {
                float2 r0v = *(const float2*)(res + ro0 + col_a);
                float2 r1v = *(const float2*)(res + ro1 + col_a);
                v0 += r0v.x; v1 += r0v.y; v2 += r1v.x; v3 += r1v.y;
            }
            if (relu) {
                v0 = fmaxf(v0, 0.f); v1 = fmaxf(v1, 0.f);
                v2 = fmaxf(v2, 0.f); v3 = fmaxf(v3, 0.f);
            }
            if (rnd) {
                v0 = __uint_as_float(f2tf32(v0));
                v1 = __uint_as_float(f2tf32(v1));
                v2 = __uint_as_float(f2tf32(v2));
                v3 = __uint_as_float(f2tf32(v3));
            }
            *(float2*)(C + ro0 + col_a) = make_float2(v0, v1);
            *(float2*)(C + ro1 + col_a) = make_float2(v2, v3);
        }
    }
}

// ---------------- tf32 tensor-core causal flash attention -------------------
// grid: (T/128 q-tiles reversed, B*H). block 256 = 8 warps; warp w owns query
// rows [w*16, w*16+16). k-tile = 64 keys, cp.async double-buffered, one
// __syncthreads per tile. Q fragments in registers. P NEVER goes to smem:
// the softmax result sacc is fed directly as the A fragment of the O-mma;
// the C->A fragment column permutation (2c,2c+1 vs c,c+4) is cancelled by
// permuting V row indices in the B fragment (rows ks*8+2c / ks*8+2c+1).
// Pad 68 (=4 mod 32) keeps both K and permuted-V accesses conflict-free.
#define QP 68
#define KVSTAGE (2 * 64 * QP)                  // K tile + V tile (floats)
#define ATTN_SMEM (2 * KVSTAGE * 4)            // 69632 bytes

__global__ __launch_bounds__(256, 2) void attn_kernel(
    const float* __restrict__ QKV, float* __restrict__ O)
{
    extern __shared__ float sm[];
    const uint32_t sbase = (uint32_t)__cvta_generic_to_shared(sm);

    const int tid  = threadIdx.x;
    const int lane = tid & 31;
    const int w    = tid >> 5;       // warp id: query rows w*16..w*16+15
    const int r    = lane >> 2;      // 0..7
    const int c    = lane & 3;       // 0..3
    const int qt   = (gridDim.x - 1) - blockIdx.x;   // big tiles first
    const int bh   = blockIdx.y;
    const int b    = bh >> 3, h = bh & 7;
    const int q0   = qt * 128;
    const size_t base  = ((size_t)b * T_) * LDQ + h * DK_;
    const size_t obase = ((size_t)b * T_) * D_  + h * DK_;
    const float* Qg = QKV + base;
    const float* Kg = QKV + base + 512;
    const float* Vg = QKV + base + 1024;

    auto issue_kv = [&](int kt) {
        const int j0 = kt * 64;
        const uint32_t kb = sbase + (uint32_t)((kt & 1) * KVSTAGE) * 4;
        const uint32_t vb = kb + 64 * QP * 4;
        #pragma unroll
        for (int i = 0; i < 4; i++) {
            int idx = tid + i * 256;           // 0..1023 float4s
            int s   = idx >> 4;                // 0..63
            int d4  = (idx & 15) * 4;
            cp16(kb + (uint32_t)(s * QP + d4) * 4,
                 Kg + (size_t)(j0 + s) * LDQ + d4);
            cp16(vb + (uint32_t)(s * QP + d4) * 4,
                 Vg + (size_t)(j0 + s) * LDQ + d4);
        }
        CP_COMMIT();
    };

    issue_kv(0);                              // into KV0; overlaps Q staging

    // ---- stage Q tile through the KV1 buffer (dead until tile 1), hoist
    //      fragments to registers ----
    float* Qstage = sm + KVSTAGE;             // 128*68 floats = KV1 exactly
    #pragma unroll
    for (int i = 0; i < 8; i++) {
        int fidx = tid + i * 256;            // 0..2047 float4s
        int row  = fidx >> 4;                // 0..127
        int d4   = (fidx & 15) * 4;          // 0..60
        float4 qv = *(const float4*)(Qg + (size_t)(q0 + row) * LDQ + d4);
        *(float4*)&Qstage[row * QP + d4] = qv;
    }
    __syncthreads();
    uint32_t qf[8][4];
    #pragma unroll
    for (int ks = 0; ks < 8; ks++) {
        const int qa = (w * 16 + r) * QP + ks * 8 + c;
        qf[ks][0] = __float_as_uint(Qstage[qa]);
        qf[ks][1] = __float_as_uint(Qstage[qa + 8 * QP]);
        qf[ks][2] = __float_as_uint(Qstage[qa + 4]);
        qf[ks][3] = __float_as_uint(Qstage[qa + 8 * QP + 4]);
    }
    // NOTE: issue_kv(1) (which overwrites KV1) happens only after the next
    // __syncthreads inside the loop, so every warp has read qf by then.

    // online-softmax state (m in raw score units)
    float m_[2] = {-1e30f, -1e30f};
    float l_[2] = {0.0f, 0.0f};
    float oacc[8][4];
    #pragma unroll
    for (int ni = 0; ni < 8; ni++)
        oacc[ni][0] = oacc[ni][1] = oacc[ni][2] = oacc[ni][3] = 0.0f;

    const int ntile = (q0 >> 6) + 2;          // causal: key tiles 0..(q0+127)/64

    for (int kt = 0; kt < ntile; kt++) {
        const int j0 = kt * 64;
        const float* Ks = sm + (kt & 1) * KVSTAGE;
        const float* Vs = Ks + 64 * QP;

        asm volatile("cp.async.wait_group 0;" ::: "memory");
        __syncthreads();                      // tile kt visible to all
        if (kt + 1 < ntile) issue_kv(kt + 1); // prefetch (buffer safe: its
                                              // readers finished pre-sync)

        // ---- S = Q K^T : [16 q] x [64 s], contraction over d=64 ----
        float sacc[8][4];
        #pragma unroll
        for (int ni = 0; ni < 8; ni++)
            sacc[ni][0] = sacc[ni][1] = sacc[ni][2] = sacc[ni][3] = 0.0f;
        #pragma unroll
        for (int ks = 0; ks < 8; ks++) {
            #pragma unroll
            for (int ni = 0; ni < 8; ni++) {
                uint32_t bf[2];
                const int kb = (ni * 8 + r) * QP + ks * 8 + c;
                bf[0] = __float_as_uint(Ks[kb]);
                bf[1] = __float_as_uint(Ks[kb + 4]);
                mma_tf32(sacc[ni], qf[ks], bf);
            }
        }

        // ---- causal mask (raw units) + online softmax (base-2 domain) ----
        const bool full = (j0 + 64 <= q0 + w * 16);   // warp-uniform
        if (!full) {
            #pragma unroll
            for (int ri = 0; ri < 2; ri++) {
                const int tg = q0 + w * 16 + r + ri * 8;
                #pragma unroll
                for (int ni = 0; ni < 8; ni++)
                    #pragma unroll
                    for (int jj = 0; jj < 2; jj++) {
                        int sg = j0 + ni * 8 + 2 * c + jj;
                        if (sg > tg) sacc[ni][ri * 2 + jj] = -1e30f;
                    }
            }
        }
        #pragma unroll
        for (int ri = 0; ri < 2; ri++) {
            float rm = -1e30f;
            #pragma unroll
            for (int ni = 0; ni < 8; ni++) {
                rm = fmaxf(rm, sacc[ni][ri * 2 + 0]);
                rm = fmaxf(rm, sacc[ni][ri * 2 + 1]);
            }
            rm = fmaxf(rm, __shfl_xor_sync(0xffffffffu, rm, 1));
            rm = fmaxf(rm, __shfl_xor_sync(0xffffffffu, rm, 2));
            const float mn  = fmaxf(m_[ri], rm);
            const float mnC = mn * SCL2;
            // skip oacc rescale if no lane in warp raised its max this tile
            const unsigned upd = __ballot_sync(0xffffffffu, mn != m_[ri]);
            if (upd) {
                const float alpha = exp2f((m_[ri] - mn) * SCL2);
                #pragma unroll
                for (int ni = 0; ni < 8; ni++) {
                    oacc[ni][ri * 2 + 0] *= alpha;
                    oacc[ni][ri * 2 + 1] *= alpha;
                }
                l_[ri] *= alpha;
                m_[ri] = mn;
            }
            float ps = 0.0f;
            #pragma unroll
            for (int ni = 0; ni < 8; ni++) {
                #pragma unroll
                for (int jj = 0; jj < 2; jj++) {
                    float p = exp2f(fmaf(sacc[ni][ri * 2 + jj], SCL2, -mnC));
                    ps += p;
                    // rna-round in registers; this value feeds the mma
                    sacc[ni][ri * 2 + jj] = __uint_as_float(f2tf32(p));
                }
            }
            ps += __shfl_xor_sync(0xffffffffu, ps, 1);
            ps += __shfl_xor_sync(0xffffffffu, ps, 2);
            l_[ri] += ps;
        }

        // ---- O += P V : P straight from registers (C-frag as A-frag with
        //      V rows permuted: slot k=c <- row 2c, slot k=c+4 <- row 2c+1) --
        #pragma unroll
        for (int ks = 0; ks < 8; ks++) {
            uint32_t af[4];
            af[0] = __float_as_uint(sacc[ks][0]);  // P[r   ][2c]
            af[1] = __float_as_uint(sacc[ks][2]);  // P[r+8 ][2c]
            af[2] = __float_as_uint(sacc[ks][1]);  // P[r   ][2c+1]
            af[3] = __float_as_uint(sacc[ks][3]);  // P[r+8 ][2c+1]
            #pragma unroll
            for (int ni = 0; ni < 8; ni++) {
                uint32_t bf[2];
                bf[0] = __float_as_uint(Vs[(ks * 8 + 2 * c)     * QP + ni * 8 + r]);
                bf[1] = __float_as_uint(Vs[(ks * 8 + 2 * c + 1) * QP + ni * 8 + r]);
                mma_tf32(oacc[ni], af, bf);
            }
        }
    }

    // ---- normalize, tf32-round (consumed only by proj GEMM), write out ----
    const float inv0 = 1.0f / l_[0];
    const float inv1 = 1.0f / l_[1];
    const int row0g = q0 + w * 16 + r;
    #pragma unroll
    for (int ni = 0; ni < 8; ni++) {
        const int col = ni * 8 + 2 * c;
        float2 a0, a1;
        a0.x = __uint_as_float(f2tf32(oacc[ni][0] * inv0));
        a0.y = __uint_as_float(f2tf32(oacc[ni][1] * inv0));
        a1.x = __uint_as_float(f2tf32(oacc[ni][2] * inv1));
        a1.y = __uint_as_float(f2tf32(oacc[ni][3] * inv1));
        *(float2*)(O + obase + (size_t)row0g * D_ + col) = a0;
        *(float2*)(O + obase + (size_t)(row0g + 8) * D_ + col) = a1;
    }
}

// ---------------- launcher ---------------------------------------------------
extern "C" void kernel_launch(void* const* d_in, const int* in_sizes, int n_in,
                              void* d_out, int out_size)
{
    const float* x   = (const float*)d_in[0];
    const float* Wq  = (const float*)d_in[1];
    const float* bq  = (const float*)d_in[2];
    const float* Wk  = (const float*)d_in[3];
    const float* bk  = (const float*)d_in[4];
    const float* Wv  = (const float*)d_in[5];
    const float* bv  = (const float*)d_in[6];
    const float* Wp  = (const float*)d_in[7];
    const float* bp  = (const float*)d_in[8];
    const float* W1  = (const float*)d_in[9];
    const float* b1  = (const float*)d_in[10];
    const float* W2  = (const float*)d_in[11];
    const float* b2  = (const float*)d_in[12];
    const float* g1  = (const float*)d_in[13];
    const float* be1 = (const float*)d_in[14];
    const float* g2  = (const float*)d_in[15];
    const float* be2 = (const float*)d_in[16];
    float* out = (float*)d_out;

    float *h, *qkv, *o, *x1, *h2, *ff, *wr;
    cudaGetSymbolAddress((void**)&h,   g_h);
    cudaGetSymbolAddress((void**)&qkv, g_qkv);
    cudaGetSymbolAddress((void**)&o,   g_o);
    cudaGetSymbolAddress((void**)&x1,  g_x1);
    cudaGetSymbolAddress((void**)&h2,  g_h2);
    cudaGetSymbolAddress((void**)&ff,  g_ff);
    cudaGetSymbolAddress((void**)&wr,  g_w);

    float* wq = wr;                    // 262144 each
    float* wk = wr + 262144;
    float* wv = wr + 524288;
    float* wp = wr + 786432;
    float* w1 = wr + 1048576;          // 1048576
    float* w2 = wr + 2097152;          // 1048576

    cudaFuncSetAttribute(attn_kernel,
                         cudaFuncAttributeMaxDynamicSharedMemorySize, ATTN_SMEM);
    cudaFuncSetAttribute(gemm_kernel,
                         cudaFuncAttributeMaxDynamicSharedMemorySize, GEMM_SMEM);

    // pre-round all weights to tf32 (rna) in one launch
    round_all_kernel<<<3072, 256>>>(Wq, Wk, Wv, Wp, W1, W2, wr);

    // LN1 (tf32-rounded output)
    ln_kernel<<<BT_, 128>>>(x, g1, be1, h);

    // fused QKV projection (head-stacked weights: cstride = D*DK, ldb = DK)
    gemm_kernel<<<dim3(LDQ / 128, BT_ / 128), 256, GEMM_SMEM>>>(
        h, D_, wq, wk, wv, D_ * DK_, DK_, bq, bk, bv,
        nullptr, qkv, LDQ, D_, 0, 1, 1);

    // causal attention (tensor-core, cp.async double-buffered, P-in-regs)
    attn_kernel<<<dim3(T_ / 128, B_ * H_), 256, ATTN_SMEM>>>(qkv, o);

    // output projection + residual (row-major weights: cstride = 64, ldb = N)
    dim3 g512(D_ / 128, BT_ / 128);
    gemm_kernel<<<g512, 256, GEMM_SMEM>>>(o, D_, wp, wp, wp, 64, D_,
                                          bp, bp, bp, x, x1, D_, D_, 0, 0, 0);

    // LN2 (tf32-rounded output)
    ln_kernel<<<BT_, 128>>>(x1, g2, be2, h2);

    // FFN
    gemm_kernel<<<dim3(DFF_ / 128, BT_ / 128), 256, GEMM_SMEM>>>(
        h2, D_, w1, w1, w1, 64, DFF_, b1, b1, b1,
        nullptr, ff, DFF_, D_, 1, 0, 1);
    gemm_kernel<<<g512, 256, GEMM_SMEM>>>(ff, DFF_, w2, w2, w2, 64, D_,
                                          b2, b2, b2, x1, out, D_, DFF_, 0, 0, 0);
}

// round 12
// speedup vs baseline: 1.4447x; 1.1188x over previous
#include <cuda_runtime.h>
#include <cuda_bf16.h>
#include <cstdint>

#define B_   4
#define T_   2048
#define D_   512
#define H_   8
#define DK_  64
#define BT_  (B_ * T_)
#define DFF_ 2048
#define LDQ  1536      // fused QKV row stride

// 0.125 * log2(e): folds the 1/sqrt(64) scale and base-e->base-2 conversion
#define SCL2 0.18033688011111772f

// ---------------- scratch (static device globals; no allocations) ----------
__device__ float g_h  [BT_ * D_];
__device__ float g_qkv[BT_ * LDQ];  // [BT, 1536]: Q | K | V each 512 cols
__device__ __nv_bfloat16 g_vb[BT_ * D_];   // V in bf16, [BT, 512]
__device__ float g_o  [BT_ * D_];   // attention output, concat-head layout
__device__ float g_x1 [BT_ * D_];
__device__ float g_h2 [BT_ * D_];
__device__ float g_ff [BT_ * DFF_];
__device__ float g_w  [4 * 262144 + 2 * 1048576];  // tf32-rounded weights

// ---------------- tf32 / bf16 helpers ----------------------------------------
__device__ __forceinline__ uint32_t f2tf32(float x) {
    uint32_t u;
    asm("cvt.rna.tf32.f32 %0, %1;" : "=r"(u) : "f"(x));
    return u;
}

// pack two floats into bf16x2: lo <- x, hi <- y
__device__ __forceinline__ uint32_t pack_bf16x2(float x, float y) {
    uint32_t u;
    asm("cvt.rn.bf16x2.f32 %0, %1, %2;" : "=r"(u) : "f"(y), "f"(x));
    return u;
}

__device__ __forceinline__ void mma_tf32(float* d, const uint32_t* a,
                                         const uint32_t* b) {
    asm volatile(
        "mma.sync.aligned.m16n8k8.row.col.f32.tf32.tf32.f32 "
        "{%0,%1,%2,%3}, {%4,%5,%6,%7}, {%8,%9}, {%0,%1,%2,%3};"
        : "+f"(d[0]), "+f"(d[1]), "+f"(d[2]), "+f"(d[3])
        : "r"(a[0]), "r"(a[1]), "r"(a[2]), "r"(a[3]),
          "r"(b[0]), "r"(b[1]));
}

__device__ __forceinline__ void mma_bf16(float* d, const uint32_t* a,
                                         uint32_t b0, uint32_t b1) {
    asm volatile(
        "mma.sync.aligned.m16n8k16.row.col.f32.bf16.bf16.f32 "
        "{%0,%1,%2,%3}, {%4,%5,%6,%7}, {%8,%9}, {%0,%1,%2,%3};"
        : "+f"(d[0]), "+f"(d[1]), "+f"(d[2]), "+f"(d[3])
        : "r"(a[0]), "r"(a[1]), "r"(a[2]), "r"(a[3]),
          "r"(b0), "r"(b1));
}

__device__ __forceinline__ void cp16(uint32_t dst_smem, const void* src) {
    asm volatile("cp.async.cg.shared.global [%0], [%1], 16;"
                 :: "r"(dst_smem), "l"(src) : "memory");
}
#define CP_COMMIT() asm volatile("cp.async.commit_group;" ::: "memory")

// ---------------- fused weight pre-rounding (rna to tf32) -------------------
__global__ __launch_bounds__(256) void round_all_kernel(
    const float* __restrict__ Wq, const float* __restrict__ Wk,
    const float* __restrict__ Wv, const float* __restrict__ Wp,
    const float* __restrict__ W1, const float* __restrict__ W2,
    float* __restrict__ dst)
{
    const int i = blockIdx.x * 256 + threadIdx.x;   // float4 index, 0..786431
    const float4* src;
    int off;
    if      (i <  65536) { src = (const float4*)Wq; off = i; }
    else if (i < 131072) { src = (const float4*)Wk; off = i - 65536; }
    else if (i < 196608) { src = (const float4*)Wv; off = i - 131072; }
    else if (i < 262144) { src = (const float4*)Wp; off = i - 196608; }
    else if (i < 524288) { src = (const float4*)W1; off = i - 262144; }
    else                 { src = (const float4*)W2; off = i - 524288; }
    float4 v = src[off];
    float4 r;
    r.x = __uint_as_float(f2tf32(v.x));
    r.y = __uint_as_float(f2tf32(v.y));
    r.z = __uint_as_float(f2tf32(v.z));
    r.w = __uint_as_float(f2tf32(v.w));
    ((float4*)dst)[i] = r;
}

// ---------------- LayerNorm: one block per row of 512 -----------------------
// Output is tf32-rounded (it is consumed only by tensor-core GEMMs).
__global__ __launch_bounds__(128) void ln_kernel(
    const float* __restrict__ x, const float* __restrict__ g,
    const float* __restrict__ b, float* __restrict__ out)
{
    const int row = blockIdx.x;
    const int tid = threadIdx.x;                 // 128 threads * float4 = 512
    float4 v = ((const float4*)(x + (size_t)row * D_))[tid];
    float s  = v.x + v.y + v.z + v.w;
    float ss = v.x * v.x + v.y * v.y + v.z * v.z + v.w * v.w;
    #pragma unroll
    for (int o = 16; o > 0; o >>= 1) {
        s  += __shfl_xor_sync(0xffffffffu, s,  o);
        ss += __shfl_xor_sync(0xffffffffu, ss, o);
    }
    __shared__ float sh_s[4], sh_ss[4];
    if ((tid & 31) == 0) { sh_s[tid >> 5] = s; sh_ss[tid >> 5] = ss; }
    __syncthreads();
    const float tot  = sh_s[0] + sh_s[1] + sh_s[2] + sh_s[3];
    const float tots = sh_ss[0] + sh_ss[1] + sh_ss[2] + sh_ss[3];
    const float mu   = tot  * (1.0f / D_);
    const float var  = tots * (1.0f / D_) - mu * mu;
    const float rstd = rsqrtf(var + 1e-5f);
    float4 gv = ((const float4*)g)[tid];
    float4 bv = ((const float4*)b)[tid];
    float4 r;
    r.x = __uint_as_float(f2tf32((v.x - mu) * rstd * gv.x + bv.x));
    r.y = __uint_as_float(f2tf32((v.y - mu) * rstd * gv.y + bv.y));
    r.z = __uint_as_float(f2tf32((v.z - mu) * rstd * gv.z + bv.z));
    r.w = __uint_as_float(f2tf32((v.w - mu) * rstd * gv.w + bv.w));
    ((float4*)(out + (size_t)row * D_))[tid] = r;
}

// ---------------- tf32 tensor-core GEMM, 128x128 tile, cp.async 3-stage -----
#define PAD_A 36
#define PAD_B 136
#define ASTAGE (128 * PAD_A)                 // 4608 floats
#define STAGE  (ASTAGE + 32 * PAD_B)         // 8960 floats
#define GEMM_SMEM (3 * STAGE * 4)            // 107520 bytes

__global__ __launch_bounds__(256, 2) void gemm_kernel(
    const float* __restrict__ A, int lda,
    const float* __restrict__ W0, const float* __restrict__ W1g,
    const float* __restrict__ W2g, int cstride, int ldb,
    const float* __restrict__ b0, const float* __restrict__ b1g,
    const float* __restrict__ b2g,
    const float* __restrict__ res,
    float* __restrict__ C, int ldc,
    int K, int relu, int qkv, int rnd,
    __nv_bfloat16* __restrict__ Vb)
{
    extern __shared__ float smg[];
    const uint32_t sbase = (uint32_t)__cvta_generic_to_shared(smg);

    const int tid  = threadIdx.x;
    const int lane = tid & 31;
    const int wid  = tid >> 5;
    const int wm   = wid & 1;        // row block of 64
    const int wn   = wid >> 1;       // col block of 32
    const int row0 = blockIdx.y * 128;
    const int col0 = blockIdx.x * 128;

    const int grp = qkv ? (col0 >> 9) : 0;
    const float* Wsel = (grp == 0) ? W0 : ((grp == 1) ? W1g : W2g);
    const float* bsel = (grp == 0) ? b0 : ((grp == 1) ? b1g : b2g);
    const int col0g = qkv ? (col0 & 511) : col0;
    const float* B0 = Wsel + (size_t)(col0g >> 6) * cstride; // cols [col0,+64)
    const float* B1 = B0 + cstride;                          // cols [+64,+128)

    const int r = lane >> 2;         // 0..7
    const int c = lane & 3;          // 0..3

    float acc[4][4][4];
    #pragma unroll
    for (int mi = 0; mi < 4; mi++)
        #pragma unroll
        for (int ni = 0; ni < 4; ni++)
            acc[mi][ni][0] = acc[mi][ni][1] = acc[mi][ni][2] = acc[mi][ni][3] = 0.f;

    const int niter = K >> 5;

    auto issue_stage = [&](int it) {
        const int k0 = it * 32;
        const uint32_t ab = sbase + (uint32_t)((it % 3) * STAGE) * 4;
        const uint32_t bb = ab + ASTAGE * 4;
        #pragma unroll
        for (int i = 0; i < 4; i++) {
            int idx = tid + i * 256;            // A: 0..1023 float4s
            int m   = idx >> 3;                 // 0..127
            int kk  = (idx & 7) * 4;            // 0..28
            cp16(ab + (uint32_t)(m * PAD_A + kk) * 4,
                 A + (size_t)(row0 + m) * lda + k0 + kk);
        }
        #pragma unroll
        for (int i = 0; i < 4; i++) {
            int idx = tid + i * 256;            // B: 0..1023 float4s
            int kk  = idx >> 5;                 // 0..31
            int n4  = (idx & 31) * 4;           // 0..124
            const float* src = (n4 < 64)
                ? (B0 + (size_t)(k0 + kk) * ldb + n4)
                : (B1 + (size_t)(k0 + kk) * ldb + (n4 - 64));
            cp16(bb + (uint32_t)(kk * PAD_B + n4) * 4, src);
        }
        CP_COMMIT();
    };

    issue_stage(0);
    issue_stage(1);

    for (int it = 0; it < niter; it++) {
        if (it < niter - 1)
            asm volatile("cp.async.wait_group 1;" ::: "memory");
        else
            asm volatile("cp.async.wait_group 0;" ::: "memory");
        __syncthreads();
        if (it + 2 < niter) issue_stage(it + 2);

        const float* Ac = smg + (it % 3) * STAGE;
        const float* Bc = Ac + ASTAGE;

        #pragma unroll
        for (int ks = 0; ks < 32; ks += 8) {
            uint32_t af[4][4], bf[4][2];
            #pragma unroll
            for (int mi = 0; mi < 4; mi++) {
                int m = wm * 64 + mi * 16 + r;
                af[mi][0] = __float_as_uint(Ac[m * PAD_A + ks + c]);
                af[mi][1] = __float_as_uint(Ac[(m + 8) * PAD_A + ks + c]);
                af[mi][2] = __float_as_uint(Ac[m * PAD_A + ks + c + 4]);
                af[mi][3] = __float_as_uint(Ac[(m + 8) * PAD_A + ks + c + 4]);
            }
            #pragma unroll
            for (int ni = 0; ni < 4; ni++) {
                int n = wn * 32 + ni * 8 + r;
                bf[ni][0] = __float_as_uint(Bc[(ks + c) * PAD_B + n]);
                bf[ni][1] = __float_as_uint(Bc[(ks + c + 4) * PAD_B + n]);
            }
            #pragma unroll
            for (int mi = 0; mi < 4; mi++)
                #pragma unroll
                for (int ni = 0; ni < 4; ni++)
                    mma_tf32(acc[mi][ni], af[mi], bf[ni]);
        }
    }

    // --- epilogue: bias (+res) (relu) (rnd); V group -> bf16 buffer ---
    const bool vgrp = (qkv != 0) && (grp == 2);
    #pragma unroll
    for (int mi = 0; mi < 4; mi++) {
        const int row_a = row0 + wm * 64 + mi * 16 + r;
        const size_t ro0 = (size_t)row_a * ldc;
        const size_t ro1 = (size_t)(row_a + 8) * ldc;
        #pragma unroll
        for (int ni = 0; ni < 4; ni++) {
            const int col_a = col0 + wn * 32 + ni * 8 + 2 * c;
            const int col_b = qkv ? (col_a & 511) : col_a;
            float2 bb = *(const float2*)(bsel + col_b);
            float v0 = acc[mi][ni][0] + bb.x;
            float v1 = acc[mi][ni][1] + bb.y;
            float v2 = acc[mi][ni][2] + bb.x;
            float v3 = acc[mi][ni][3] + bb.y;
            if (res) {
                float2 r0v = *(const float2*)(res + ro0 + col_a);
                float2 r1v = *(const float2*)(res + ro1 + col_a);
                v0 += r0v.x; v1 += r0v.y; v2 += r1v.x; v3 += r1v.y;
            }
            if (relu) {
                v0 = fmaxf(v0, 0.f); v1 = fmaxf(v1, 0.f);
                v2 = fmaxf(v2, 0.f); v3 = fmaxf(v3, 0.f);
            }
            if (vgrp) {
                // V is consumed only as bf16 by the attention O-mma
                *(uint32_t*)(Vb + (size_t)row_a * D_ + col_b) =
                    pack_bf16x2(v0, v1);
                *(uint32_t*)(Vb + (size_t)(row_a + 8) * D_ + col_b) =
                    pack_bf16x2(v2, v3);
            } else {
                if (rnd) {
                    v0 = __uint_as_float(f2tf32(v0));
                    v1 = __uint_as_float(f2tf32(v1));
                    v2 = __uint_as_float(f2tf32(v2));
                    v3 = __uint_as_float(f2tf32(v3));
                }
                *(float2*)(C + ro0 + col_a) = make_float2(v0, v1);
                *(float2*)(C + ro1 + col_a) = make_float2(v2, v3);
            }
        }
    }
}

// ---------------- tensor-core causal flash attention -------------------------
// S = QK^T in tf32 (m16n8k8). P*V in bf16 (m16n8k16): P packed straight from
// softmax registers (C-frag cols 2c,2c+1 = bf16 A-frag packing), V fragments
// via ldmatrix.m8n8.x4.trans.b16 from a bf16 V tile (row stride 144B keeps
// ldmatrix conflict-free). K tile fp32 [64][68], V tile bf16 [64][72].
#define QP 68
#define KVBYTES (64 * QP * 4 + 64 * 72 * 2)     // 17408 + 9216 = 26624
#define VOFF    (64 * QP * 4)                   // V region byte offset in stage
#define ATTN_SMEM (2 * KVBYTES)                 // 53248 bytes

__global__ __launch_bounds__(256, 2) void attn_kernel(
    const float* __restrict__ QKV, const __nv_bfloat16* __restrict__ VB,
    float* __restrict__ O)
{
    extern __shared__ float sm[];
    const uint32_t sbase = (uint32_t)__cvta_generic_to_shared(sm);

    const int tid  = threadIdx.x;
    const int lane = tid & 31;
    const int w    = tid >> 5;       // warp id: query rows w*16..w*16+15
    const int r    = lane >> 2;      // 0..7
    const int c    = lane & 3;       // 0..3
    const int qt   = (gridDim.x - 1) - blockIdx.x;   // big tiles first
    const int bh   = blockIdx.y;
    const int b    = bh >> 3, h = bh & 7;
    const int q0   = qt * 128;
    const size_t base  = ((size_t)b * T_) * LDQ + h * DK_;
    const size_t obase = ((size_t)b * T_) * D_  + h * DK_;
    const float* Qg = QKV + base;
    const float* Kg = QKV + base + 512;
    const __nv_bfloat16* Vg = VB + ((size_t)b * T_) * D_ + h * DK_;

    auto issue_kv = [&](int kt) {
        const int j0 = kt * 64;
        const uint32_t kb = sbase + (uint32_t)(kt & 1) * KVBYTES;
        const uint32_t vb = kb + VOFF;
        #pragma unroll
        for (int i = 0; i < 4; i++) {
            int idx = tid + i * 256;           // K: 0..1023 16B chunks
            int s   = idx >> 4;                // 0..63
            int d4  = (idx & 15) * 4;
            cp16(kb + (uint32_t)(s * QP + d4) * 4,
                 Kg + (size_t)(j0 + s) * LDQ + d4);
        }
        #pragma unroll
        for (int i = 0; i < 2; i++) {
            int idx = tid + i * 256;           // V: 0..511 16B chunks
            int s   = idx >> 3;                // 0..63
            int ch  = idx & 7;                 // 8 bf16 per chunk
            cp16(vb + (uint32_t)(s * 144 + ch * 16),
                 Vg + (size_t)(j0 + s) * D_ + ch * 8);
        }
        CP_COMMIT();
    };

    // ---- stage Q tile through the (not yet used) KV buffers, hoist to regs --
    #pragma unroll
    for (int i = 0; i < 8; i++) {
        int fidx = tid + i * 256;            // 0..2047 float4s
        int row  = fidx >> 4;                // 0..127
        int d4   = (fidx & 15) * 4;          // 0..60
        float4 qv = *(const float4*)(Qg + (size_t)(q0 + row) * LDQ + d4);
        *(float4*)&sm[row * QP + d4] = qv;
    }
    __syncthreads();
    uint32_t qf[8][4];
    #pragma unroll
    for (int ks = 0; ks < 8; ks++) {
        const int qa = (w * 16 + r) * QP + ks * 8 + c;
        qf[ks][0] = __float_as_uint(sm[qa]);
        qf[ks][1] = __float_as_uint(sm[qa + 8 * QP]);
        qf[ks][2] = __float_as_uint(sm[qa + 4]);
        qf[ks][3] = __float_as_uint(sm[qa + 8 * QP + 4]);
    }
    __syncthreads();                      // all warps done reading Q
    issue_kv(0);

    // ldmatrix per-thread address pattern (within a V tile)
    const int g8 = lane >> 3;             // matrix group 0..3
    const uint32_t vpat = (uint32_t)(((g8 & 1) * 8 + (lane & 7)) * 144
                                     + (g8 >> 1) * 16);

    // online-softmax state (m in raw score units)
    float m_[2] = {-1e30f, -1e30f};
    float l_[2] = {0.0f, 0.0f};
    float oacc[8][4];
    #pragma unroll
    for (int ni = 0; ni < 8; ni++)
        oacc[ni][0] = oacc[ni][1] = oacc[ni][2] = oacc[ni][3] = 0.0f;

    const int ntile = (q0 >> 6) + 2;          // causal: key tiles 0..(q0+127)/64

    for (int kt = 0; kt < ntile; kt++) {
        const int j0 = kt * 64;
        const float* Ks = sm + (kt & 1) * (KVBYTES / 4);
        const uint32_t vaddr = sbase + (uint32_t)(kt & 1) * KVBYTES + VOFF + vpat;

        asm volatile("cp.async.wait_group 0;" ::: "memory");
        __syncthreads();                      // tile kt visible to all
        if (kt + 1 < ntile) issue_kv(kt + 1); // prefetch (buffer safe: its
                                              // readers finished pre-sync)

        // ---- S = Q K^T : [16 q] x [64 s], contraction over d=64 (tf32) ----
        float sacc[8][4];
        #pragma unroll
        for (int ni = 0; ni < 8; ni++)
            sacc[ni][0] = sacc[ni][1] = sacc[ni][2] = sacc[ni][3] = 0.0f;
        #pragma unroll
        for (int ks = 0; ks < 8; ks++) {
            #pragma unroll
            for (int ni = 0; ni < 8; ni++) {
                uint32_t bf[2];
                const int kb = (ni * 8 + r) * QP + ks * 8 + c;
                bf[0] = __float_as_uint(Ks[kb]);
                bf[1] = __float_as_uint(Ks[kb + 4]);
                mma_tf32(sacc[ni], qf[ks], bf);
            }
        }

        // ---- causal mask (raw units) + online softmax (base-2 domain) ----
        const bool full = (j0 + 64 <= q0 + w * 16);   // warp-uniform
        if (!full) {
            #pragma unroll
            for (int ri = 0; ri < 2; ri++) {
                const int tg = q0 + w * 16 + r + ri * 8;
                #pragma unroll
                for (int ni = 0; ni < 8; ni++)
                    #pragma unroll
                    for (int jj = 0; jj < 2; jj++) {
                        int sg = j0 + ni * 8 + 2 * c + jj;
                        if (sg > tg) sacc[ni][ri * 2 + jj] = -1e30f;
                    }
            }
        }
        #pragma unroll
        for (int ri = 0; ri < 2; ri++) {
            float rm = -1e30f;
            #pragma unroll
            for (int ni = 0; ni < 8; ni++) {
                rm = fmaxf(rm, sacc[ni][ri * 2 + 0]);
                rm = fmaxf(rm, sacc[ni][ri * 2 + 1]);
            }
            rm = fmaxf(rm, __shfl_xor_sync(0xffffffffu, rm, 1));
            rm = fmaxf(rm, __shfl_xor_sync(0xffffffffu, rm, 2));
            const float mn  = fmaxf(m_[ri], rm);
            const float mnC = mn * SCL2;
            // skip oacc rescale if no lane in warp raised its max this tile
            const unsigned upd = __ballot_sync(0xffffffffu, mn != m_[ri]);
            if (upd) {
                const float alpha = exp2f((m_[ri] - mn) * SCL2);
                #pragma unroll
                for (int ni = 0; ni < 8; ni++) {
                    oacc[ni][ri * 2 + 0] *= alpha;
                    oacc[ni][ri * 2 + 1] *= alpha;
                }
                l_[ri] *= alpha;
                m_[ri] = mn;
            }
            float ps = 0.0f;
            #pragma unroll
            for (int ni = 0; ni < 8; ni++) {
                #pragma unroll
                for (int jj = 0; jj < 2; jj++) {
                    float p = exp2f(fmaf(sacc[ni][ri * 2 + jj], SCL2, -mnC));
                    ps += p;
                    sacc[ni][ri * 2 + jj] = p;
                }
            }
            ps += __shfl_xor_sync(0xffffffffu, ps, 1);
            ps += __shfl_xor_sync(0xffffffffu, ps, 2);
            l_[ri] += ps;
        }

        // ---- O += P V in bf16 (m16n8k16): P packed from registers, V via
        //      ldmatrix.trans. 4 k-blocks of 16 keys x 4 d-pairs of 16 dims. --
        #pragma unroll
        for (int k4 = 0; k4 < 4; k4++) {
            uint32_t a[4];
            a[0] = pack_bf16x2(sacc[2 * k4][0],     sacc[2 * k4][1]);
            a[1] = pack_bf16x2(sacc[2 * k4][2],     sacc[2 * k4][3]);
            a[2] = pack_bf16x2(sacc[2 * k4 + 1][0], sacc[2 * k4 + 1][1]);
            a[3] = pack_bf16x2(sacc[2 * k4 + 1][2], sacc[2 * k4 + 1][3]);
            #pragma unroll
            for (int dp = 0; dp < 4; dp++) {
                uint32_t m0, m1, m2, m3;
                const uint32_t addr = vaddr + (uint32_t)(k4 * 16 * 144 + dp * 32);
                asm volatile(
                    "ldmatrix.sync.aligned.m8n8.x4.trans.shared.b16 "
                    "{%0,%1,%2,%3}, [%4];"
                    : "=r"(m0), "=r"(m1), "=r"(m2), "=r"(m3) : "r"(addr));
                mma_bf16(oacc[2 * dp],     a, m0, m1);
                mma_bf16(oacc[2 * dp + 1], a, m2, m3);
            }
        }
    }

    // ---- normalize, tf32-round (consumed only by proj GEMM), write out ----
    const float inv0 = 1.0f / l_[0];
    const float inv1 = 1.0f / l_[1];
    const int row0g = q0 + w * 16 + r;
    #pragma unroll
    for (int ni = 0; ni < 8; ni++) {
        const int col = ni * 8 + 2 * c;
        float2 a0, a1;
        a0.x = __uint_as_float(f2tf32(oacc[ni][0] * inv0));
        a0.y = __uint_as_float(f2tf32(oacc[ni][1] * inv0));
        a1.x = __uint_as_float(f2tf32(oacc[ni][2] * inv1));
        a1.y = __uint_as_float(f2tf32(oacc[ni][3] * inv1));
        *(float2*)(O + obase + (size_t)row0g * D_ + col) = a0;
        *(float2*)(O + obase + (size_t)(row0g + 8) * D_ + col) = a1;
    }
}

// ---------------- launcher ---------------------------------------------------
extern "C" void kernel_launch(void* const* d_in, const int* in_sizes, int n_in,
                              void* d_out, int out_size)
{
    const float* x   = (const float*)d_in[0];
    const float* Wq  = (const float*)d_in[1];
    const float* bq  = (const float*)d_in[2];
    const float* Wk  = (const float*)d_in[3];
    const float* bk  = (const float*)d_in[4];
    const float* Wv  = (const float*)d_in[5];
    const float* bv  = (const float*)d_in[6];
    const float* Wp  = (const float*)d_in[7];
    const float* bp  = (const float*)d_in[8];
    const float* W1  = (const float*)d_in[9];
    const float* b1  = (const float*)d_in[10];
    const float* W2  = (const float*)d_in[11];
    const float* b2  = (const float*)d_in[12];
    const float* g1  = (const float*)d_in[13];
    const float* be1 = (const float*)d_in[14];
    const float* g2  = (const float*)d_in[15];
    const float* be2 = (const float*)d_in[16];
    float* out = (float*)d_out;

    float *h, *qkv, *o, *x1, *h2, *ff, *wr;
    __nv_bfloat16* vb;
    cudaGetSymbolAddress((void**)&h,   g_h);
    cudaGetSymbolAddress((void**)&qkv, g_qkv);
    cudaGetSymbolAddress((void**)&vb,  g_vb);
    cudaGetSymbolAddress((void**)&o,   g_o);
    cudaGetSymbolAddress((void**)&x1,  g_x1);
    cudaGetSymbolAddress((void**)&h2,  g_h2);
    cudaGetSymbolAddress((void**)&ff,  g_ff);
    cudaGetSymbolAddress((void**)&wr,  g_w);

    float* wq = wr;                    // 262144 each
    float* wk = wr + 262144;
    float* wv = wr + 524288;
    float* wp = wr + 786432;
    float* w1 = wr + 1048576;          // 1048576
    float* w2 = wr + 2097152;          // 1048576

    cudaFuncSetAttribute(attn_kernel,
                         cudaFuncAttributeMaxDynamicSharedMemorySize, ATTN_SMEM);
    cudaFuncSetAttribute(gemm_kernel,
                         cudaFuncAttributeMaxDynamicSharedMemorySize, GEMM_SMEM);

    // pre-round all weights to tf32 (rna) in one launch
    round_all_kernel<<<3072, 256>>>(Wq, Wk, Wv, Wp, W1, W2, wr);

    // LN1 (tf32-rounded output)
    ln_kernel<<<BT_, 128>>>(x, g1, be1, h);

    // fused QKV projection (head-stacked weights: cstride = D*DK, ldb = DK);
    // V group lands in the bf16 buffer
    gemm_kernel<<<dim3(LDQ / 128, BT_ / 128), 256, GEMM_SMEM>>>(
        h, D_, wq, wk, wv, D_ * DK_, DK_, bq, bk, bv,
        nullptr, qkv, LDQ, D_, 0, 1, 1, vb);

    // causal attention (tf32 S, bf16 PV, cp.async double-buffered)
    attn_kernel<<<dim3(T_ / 128, B_ * H_), 256, ATTN_SMEM>>>(qkv, vb, o);

    // output projection + residual (row-major weights: cstride = 64, ldb = N)
    dim3 g512(D_ / 128, BT_ / 128);
    gemm_kernel<<<g512, 256, GEMM_SMEM>>>(o, D_, wp, wp, wp, 64, D_,
                                          bp, bp, bp, x, x1, D_, D_, 0, 0, 0,
                                          nullptr);

    // LN2 (tf32-rounded output)
    ln_kernel<<<BT_, 128>>>(x1, g2, be2, h2);

    // FFN
    gemm_kernel<<<dim3(DFF_ / 128, BT_ / 128), 256, GEMM_SMEM>>>(
        h2, D_, w1, w1, w1, 64, DFF_, b1, b1, b1,
        nullptr, ff, DFF_, D_, 1, 0, 1, nullptr);
    gemm_kernel<<<g512, 256, GEMM_SMEM>>>(ff, DFF_, w2, w2, w2, 64, D_,
                                          b2, b2, b2, x1, out, D_, DFF_, 0, 0, 0,
                                          nullptr);
}

// round 13
// speedup vs baseline: 1.5523x; 1.0745x over previous
#include <cuda_runtime.h>
#include <cuda_bf16.h>
#include <cstdint>

#define B_   4
#define T_   2048
#define D_   512
#define H_   8
#define DK_  64
#define BT_  (B_ * T_)
#define DFF_ 2048
#define LDQ  1536      // fused QKV col count (bf16 buffer)

// 0.125 * log2(e): folds the 1/sqrt(64) scale and base-e->base-2 conversion
#define SCL2 0.18033688011111772f

// ---------------- scratch (static device globals; no allocations) ----------
__device__ float g_h  [BT_ * D_];
__device__ __nv_bfloat16 g_qkvb[BT_ * LDQ];  // bf16: Q | K | V each 512 cols
__device__ float g_o  [BT_ * D_];   // attention output, concat-head layout
__device__ float g_x1 [BT_ * D_];
__device__ float g_h2 [BT_ * D_];
__device__ float g_ff [BT_ * DFF_];
__device__ float g_w  [4 * 262144 + 2 * 1048576];  // tf32-rounded weights

// ---------------- tf32 / bf16 helpers ----------------------------------------
__device__ __forceinline__ uint32_t f2tf32(float x) {
    uint32_t u;
    asm("cvt.rna.tf32.f32 %0, %1;" : "=r"(u) : "f"(x));
    return u;
}

// pack two floats into bf16x2: lo <- x, hi <- y
__device__ __forceinline__ uint32_t pack_bf16x2(float x, float y) {
    uint32_t u;
    asm("cvt.rn.bf16x2.f32 %0, %1, %2;" : "=r"(u) : "f"(y), "f"(x));
    return u;
}

__device__ __forceinline__ void mma_tf32(float* d, const uint32_t* a,
                                         const uint32_t* b) {
    asm volatile(
        "mma.sync.aligned.m16n8k8.row.col.f32.tf32.tf32.f32 "
        "{%0,%1,%2,%3}, {%4,%5,%6,%7}, {%8,%9}, {%0,%1,%2,%3};"
        : "+f"(d[0]), "+f"(d[1]), "+f"(d[2]), "+f"(d[3])
        : "r"(a[0]), "r"(a[1]), "r"(a[2]), "r"(a[3]),
          "r"(b[0]), "r"(b[1]));
}

__device__ __forceinline__ void mma_bf16(float* d, const uint32_t* a,
                                         uint32_t b0, uint32_t b1) {
    asm volatile(
        "mma.sync.aligned.m16n8k16.row.col.f32.bf16.bf16.f32 "
        "{%0,%1,%2,%3}, {%4,%5,%6,%7}, {%8,%9}, {%0,%1,%2,%3};"
        : "+f"(d[0]), "+f"(d[1]), "+f"(d[2]), "+f"(d[3])
        : "r"(a[0]), "r"(a[1]), "r"(a[2]), "r"(a[3]),
          "r"(b0), "r"(b1));
}

__device__ __forceinline__ void cp16(uint32_t dst_smem, const void* src) {
    asm volatile("cp.async.cg.shared.global [%0], [%1], 16;"
                 :: "r"(dst_smem), "l"(src) : "memory");
}
#define CP_COMMIT() asm volatile("cp.async.commit_group;" ::: "memory")

// ---------------- fused weight pre-rounding (rna to tf32) -------------------
__global__ __launch_bounds__(256) void round_all_kernel(
    const float* __restrict__ Wq, const float* __restrict__ Wk,
    const float* __restrict__ Wv, const float* __restrict__ Wp,
    const float* __restrict__ W1, const float* __restrict__ W2,
    float* __restrict__ dst)
{
    const int i = blockIdx.x * 256 + threadIdx.x;   // float4 index, 0..786431
    const float4* src;
    int off;
    if      (i <  65536) { src = (const float4*)Wq; off = i; }
    else if (i < 131072) { src = (const float4*)Wk; off = i - 65536; }
    else if (i < 196608) { src = (const float4*)Wv; off = i - 131072; }
    else if (i < 262144) { src = (const float4*)Wp; off = i - 196608; }
    else if (i < 524288) { src = (const float4*)W1; off = i - 262144; }
    else                 { src = (const float4*)W2; off = i - 524288; }
    float4 v = src[off];
    float4 r;
    r.x = __uint_as_float(f2tf32(v.x));
    r.y = __uint_as_float(f2tf32(v.y));
    r.z = __uint_as_float(f2tf32(v.z));
    r.w = __uint_as_float(f2tf32(v.w));
    ((float4*)dst)[i] = r;
}

// ---------------- LayerNorm: one block per row of 512 -----------------------
// Output is tf32-rounded (it is consumed only by tensor-core GEMMs).
__global__ __launch_bounds__(128) void ln_kernel(
    const float* __restrict__ x, const float* __restrict__ g,
    const float* __restrict__ b, float* __restrict__ out)
{
    const int row = blockIdx.x;
    const int tid = threadIdx.x;                 // 128 threads * float4 = 512
    float4 v = ((const float4*)(x + (size_t)row * D_))[tid];
    float s  = v.x + v.y + v.z + v.w;
    float ss = v.x * v.x + v.y * v.y + v.z * v.z + v.w * v.w;
    #pragma unroll
    for (int o = 16; o > 0; o >>= 1) {
        s  += __shfl_xor_sync(0xffffffffu, s,  o);
        ss += __shfl_xor_sync(0xffffffffu, ss, o);
    }
    __shared__ float sh_s[4], sh_ss[4];
    if ((tid & 31) == 0) { sh_s[tid >> 5] = s; sh_ss[tid >> 5] = ss; }
    __syncthreads();
    const float tot  = sh_s[0] + sh_s[1] + sh_s[2] + sh_s[3];
    const float tots = sh_ss[0] + sh_ss[1] + sh_ss[2] + sh_ss[3];
    const float mu   = tot  * (1.0f / D_);
    const float var  = tots * (1.0f / D_) - mu * mu;
    const float rstd = rsqrtf(var + 1e-5f);
    float4 gv = ((const float4*)g)[tid];
    float4 bv = ((const float4*)b)[tid];
    float4 r;
    r.x = __uint_as_float(f2tf32((v.x - mu) * rstd * gv.x + bv.x));
    r.y = __uint_as_float(f2tf32((v.y - mu) * rstd * gv.y + bv.y));
    r.z = __uint_as_float(f2tf32((v.z - mu) * rstd * gv.z + bv.z));
    r.w = __uint_as_float(f2tf32((v.w - mu) * rstd * gv.w + bv.w));
    ((float4*)(out + (size_t)row * D_))[tid] = r;
}

// ---------------- tf32 tensor-core GEMM, 128x128 tile, cp.async 3-stage -----
#define PAD_A 36
#define PAD_B 136
#define ASTAGE (128 * PAD_A)                 // 4608 floats
#define STAGE  (ASTAGE + 32 * PAD_B)         // 8960 floats
#define GEMM_SMEM (3 * STAGE * 4)            // 107520 bytes

__global__ __launch_bounds__(256, 2) void gemm_kernel(
    const float* __restrict__ A, int lda,
    const float* __restrict__ W0, const float* __restrict__ W1g,
    const float* __restrict__ W2g, int cstride, int ldb,
    const float* __restrict__ b0, const float* __restrict__ b1g,
    const float* __restrict__ b2g,
    const float* __restrict__ res,
    float* __restrict__ C, int ldc,
    int K, int relu, int qkv, int rnd,
    __nv_bfloat16* __restrict__ Qb)
{
    extern __shared__ float smg[];
    const uint32_t sbase = (uint32_t)__cvta_generic_to_shared(smg);

    const int tid  = threadIdx.x;
    const int lane = tid & 31;
    const int wid  = tid >> 5;
    const int wm   = wid & 1;        // row block of 64
    const int wn   = wid >> 1;       // col block of 32
    const int row0 = blockIdx.y * 128;
    const int col0 = blockIdx.x * 128;

    const int grp = qkv ? (col0 >> 9) : 0;
    const float* Wsel = (grp == 0) ? W0 : ((grp == 1) ? W1g : W2g);
    const float* bsel = (grp == 0) ? b0 : ((grp == 1) ? b1g : b2g);
    const int col0g = qkv ? (col0 & 511) : col0;
    const float* B0 = Wsel + (size_t)(col0g >> 6) * cstride; // cols [col0,+64)
    const float* B1 = B0 + cstride;                          // cols [+64,+128)

    const int r = lane >> 2;         // 0..7
    const int c = lane & 3;          // 0..3

    float acc[4][4][4];
    #pragma unroll
    for (int mi = 0; mi < 4; mi++)
        #pragma unroll
        for (int ni = 0; ni < 4; ni++)
            acc[mi][ni][0] = acc[mi][ni][1] = acc[mi][ni][2] = acc[mi][ni][3] = 0.f;

    const int niter = K >> 5;

    auto issue_stage = [&](int it) {
        const int k0 = it * 32;
        const uint32_t ab = sbase + (uint32_t)((it % 3) * STAGE) * 4;
        const uint32_t bb = ab + ASTAGE * 4;
        #pragma unroll
        for (int i = 0; i < 4; i++) {
            int idx = tid + i * 256;            // A: 0..1023 float4s
            int m   = idx >> 3;                 // 0..127
            int kk  = (idx & 7) * 4;            // 0..28
            cp16(ab + (uint32_t)(m * PAD_A + kk) * 4,
                 A + (size_t)(row0 + m) * lda + k0 + kk);
        }
        #pragma unroll
        for (int i = 0; i < 4; i++) {
            int idx = tid + i * 256;            // B: 0..1023 float4s
            int kk  = idx >> 5;                 // 0..31
            int n4  = (idx & 31) * 4;           // 0..124
            const float* src = (n4 < 64)
                ? (B0 + (size_t)(k0 + kk) * ldb + n4)
                : (B1 + (size_t)(k0 + kk) * ldb + (n4 - 64));
            cp16(bb + (uint32_t)(kk * PAD_B + n4) * 4, src);
        }
        CP_COMMIT();
    };

    issue_stage(0);
    issue_stage(1);

    for (int it = 0; it < niter; it++) {
        if (it < niter - 1)
            asm volatile("cp.async.wait_group 1;" ::: "memory");
        else
            asm volatile("cp.async.wait_group 0;" ::: "memory");
        __syncthreads();
        if (it + 2 < niter) issue_stage(it + 2);

        const float* Ac = smg + (it % 3) * STAGE;
        const float* Bc = Ac + ASTAGE;

        #pragma unroll
        for (int ks = 0; ks < 32; ks += 8) {
            uint32_t af[4][4], bf[4][2];
            #pragma unroll
            for (int mi = 0; mi < 4; mi++) {
                int m = wm * 64 + mi * 16 + r;
                af[mi][0] = __float_as_uint(Ac[m * PAD_A + ks + c]);
                af[mi][1] = __float_as_uint(Ac[(m + 8) * PAD_A + ks + c]);
                af[mi][2] = __float_as_uint(Ac[m * PAD_A + ks + c + 4]);
                af[mi][3] = __float_as_uint(Ac[(m + 8) * PAD_A + ks + c + 4]);
            }
            #pragma unroll
            for (int ni = 0; ni < 4; ni++) {
                int n = wn * 32 + ni * 8 + r;
                bf[ni][0] = __float_as_uint(Bc[(ks + c) * PAD_B + n]);
                bf[ni][1] = __float_as_uint(Bc[(ks + c + 4) * PAD_B + n]);
            }
            #pragma unroll
            for (int mi = 0; mi < 4; mi++)
                #pragma unroll
                for (int ni = 0; ni < 4; ni++)
                    mma_tf32(acc[mi][ni], af[mi], bf[ni]);
        }
    }

    // --- epilogue: bias (+res) (relu) (rnd); qkv mode -> bf16 buffer ---
    #pragma unroll
    for (int mi = 0; mi < 4; mi++) {
        const int row_a = row0 + wm * 64 + mi * 16 + r;
        const size_t ro0 = (size_t)row_a * ldc;
        const size_t ro1 = (size_t)(row_a + 8) * ldc;
        #pragma unroll
        for (int ni = 0; ni < 4; ni++) {
            const int col_a = col0 + wn * 32 + ni * 8 + 2 * c;
            const int col_b = qkv ? (col_a & 511) : col_a;
            float2 bb = *(const float2*)(bsel + col_b);
            float v0 = acc[mi][ni][0] + bb.x;
            float v1 = acc[mi][ni][1] + bb.y;
            float v2 = acc[mi][ni][2] + bb.x;
            float v3 = acc[mi][ni][3] + bb.y;
            if (res) {
                float2 r0v = *(const float2*)(res + ro0 + col_a);
                float2 r1v = *(const float2*)(res + ro1 + col_a);
                v0 += r0v.x; v1 += r0v.y; v2 += r1v.x; v3 += r1v.y;
            }
            if (relu) {
                v0 = fmaxf(v0, 0.f); v1 = fmaxf(v1, 0.f);
                v2 = fmaxf(v2, 0.f); v3 = fmaxf(v3, 0.f);
            }
            if (qkv) {
                // Q/K/V are consumed only as bf16 by the attention kernel
                *(uint32_t*)(Qb + (size_t)row_a * LDQ + col_a) =
                    pack_bf16x2(v0, v1);
                *(uint32_t*)(Qb + (size_t)(row_a + 8) * LDQ + col_a) =
                    pack_bf16x2(v2, v3);
            } else {
                if (rnd) {
                    v0 = __uint_as_float(f2tf32(v0));
                    v1 = __uint_as_float(f2tf32(v1));
                    v2 = __uint_as_float(f2tf32(v2));
                    v3 = __uint_as_float(f2tf32(v3));
                }
                *(float2*)(C + ro0 + col_a) = make_float2(v0, v1);
                *(float2*)(C + ro1 + col_a) = make_float2(v2, v3);
            }
        }
    }
}

// ---------------- bf16 tensor-core causal flash attention -------------------
// All mma in bf16 m16n8k16. Q fragments via 4x ldmatrix.x4 (once per block,
// held in registers). K B-fragments via ldmatrix.x4 (non-trans), V via
// ldmatrix.x4.trans. P packed straight from softmax registers. All smem rows
// are 144B (72 bf16): ldmatrix phases conflict-free (banks 4r mod 32 distinct).
#define KROWB 144
#define KVBYTES (2 * 64 * KROWB)                 // K tile + V tile = 18432
#define VOFF    (64 * KROWB)                     // V region byte offset
#define ATTN_SMEM (2 * KVBYTES)                  // 36864 bytes

__global__ __launch_bounds__(256, 2) void attn_kernel(
    const __nv_bfloat16* __restrict__ QKV, float* __restrict__ O)
{
    extern __shared__ float sm[];
    char* smb = (char*)sm;
    const uint32_t sbase = (uint32_t)__cvta_generic_to_shared(sm);

    const int tid  = threadIdx.x;
    const int lane = tid & 31;
    const int w    = tid >> 5;       // warp id: query rows w*16..w*16+15
    const int r    = lane >> 2;      // 0..7
    const int c    = lane & 3;       // 0..3
    const int qt   = (gridDim.x - 1) - blockIdx.x;   // big tiles first
    const int bh   = blockIdx.y;
    const int b    = bh >> 3, h = bh & 7;
    const int q0   = qt * 128;
    const size_t base  = ((size_t)b * T_) * LDQ + h * DK_;
    const size_t obase = ((size_t)b * T_) * D_  + h * DK_;
    const __nv_bfloat16* Qg = QKV + base;
    const __nv_bfloat16* Kg = QKV + base + 512;
    const __nv_bfloat16* Vg = QKV + base + 1024;

    auto issue_kv = [&](int kt) {
        const int j0 = kt * 64;
        const uint32_t kb = sbase + (uint32_t)(kt & 1) * KVBYTES;
        const uint32_t vb = kb + VOFF;
        #pragma unroll
        for (int i = 0; i < 2; i++) {
            int idx = tid + i * 256;           // 0..511 16B chunks each
            int s   = idx >> 3;                // 0..63
            int ch  = idx & 7;
            cp16(kb + (uint32_t)(s * KROWB + ch * 16),
                 Kg + (size_t)(j0 + s) * LDQ + ch * 8);
            cp16(vb + (uint32_t)(s * KROWB + ch * 16),
                 Vg + (size_t)(j0 + s) * LDQ + ch * 8);
        }
        CP_COMMIT();
    };

    // ---- stage Q tile (bf16, 144B rows spans exactly stage 0) ----
    #pragma unroll
    for (int i = 0; i < 4; i++) {
        int idx = tid + i * 256;             // 0..1023 16B chunks
        int row = idx >> 3;                  // 0..127
        int ch  = idx & 7;
        uint4 qv = *(const uint4*)(Qg + (size_t)(q0 + row) * LDQ + ch * 8);
        *(uint4*)(smb + row * KROWB + ch * 16) = qv;
    }
    __syncthreads();
    // Q A-fragments: 4 k16-blocks via ldmatrix.x4 (non-trans)
    uint32_t qf[4][4];
    {
        const int qrow = w * 16 + (lane & 7) + ((lane >> 3) & 1) * 8;
        const uint32_t qoff = (uint32_t)(qrow * KROWB + (lane >> 4) * 16);
        #pragma unroll
        for (int kb4 = 0; kb4 < 4; kb4++) {
            const uint32_t addr = sbase + qoff + kb4 * 32;
            asm volatile(
                "ldmatrix.sync.aligned.m8n8.x4.shared.b16 {%0,%1,%2,%3}, [%4];"
                : "=r"(qf[kb4][0]), "=r"(qf[kb4][1]),
                  "=r"(qf[kb4][2]), "=r"(qf[kb4][3]) : "r"(addr));
        }
    }
    __syncthreads();                      // all warps done reading Q
    issue_kv(0);

    // per-thread ldmatrix address patterns (within a tile region)
    const int g8 = lane >> 3;             // matrix group 0..3
    const uint32_t kpat = (uint32_t)(((lane & 7) + ((lane >> 3) & 1) * 8) * KROWB
                                     + (lane >> 4) * 16);
    const uint32_t vpat = (uint32_t)(((g8 & 1) * 8 + (lane & 7)) * KROWB
                                     + (g8 >> 1) * 16);

    // online-softmax state (m in raw score units)
    float m_[2] = {-1e30f, -1e30f};
    float l_[2] = {0.0f, 0.0f};
    float oacc[8][4];
    #pragma unroll
    for (int ni = 0; ni < 8; ni++)
        oacc[ni][0] = oacc[ni][1] = oacc[ni][2] = oacc[ni][3] = 0.0f;

    const int ntile = (q0 >> 6) + 2;          // causal: key tiles 0..(q0+127)/64

    for (int kt = 0; kt < ntile; kt++) {
        const int j0 = kt * 64;
        const uint32_t kaddr0 = sbase + (uint32_t)(kt & 1) * KVBYTES + kpat;
        const uint32_t vaddr0 = sbase + (uint32_t)(kt & 1) * KVBYTES + VOFF + vpat;

        asm volatile("cp.async.wait_group 0;" ::: "memory");
        __syncthreads();                      // tile kt visible to all
        if (kt + 1 < ntile) issue_kv(kt + 1); // prefetch (buffer safe: its
                                              // readers finished pre-sync)

        // ---- S = Q K^T : bf16 m16n8k16, K B-frags via ldmatrix.x4 ----
        float sacc[8][4];
        #pragma unroll
        for (int ni = 0; ni < 8; ni++)
            sacc[ni][0] = sacc[ni][1] = sacc[ni][2] = sacc[ni][3] = 0.0f;
        #pragma unroll
        for (int kb4 = 0; kb4 < 4; kb4++) {
            #pragma unroll
            for (int ni2 = 0; ni2 < 4; ni2++) {
                uint32_t k0r, k1r, k2r, k3r;
                const uint32_t addr = kaddr0
                    + (uint32_t)(ni2 * 16 * KROWB + kb4 * 32);
                asm volatile(
                    "ldmatrix.sync.aligned.m8n8.x4.shared.b16 "
                    "{%0,%1,%2,%3}, [%4];"
                    : "=r"(k0r), "=r"(k1r), "=r"(k2r), "=r"(k3r) : "r"(addr));
                mma_bf16(sacc[2 * ni2],     qf[kb4], k0r, k2r);
                mma_bf16(sacc[2 * ni2 + 1], qf[kb4], k1r, k3r);
            }
        }

        // ---- causal mask (raw units) + online softmax (base-2 domain) ----
        const bool full = (j0 + 64 <= q0 + w * 16);   // warp-uniform
        if (!full) {
            #pragma unroll
            for (int ri = 0; ri < 2; ri++) {
                const int tg = q0 + w * 16 + r + ri * 8;
                #pragma unroll
                for (int ni = 0; ni < 8; ni++)
                    #pragma unroll
                    for (int jj = 0; jj < 2; jj++) {
                        int sg = j0 + ni * 8 + 2 * c + jj;
                        if (sg > tg) sacc[ni][ri * 2 + jj] = -1e30f;
                    }
            }
        }
        #pragma unroll
        for (int ri = 0; ri < 2; ri++) {
            float rm = -1e30f;
            #pragma unroll
            for (int ni = 0; ni < 8; ni++) {
                rm = fmaxf(rm, sacc[ni][ri * 2 + 0]);
                rm = fmaxf(rm, sacc[ni][ri * 2 + 1]);
            }
            rm = fmaxf(rm, __shfl_xor_sync(0xffffffffu, rm, 1));
            rm = fmaxf(rm, __shfl_xor_sync(0xffffffffu, rm, 2));
            const float mn  = fmaxf(m_[ri], rm);
            const float mnC = mn * SCL2;
            // skip oacc rescale if no lane in warp raised its max this tile
            const unsigned upd = __ballot_sync(0xffffffffu, mn != m_[ri]);
            if (upd) {
                const float alpha = exp2f((m_[ri] - mn) * SCL2);
                #pragma unroll
                for (int ni = 0; ni < 8; ni++) {
                    oacc[ni][ri * 2 + 0] *= alpha;
                    oacc[ni][ri * 2 + 1] *= alpha;
                }
                l_[ri] *= alpha;
                m_[ri] = mn;
            }
            float ps = 0.0f;
            #pragma unroll
            for (int ni = 0; ni < 8; ni++) {
                #pragma unroll
                for (int jj = 0; jj < 2; jj++) {
                    float p = exp2f(fmaf(sacc[ni][ri * 2 + jj], SCL2, -mnC));
                    ps += p;
                    sacc[ni][ri * 2 + jj] = p;
                }
            }
            ps += __shfl_xor_sync(0xffffffffu, ps, 1);
            ps += __shfl_xor_sync(0xffffffffu, ps, 2);
            l_[ri] += ps;
        }

        // ---- O += P V in bf16: P packed from registers, V via ldmatrix.trans
        #pragma unroll
        for (int k4 = 0; k4 < 4; k4++) {
            uint32_t a[4];
            a[0] = pack_bf16x2(sacc[2 * k4][0],     sacc[2 * k4][1]);
            a[1] = pack_bf16x2(sacc[2 * k4][2],     sacc[2 * k4][3]);
            a[2] = pack_bf16x2(sacc[2 * k4 + 1][0], sacc[2 * k4 + 1][1]);
            a[3] = pack_bf16x2(sacc[2 * k4 + 1][2], sacc[2 * k4 + 1][3]);
            #pragma unroll
            for (int dp = 0; dp < 4; dp++) {
                uint32_t m0, m1, m2, m3;
                const uint32_t addr = vaddr0
                    + (uint32_t)(k4 * 16 * KROWB + dp * 32);
                asm volatile(
                    "ldmatrix.sync.aligned.m8n8.x4.trans.shared.b16 "
                    "{%0,%1,%2,%3}, [%4];"
                    : "=r"(m0), "=r"(m1), "=r"(m2), "=r"(m3) : "r"(addr));
                mma_bf16(oacc[2 * dp],     a, m0, m1);
                mma_bf16(oacc[2 * dp + 1], a, m2, m3);
            }
        }
    }

    // ---- normalize, tf32-round (consumed only by proj GEMM), write out ----
    const float inv0 = 1.0f / l_[0];
    const float inv1 = 1.0f / l_[1];
    const int row0g = q0 + w * 16 + r;
    #pragma unroll
    for (int ni = 0; ni < 8; ni++) {
        const int col = ni * 8 + 2 * c;
        float2 a0, a1;
        a0.x = __uint_as_float(f2tf32(oacc[ni][0] * inv0));
        a0.y = __uint_as_float(f2tf32(oacc[ni][1] * inv0));
        a1.x = __uint_as_float(f2tf32(oacc[ni][2] * inv1));
        a1.y = __uint_as_float(f2tf32(oacc[ni][3] * inv1));
        *(float2*)(O + obase + (size_t)row0g * D_ + col) = a0;
        *(float2*)(O + obase + (size_t)(row0g + 8) * D_ + col) = a1;
    }
}

// ---------------- launcher ---------------------------------------------------
extern "C" void kernel_launch(void* const* d_in, const int* in_sizes, int n_in,
                              void* d_out, int out_size)
{
    const float* x   = (const float*)d_in[0];
    const float* Wq  = (const float*)d_in[1];
    const float* bq  = (const float*)d_in[2];
    const float* Wk  = (const float*)d_in[3];
    const float* bk  = (const float*)d_in[4];
    const float* Wv  = (const float*)d_in[5];
    const float* bv  = (const float*)d_in[6];
    const float* Wp  = (const float*)d_in[7];
    const float* bp  = (const float*)d_in[8];
    const float* W1  = (const float*)d_in[9];
    const float* b1  = (const float*)d_in[10];
    const float* W2  = (const float*)d_in[11];
    const float* b2  = (const float*)d_in[12];
    const float* g1  = (const float*)d_in[13];
    const float* be1 = (const float*)d_in[14];
    const float* g2  = (const float*)d_in[15];
    const float* be2 = (const float*)d_in[16];
    float* out = (float*)d_out;

    float *h, *o, *x1, *h2, *ff, *wr;
    __nv_bfloat16* qkvb;
    cudaGetSymbolAddress((void**)&h,    g_h);
    cudaGetSymbolAddress((void**)&qkvb, g_qkvb);
    cudaGetSymbolAddress((void**)&o,    g_o);
    cudaGetSymbolAddress((void**)&x1,   g_x1);
    cudaGetSymbolAddress((void**)&h2,   g_h2);
    cudaGetSymbolAddress((void**)&ff,   g_ff);
    cudaGetSymbolAddress((void**)&wr,   g_w);

    float* wq = wr;                    // 262144 each
    float* wk = wr + 262144;
    float* wv = wr + 524288;
    float* wp = wr + 786432;
    float* w1 = wr + 1048576;          // 1048576
    float* w2 = wr + 2097152;          // 1048576

    cudaFuncSetAttribute(attn_kernel,
                         cudaFuncAttributeMaxDynamicSharedMemorySize, ATTN_SMEM);
    cudaFuncSetAttribute(gemm_kernel,
                         cudaFuncAttributeMaxDynamicSharedMemorySize, GEMM_SMEM);

    // pre-round all weights to tf32 (rna) in one launch
    round_all_kernel<<<3072, 256>>>(Wq, Wk, Wv, Wp, W1, W2, wr);

    // LN1 (tf32-rounded output)
    ln_kernel<<<BT_, 128>>>(x, g1, be1, h);

    // fused QKV projection -> bf16 buffer (head-stacked weights)
    gemm_kernel<<<dim3(LDQ / 128, BT_ / 128), 256, GEMM_SMEM>>>(
        h, D_, wq, wk, wv, D_ * DK_, DK_, bq, bk, bv,
        nullptr, nullptr, LDQ, D_, 0, 1, 0, qkvb);

    // causal attention (all-bf16 mma, cp.async double-buffered)
    attn_kernel<<<dim3(T_ / 128, B_ * H_), 256, ATTN_SMEM>>>(qkvb, o);

    // output projection + residual (row-major weights: cstride = 64, ldb = N)
    dim3 g512(D_ / 128, BT_ / 128);
    gemm_kernel<<<g512, 256, GEMM_SMEM>>>(o, D_, wp, wp, wp, 64, D_,
                                          bp, bp, bp, x, x1, D_, D_, 0, 0, 0,
                                          nullptr);

    // LN2 (tf32-rounded output)
    ln_kernel<<<BT_, 128>>>(x1, g2, be2, h2);

    // FFN
    gemm_kernel<<<dim3(DFF_ / 128, BT_ / 128), 256, GEMM_SMEM>>>(
        h2, D_, w1, w1, w1, 64, DFF_, b1, b1, b1,
        nullptr, ff, DFF_, D_, 1, 0, 1, nullptr);
    gemm_kernel<<<g512, 256, GEMM_SMEM>>>(ff, DFF_, w2, w2, w2, 64, D_,
                                          b2, b2, b2, x1, out, D_, DFF_, 0, 0, 0,
                                          nullptr);
}

// round 14
// speedup vs baseline: 2.2691x; 1.4617x over previous
#include <cuda_runtime.h>
#include <cuda_fp16.h>
#include <cstdint>

#define B_   4
#define T_   2048
#define D_   512
#define H_   8
#define DK_  64
#define BT_  (B_ * T_)
#define DFF_ 2048
#define LDQ  1536      // fused QKV col count (fp16 buffer)

// 0.125 * log2(e): folds the 1/sqrt(64) scale and base-e->base-2 conversion
#define SCL2 0.18033688011111772f

// ---------------- scratch (static device globals; no allocations) ----------
__device__ __half g_h  [BT_ * D_];          // LN1 out (fp16)
__device__ __half g_qkvb[BT_ * LDQ];        // fp16: Q | K | V each 512 cols
__device__ __half g_o  [BT_ * D_];          // attention out (fp16)
__device__ float  g_x1 [BT_ * D_];          // residual stream (fp32)
__device__ __half g_h2 [BT_ * D_];          // LN2 out (fp16)
__device__ __half g_ff [BT_ * DFF_];        // FFN1 out (fp16)
__device__ __half g_wh [4 * 1048576 + 2 * 4194304 / 2]; // fp16 weights (3.1M)

// ---------------- fp16 helpers ----------------------------------------------
// pack two floats into f16x2: lo <- x, hi <- y
__device__ __forceinline__ uint32_t pack_f16x2(float x, float y) {
    uint32_t u;
    asm("cvt.rn.f16x2.f32 %0, %1, %2;" : "=r"(u) : "f"(y), "f"(x));
    return u;
}

__device__ __forceinline__ void mma_f16(float* d, const uint32_t* a,
                                        uint32_t b0, uint32_t b1) {
    asm volatile(
        "mma.sync.aligned.m16n8k16.row.col.f32.f16.f16.f32 "
        "{%0,%1,%2,%3}, {%4,%5,%6,%7}, {%8,%9}, {%0,%1,%2,%3};"
        : "+f"(d[0]), "+f"(d[1]), "+f"(d[2]), "+f"(d[3])
        : "r"(a[0]), "r"(a[1]), "r"(a[2]), "r"(a[3]),
          "r"(b0), "r"(b1));
}

__device__ __forceinline__ void cp16(uint32_t dst_smem, const void* src) {
    asm volatile("cp.async.cg.shared.global [%0], [%1], 16;"
                 :: "r"(dst_smem), "l"(src) : "memory");
}
#define CP_COMMIT() asm volatile("cp.async.commit_group;" ::: "memory")

#define LDMX4(r0, r1, r2, r3, addr) \
    asm volatile("ldmatrix.sync.aligned.m8n8.x4.shared.b16 {%0,%1,%2,%3}, [%4];" \
        : "=r"(r0), "=r"(r1), "=r"(r2), "=r"(r3) : "r"(addr))
#define LDMX4T(r0, r1, r2, r3, addr) \
    asm volatile("ldmatrix.sync.aligned.m8n8.x4.trans.shared.b16 {%0,%1,%2,%3}, [%4];" \
        : "=r"(r0), "=r"(r1), "=r"(r2), "=r"(r3) : "r"(addr))

// ---------------- fused weight conversion to fp16 ---------------------------
__global__ __launch_bounds__(256) void round_all_kernel(
    const float* __restrict__ Wq, const float* __restrict__ Wk,
    const float* __restrict__ Wv, const float* __restrict__ Wp,
    const float* __restrict__ W1, const float* __restrict__ W2,
    __half* __restrict__ dst)
{
    const int i = blockIdx.x * 256 + threadIdx.x;   // float4 index, 0..786431
    const float4* src;
    int off;
    if      (i <  65536) { src = (const float4*)Wq; off = i; }
    else if (i < 131072) { src = (const float4*)Wk; off = i - 65536; }
    else if (i < 196608) { src = (const float4*)Wv; off = i - 131072; }
    else if (i < 262144) { src = (const float4*)Wp; off = i - 196608; }
    else if (i < 524288) { src = (const float4*)W1; off = i - 262144; }
    else                 { src = (const float4*)W2; off = i - 524288; }
    float4 v = src[off];
    uint2 p;
    p.x = pack_f16x2(v.x, v.y);
    p.y = pack_f16x2(v.z, v.w);
    ((uint2*)dst)[i] = p;
}

// ---------------- LayerNorm: one block per row of 512, fp16 out -------------
__global__ __launch_bounds__(128) void ln_kernel(
    const float* __restrict__ x, const float* __restrict__ g,
    const float* __restrict__ b, __half* __restrict__ out)
{
    const int row = blockIdx.x;
    const int tid = threadIdx.x;                 // 128 threads * float4 = 512
    float4 v = ((const float4*)(x + (size_t)row * D_))[tid];
    float s  = v.x + v.y + v.z + v.w;
    float ss = v.x * v.x + v.y * v.y + v.z * v.z + v.w * v.w;
    #pragma unroll
    for (int o = 16; o > 0; o >>= 1) {
        s  += __shfl_xor_sync(0xffffffffu, s,  o);
        ss += __shfl_xor_sync(0xffffffffu, ss, o);
    }
    __shared__ float sh_s[4], sh_ss[4];
    if ((tid & 31) == 0) { sh_s[tid >> 5] = s; sh_ss[tid >> 5] = ss; }
    __syncthreads();
    const float tot  = sh_s[0] + sh_s[1] + sh_s[2] + sh_s[3];
    const float tots = sh_ss[0] + sh_ss[1] + sh_ss[2] + sh_ss[3];
    const float mu   = tot  * (1.0f / D_);
    const float var  = tots * (1.0f / D_) - mu * mu;
    const float rstd = rsqrtf(var + 1e-5f);
    float4 gv = ((const float4*)g)[tid];
    float4 bv = ((const float4*)b)[tid];
    uint2 p;
    p.x = pack_f16x2((v.x - mu) * rstd * gv.x + bv.x,
                     (v.y - mu) * rstd * gv.y + bv.y);
    p.y = pack_f16x2((v.z - mu) * rstd * gv.z + bv.z,
                     (v.w - mu) * rstd * gv.w + bv.w);
    ((uint2*)(out + (size_t)row * D_))[tid] = p;
}

// ---------------- fp16 tensor-core GEMM, 128x128 tile, cp.async 3-stage -----
// C[row, col] = sum_k A[row, k] * B(k, col) (+bias[col]) (+res[row,col])
//               (relu). Output: fp32 to C, or fp16 to Hout (stride ldc).
// mma m16n8k16, ldmatrix operand loads. BK = 32.
// A tile 128x32 fp16, rows padded to 80B; B tile 32x128 fp16, rows 272B.
#define AROWB 80
#define BROWB 272
#define ASTAGEB (128 * AROWB)               // 10240 bytes
#define BSTAGEB (32 * BROWB)                // 8704 bytes
#define STAGEB  (ASTAGEB + BSTAGEB)         // 18944 bytes
#define GEMM_SMEM (3 * STAGEB)              // 56832 bytes

__global__ __launch_bounds__(256, 2) void gemm_kernel(
    const __half* __restrict__ A, int lda,
    const __half* __restrict__ W0, const __half* __restrict__ W1g,
    const __half* __restrict__ W2g, int cstride, int ldb,
    const float* __restrict__ b0, const float* __restrict__ b1g,
    const float* __restrict__ b2g,
    const float* __restrict__ res,
    float* __restrict__ C, int ldc,
    int K, int relu, int qkv,
    __half* __restrict__ Hout)
{
    extern __shared__ float smg[];
    const uint32_t sbase = (uint32_t)__cvta_generic_to_shared(smg);

    const int tid  = threadIdx.x;
    const int lane = tid & 31;
    const int wid  = tid >> 5;
    const int wm   = wid & 1;        // row block of 64
    const int wn   = wid >> 1;       // col block of 32
    const int row0 = blockIdx.y * 128;
    const int col0 = blockIdx.x * 128;

    const int grp = qkv ? (col0 >> 9) : 0;
    const __half* Wsel = (grp == 0) ? W0 : ((grp == 1) ? W1g : W2g);
    const float*  bsel = (grp == 0) ? b0 : ((grp == 1) ? b1g : b2g);
    const int col0g = qkv ? (col0 & 511) : col0;
    const __half* B0 = Wsel + (size_t)(col0g >> 6) * cstride; // cols [col0,+64)
    const __half* B1 = B0 + cstride;                          // cols [+64,+128)

    const int r = lane >> 2;         // 0..7
    const int c = lane & 3;          // 0..3

    float acc[4][4][4];
    #pragma unroll
    for (int mi = 0; mi < 4; mi++)
        #pragma unroll
        for (int ni = 0; ni < 4; ni++)
            acc[mi][ni][0] = acc[mi][ni][1] = acc[mi][ni][2] = acc[mi][ni][3] = 0.f;

    const int niter = K >> 5;

    auto issue_stage = [&](int it) {
        const int k0 = it * 32;
        const uint32_t ab = sbase + (uint32_t)((it % 3) * STAGEB);
        const uint32_t bb = ab + ASTAGEB;
        #pragma unroll
        for (int i = 0; i < 2; i++) {
            int idx = tid + i * 256;            // A: 0..511 16B chunks
            int m   = idx >> 2;                 // 0..127
            int ch  = idx & 3;                  // 8 fp16 per chunk
            cp16(ab + (uint32_t)(m * AROWB + ch * 16),
                 A + (size_t)(row0 + m) * lda + k0 + ch * 8);
        }
        #pragma unroll
        for (int i = 0; i < 2; i++) {
            int idx = tid + i * 256;            // B: 0..511 16B chunks
            int kk  = idx >> 4;                 // 0..31
            int ch  = idx & 15;                 // col chunk
            const __half* src = (ch < 8)
                ? (B0 + (size_t)(k0 + kk) * ldb + ch * 8)
                : (B1 + (size_t)(k0 + kk) * ldb + (ch - 8) * 8);
            cp16(bb + (uint32_t)(kk * BROWB + ch * 16), src);
        }
        CP_COMMIT();
    };

    issue_stage(0);
    issue_stage(1);

    // ldmatrix per-thread offsets
    const int g8 = lane >> 3;
    const uint32_t apat = (uint32_t)(((lane & 7) + ((lane >> 3) & 1) * 8) * AROWB
                                     + (lane >> 4) * 16);
    const uint32_t bpat = (uint32_t)(((g8 & 1) * 8 + (lane & 7)) * BROWB
                                     + (g8 >> 1) * 16);

    for (int it = 0; it < niter; it++) {
        if (it < niter - 1)
            asm volatile("cp.async.wait_group 1;" ::: "memory");
        else
            asm volatile("cp.async.wait_group 0;" ::: "memory");
        __syncthreads();
        if (it + 2 < niter) issue_stage(it + 2);

        const uint32_t acb = sbase + (uint32_t)((it % 3) * STAGEB);
        const uint32_t bcb = acb + ASTAGEB;

        #pragma unroll
        for (int ks = 0; ks < 2; ks++) {            // two k16 blocks
            uint32_t af[4][4];
            #pragma unroll
            for (int mi = 0; mi < 4; mi++) {
                const uint32_t addr = acb + apat
                    + (uint32_t)((wm * 64 + mi * 16) * AROWB + ks * 32);
                LDMX4(af[mi][0], af[mi][1], af[mi][2], af[mi][3], addr);
            }
            #pragma unroll
            for (int ni2 = 0; ni2 < 2; ni2++) {     // two n16 blocks
                uint32_t m0, m1, m2, m3;
                const uint32_t addr = bcb + bpat
                    + (uint32_t)(ks * 16 * BROWB + wn * 64 + ni2 * 32);
                LDMX4T(m0, m1, m2, m3, addr);
                #pragma unroll
                for (int mi = 0; mi < 4; mi++) {
                    mma_f16(acc[mi][ni2 * 2 + 0], af[mi], m0, m1);
                    mma_f16(acc[mi][ni2 * 2 + 1], af[mi], m2, m3);
                }
            }
        }
    }

    // --- epilogue: bias (+res) (relu); fp16 (Hout) or fp32 (C) stores ---
    #pragma unroll
    for (int mi = 0; mi < 4; mi++) {
        const int row_a = row0 + wm * 64 + mi * 16 + r;
        const size_t ro0 = (size_t)row_a * ldc;
        const size_t ro1 = (size_t)(row_a + 8) * ldc;
        #pragma unroll
        for (int ni = 0; ni < 4; ni++) {
            const int col_a = col0 + wn * 32 + ni * 8 + 2 * c;
            const int col_b = qkv ? (col_a & 511) : col_a;
            float2 bb = *(const float2*)(bsel + col_b);
            float v0 = acc[mi][ni][0] + bb.x;
            float v1 = acc[mi][ni][1] + bb.y;
            float v2 = acc[mi][ni][2] + bb.x;
            float v3 = acc[mi][ni][3] + bb.y;
            if (res) {
                float2 r0v = *(const float2*)(res + ro0 + col_a);
                float2 r1v = *(const float2*)(res + ro1 + col_a);
                v0 += r0v.x; v1 += r0v.y; v2 += r1v.x; v3 += r1v.y;
            }
            if (relu) {
                v0 = fmaxf(v0, 0.f); v1 = fmaxf(v1, 0.f);
                v2 = fmaxf(v2, 0.f); v3 = fmaxf(v3, 0.f);
            }
            if (Hout) {
                *(uint32_t*)(Hout + ro0 + col_a) = pack_f16x2(v0, v1);
                *(uint32_t*)(Hout + ro1 + col_a) = pack_f16x2(v2, v3);
            } else {
                *(float2*)(C + ro0 + col_a) = make_float2(v0, v1);
                *(float2*)(C + ro1 + col_a) = make_float2(v2, v3);
            }
        }
    }
}

// ---------------- fp16 tensor-core causal flash attention -------------------
// All mma in fp16 m16n8k16 (fp32 accum). Q frags via ldmatrix.x4 (held in
// regs), K via ldmatrix.x4, V via ldmatrix.x4.trans, P packed from softmax
// registers. 144B smem rows: all ldmatrix phases conflict-free.
#define KROWB 144
#define KVBYTES (2 * 64 * KROWB)                 // K tile + V tile = 18432
#define VOFF    (64 * KROWB)                     // V region byte offset
#define ATTN_SMEM (2 * KVBYTES)                  // 36864 bytes

__global__ __launch_bounds__(256, 2) void attn_kernel(
    const __half* __restrict__ QKV, __half* __restrict__ O)
{
    extern __shared__ float sm[];
    char* smb = (char*)sm;
    const uint32_t sbase = (uint32_t)__cvta_generic_to_shared(sm);

    const int tid  = threadIdx.x;
    const int lane = tid & 31;
    const int w    = tid >> 5;       // warp id: query rows w*16..w*16+15
    const int r    = lane >> 2;      // 0..7
    const int c    = lane & 3;       // 0..3
    const int qt   = (gridDim.x - 1) - blockIdx.x;   // big tiles first
    const int bh   = blockIdx.y;
    const int b    = bh >> 3, h = bh & 7;
    const int q0   = qt * 128;
    const size_t base  = ((size_t)b * T_) * LDQ + h * DK_;
    const size_t obase = ((size_t)b * T_) * D_  + h * DK_;
    const __half* Qg = QKV + base;
    const __half* Kg = QKV + base + 512;
    const __half* Vg = QKV + base + 1024;

    auto issue_kv = [&](int kt) {
        const int j0 = kt * 64;
        const uint32_t kb = sbase + (uint32_t)(kt & 1) * KVBYTES;
        const uint32_t vb = kb + VOFF;
        #pragma unroll
        for (int i = 0; i < 2; i++) {
            int idx = tid + i * 256;           // 0..511 16B chunks each
            int s   = idx >> 3;                // 0..63
            int ch  = idx & 7;
            cp16(kb + (uint32_t)(s * KROWB + ch * 16),
                 Kg + (size_t)(j0 + s) * LDQ + ch * 8);
            cp16(vb + (uint32_t)(s * KROWB + ch * 16),
                 Vg + (size_t)(j0 + s) * LDQ + ch * 8);
        }
        CP_COMMIT();
    };

    // ---- stage Q tile (fp16, 144B rows spans exactly stage 0) ----
    #pragma unroll
    for (int i = 0; i < 4; i++) {
        int idx = tid + i * 256;             // 0..1023 16B chunks
        int row = idx >> 3;                  // 0..127
        int ch  = idx & 7;
        uint4 qv = *(const uint4*)(Qg + (size_t)(q0 + row) * LDQ + ch * 8);
        *(uint4*)(smb + row * KROWB + ch * 16) = qv;
    }
    __syncthreads();
    // Q A-fragments: 4 k16-blocks via ldmatrix.x4 (non-trans)
    uint32_t qf[4][4];
    {
        const int qrow = w * 16 + (lane & 7) + ((lane >> 3) & 1) * 8;
        const uint32_t qoff = (uint32_t)(qrow * KROWB + (lane >> 4) * 16);
        #pragma unroll
        for (int kb4 = 0; kb4 < 4; kb4++) {
            const uint32_t addr = sbase + qoff + kb4 * 32;
            LDMX4(qf[kb4][0], qf[kb4][1], qf[kb4][2], qf[kb4][3], addr);
        }
    }
    __syncthreads();                      // all warps done reading Q
    issue_kv(0);

    // per-thread ldmatrix address patterns (within a tile region)
    const int g8 = lane >> 3;             // matrix group 0..3
    const uint32_t kpat = (uint32_t)(((lane & 7) + ((lane >> 3) & 1) * 8) * KROWB
                                     + (lane >> 4) * 16);
    const uint32_t vpat = (uint32_t)(((g8 & 1) * 8 + (lane & 7)) * KROWB
                                     + (g8 >> 1) * 16);

    // online-softmax state (m in raw score units)
    float m_[2] = {-1e30f, -1e30f};
    float l_[2] = {0.0f, 0.0f};
    float oacc[8][4];
    #pragma unroll
    for (int ni = 0; ni < 8; ni++)
        oacc[ni][0] = oacc[ni][1] = oacc[ni][2] = oacc[ni][3] = 0.0f;

    const int ntile = (q0 >> 6) + 2;          // causal: key tiles 0..(q0+127)/64

    for (int kt = 0; kt < ntile; kt++) {
        const int j0 = kt * 64;
        const uint32_t kaddr0 = sbase + (uint32_t)(kt & 1) * KVBYTES + kpat;
        const uint32_t vaddr0 = sbase + (uint32_t)(kt & 1) * KVBYTES + VOFF + vpat;

        asm volatile("cp.async.wait_group 0;" ::: "memory");
        __syncthreads();                      // tile kt visible to all
        if (kt + 1 < ntile) issue_kv(kt + 1); // prefetch (buffer safe: its
                                              // readers finished pre-sync)

        // ---- S = Q K^T : fp16 m16n8k16, K B-frags via ldmatrix.x4 ----
        float sacc[8][4];
        #pragma unroll
        for (int ni = 0; ni < 8; ni++)
            sacc[ni][0] = sacc[ni][1] = sacc[ni][2] = sacc[ni][3] = 0.0f;
        #pragma unroll
        for (int kb4 = 0; kb4 < 4; kb4++) {
            #pragma unroll
            for (int ni2 = 0; ni2 < 4; ni2++) {
                uint32_t k0r, k1r, k2r, k3r;
                const uint32_t addr = kaddr0
                    + (uint32_t)(ni2 * 16 * KROWB + kb4 * 32);
                LDMX4(k0r, k1r, k2r, k3r, addr);
                mma_f16(sacc[2 * ni2],     qf[kb4], k0r, k2r);
                mma_f16(sacc[2 * ni2 + 1], qf[kb4], k1r, k3r);
            }
        }

        // ---- causal mask (raw units) + online softmax (base-2 domain) ----
        const bool full = (j0 + 64 <= q0 + w * 16);   // warp-uniform
        if (!full) {
            #pragma unroll
            for (int ri = 0; ri < 2; ri++) {
                const int tg = q0 + w * 16 + r + ri * 8;
                #pragma unroll
                for (int ni = 0; ni < 8; ni++)
                    #pragma unroll
                    for (int jj = 0; jj < 2; jj++) {
                        int sg = j0 + ni * 8 + 2 * c + jj;
                        if (sg > tg) sacc[ni][ri * 2 + jj] = -1e30f;
                    }
            }
        }
        #pragma unroll
        for (int ri = 0; ri < 2; ri++) {
            float rm = -1e30f;
            #pragma unroll
            for (int ni = 0; ni < 8; ni++) {
                rm = fmaxf(rm, sacc[ni][ri * 2 + 0]);
                rm = fmaxf(rm, sacc[ni][ri * 2 + 1]);
            }
            rm = fmaxf(rm, __shfl_xor_sync(0xffffffffu, rm, 1));
            rm = fmaxf(rm, __shfl_xor_sync(0xffffffffu, rm, 2));
            const float mn  = fmaxf(m_[ri], rm);
            const float mnC = mn * SCL2;
            // skip oacc rescale if no lane in warp raised its max this tile
            const unsigned upd = __ballot_sync(0xffffffffu, mn != m_[ri]);
            if (upd) {
                const float alpha = exp2f((m_[ri] - mn) * SCL2);
                #pragma unroll
                for (int ni = 0; ni < 8; ni++) {
                    oacc[ni][ri * 2 + 0] *= alpha;
                    oacc[ni][ri * 2 + 1] *= alpha;
                }
                l_[ri] *= alpha;
                m_[ri] = mn;
            }
            float ps = 0.0f;
            #pragma unroll
            for (int ni = 0; ni < 8; ni++) {
                #pragma unroll
                for (int jj = 0; jj < 2; jj++) {
                    float p = exp2f(fmaf(sacc[ni][ri * 2 + jj], SCL2, -mnC));
                    ps += p;
                    sacc[ni][ri * 2 + jj] = p;
                }
            }
            ps += __shfl_xor_sync(0xffffffffu, ps, 1);
            ps += __shfl_xor_sync(0xffffffffu, ps, 2);
            l_[ri] += ps;
        }

        // ---- O += P V in fp16: P packed from registers, V via ldmatrix.trans
        #pragma unroll
        for (int k4 = 0; k4 < 4; k4++) {
            uint32_t a[4];
            a[0] = pack_f16x2(sacc[2 * k4][0],     sacc[2 * k4][1]);
            a[1] = pack_f16x2(sacc[2 * k4][2],     sacc[2 * k4][3]);
            a[2] = pack_f16x2(sacc[2 * k4 + 1][0], sacc[2 * k4 + 1][1]);
            a[3] = pack_f16x2(sacc[2 * k4 + 1][2], sacc[2 * k4 + 1][3]);
            #pragma unroll
            for (int dp = 0; dp < 4; dp++) {
                uint32_t m0, m1, m2, m3;
                const uint32_t addr = vaddr0
                    + (uint32_t)(k4 * 16 * KROWB + dp * 32);
                LDMX4T(m0, m1, m2, m3, addr);
                mma_f16(oacc[2 * dp],     a, m0, m1);
                mma_f16(oacc[2 * dp + 1], a, m2, m3);
            }
        }
    }

    // ---- normalize, write out as fp16 (consumed by proj GEMM) ----
    const float inv0 = 1.0f / l_[0];
    const float inv1 = 1.0f / l_[1];
    const int row0g = q0 + w * 16 + r;
    #pragma unroll
    for (int ni = 0; ni < 8; ni++) {
        const int col = ni * 8 + 2 * c;
        *(uint32_t*)(O + obase + (size_t)row0g * D_ + col) =
            pack_f16x2(oacc[ni][0] * inv0, oacc[ni][1] * inv0);
        *(uint32_t*)(O + obase + (size_t)(row0g + 8) * D_ + col) =
            pack_f16x2(oacc[ni][2] * inv1, oacc[ni][3] * inv1);
    }
}

// ---------------- launcher ---------------------------------------------------
extern "C" void kernel_launch(void* const* d_in, const int* in_sizes, int n_in,
                              void* d_out, int out_size)
{
    const float* x   = (const float*)d_in[0];
    const float* Wq  = (const float*)d_in[1];
    const float* bq  = (const float*)d_in[2];
    const float* Wk  = (const float*)d_in[3];
    const float* bk  = (const float*)d_in[4];
    const float* Wv  = (const float*)d_in[5];
    const float* bv  = (const float*)d_in[6];
    const float* Wp  = (const float*)d_in[7];
    const float* bp  = (const float*)d_in[8];
    const float* W1  = (const float*)d_in[9];
    const float* b1  = (const float*)d_in[10];
    const float* W2  = (const float*)d_in[11];
    const float* b2  = (const float*)d_in[12];
    const float* g1  = (const float*)d_in[13];
    const float* be1 = (const float*)d_in[14];
    const float* g2  = (const float*)d_in[15];
    const float* be2 = (const float*)d_in[16];
    float* out = (float*)d_out;

    __half *h, *qkvb, *o, *h2, *ff, *wh;
    float *x1;
    cudaGetSymbolAddress((void**)&h,    g_h);
    cudaGetSymbolAddress((void**)&qkvb, g_qkvb);
    cudaGetSymbolAddress((void**)&o,    g_o);
    cudaGetSymbolAddress((void**)&x1,   g_x1);
    cudaGetSymbolAddress((void**)&h2,   g_h2);
    cudaGetSymbolAddress((void**)&ff,   g_ff);
    cudaGetSymbolAddress((void**)&wh,   g_wh);

    __half* wq = wh;                    // 262144 each
    __half* wk = wh + 262144;
    __half* wv = wh + 524288;
    __half* wp = wh + 786432;
    __half* w1 = wh + 1048576;          // 1048576 each
    __half* w2 = wh + 2097152;

    cudaFuncSetAttribute(attn_kernel,
                         cudaFuncAttributeMaxDynamicSharedMemorySize, ATTN_SMEM);
    cudaFuncSetAttribute(gemm_kernel,
                         cudaFuncAttributeMaxDynamicSharedMemorySize, GEMM_SMEM);

    // convert all weights to fp16 in one launch
    round_all_kernel<<<3072, 256>>>(Wq, Wk, Wv, Wp, W1, W2, wh);

    // LN1 (fp16 output)
    ln_kernel<<<BT_, 128>>>(x, g1, be1, h);

    // fused QKV projection -> fp16 buffer (head-stacked weights)
    gemm_kernel<<<dim3(LDQ / 128, BT_ / 128), 256, GEMM_SMEM>>>(
        h, D_, wq, wk, wv, D_ * DK_, DK_, bq, bk, bv,
        nullptr, nullptr, LDQ, D_, 0, 1, qkvb);

    // causal attention (all-fp16 mma, cp.async double-buffered)
    attn_kernel<<<dim3(T_ / 128, B_ * H_), 256, ATTN_SMEM>>>(qkvb, o);

    // output projection + residual (fp32 out to x1)
    dim3 g512(D_ / 128, BT_ / 128);
    gemm_kernel<<<g512, 256, GEMM_SMEM>>>(o, D_, wp, wp, wp, 64, D_,
                                          bp, bp, bp, x, x1, D_, D_, 0, 0,
                                          nullptr);

    // LN2 (fp16 output)
    ln_kernel<<<BT_, 128>>>(x1, g2, be2, h2);

    // FFN1 (relu, fp16 out) ; FFN2 (fp32 out + residual)
    gemm_kernel<<<dim3(DFF_ / 128, BT_ / 128), 256, GEMM_SMEM>>>(
        h2, D_, w1, w1, w1, 64, DFF_, b1, b1, b1,
        nullptr, nullptr, DFF_, D_, 1, 0, ff);
    gemm_kernel<<<g512, 256, GEMM_SMEM>>>(ff, DFF_, w2, w2, w2, 64, D_,
                                          b2, b2, b2, x1, out, D_, DFF_, 0, 0,
                                          nullptr);
}

// round 15
// speedup vs baseline: 2.4105x; 1.0623x over previous
#include <cuda_runtime.h>
#include <cuda_fp16.h>
#include <cstdint>

#define B_   4
#define T_   2048
#define D_   512
#define H_   8
#define DK_  64
#define BT_  (B_ * T_)
#define DFF_ 2048
#define LDQ  1536      // fused QKV col count (fp16 buffer)

// 0.125 * log2(e): folds the 1/sqrt(64) scale and base-e->base-2 conversion
#define SCL2 0.18033688011111772f

// ---------------- scratch (static device globals; no allocations) ----------
__device__ __half g_h  [BT_ * D_];          // LN1 out (fp16)
__device__ __half g_qkvb[BT_ * LDQ];        // fp16: Q | K | V each 512 cols
__device__ __half g_o  [BT_ * D_];          // attention out (fp16)
__device__ float  g_x1 [BT_ * D_];          // residual stream (fp32)
__device__ __half g_h2 [BT_ * D_];          // LN2 out (fp16)
__device__ __half g_ff [BT_ * DFF_];        // FFN1 out (fp16)
__device__ __half g_wh [4 * 1048576 + 2 * 4194304 / 2]; // fp16 weights (3.1M)

// ---------------- fp16 helpers ----------------------------------------------
// pack two floats into f16x2: lo <- x, hi <- y
__device__ __forceinline__ uint32_t pack_f16x2(float x, float y) {
    uint32_t u;
    asm("cvt.rn.f16x2.f32 %0, %1, %2;" : "=r"(u) : "f"(y), "f"(x));
    return u;
}

__device__ __forceinline__ void mma_f16(float* d, const uint32_t* a,
                                        uint32_t b0, uint32_t b1) {
    asm volatile(
        "mma.sync.aligned.m16n8k16.row.col.f32.f16.f16.f32 "
        "{%0,%1,%2,%3}, {%4,%5,%6,%7}, {%8,%9}, {%0,%1,%2,%3};"
        : "+f"(d[0]), "+f"(d[1]), "+f"(d[2]), "+f"(d[3])
        : "r"(a[0]), "r"(a[1]), "r"(a[2]), "r"(a[3]),
          "r"(b0), "r"(b1));
}

__device__ __forceinline__ void cp16(uint32_t dst_smem, const void* src) {
    asm volatile("cp.async.cg.shared.global [%0], [%1], 16;"
                 :: "r"(dst_smem), "l"(src) : "memory");
}
#define CP_COMMIT() asm volatile("cp.async.commit_group;" ::: "memory")

#define LDMX4(r0, r1, r2, r3, addr) \
    asm volatile("ldmatrix.sync.aligned.m8n8.x4.shared.b16 {%0,%1,%2,%3}, [%4];" \
        : "=r"(r0), "=r"(r1), "=r"(r2), "=r"(r3) : "r"(addr))
#define LDMX4T(r0, r1, r2, r3, addr) \
    asm volatile("ldmatrix.sync.aligned.m8n8.x4.trans.shared.b16 {%0,%1,%2,%3}, [%4];" \
        : "=r"(r0), "=r"(r1), "=r"(r2), "=r"(r3) : "r"(addr))

// ---------------- fused weight conversion to fp16 ---------------------------
__global__ __launch_bounds__(256) void round_all_kernel(
    const float* __restrict__ Wq, const float* __restrict__ Wk,
    const float* __restrict__ Wv, const float* __restrict__ Wp,
    const float* __restrict__ W1, const float* __restrict__ W2,
    __half* __restrict__ dst)
{
    const int i = blockIdx.x * 256 + threadIdx.x;   // float4 index, 0..786431
    const float4* src;
    int off;
    if      (i <  65536) { src = (const float4*)Wq; off = i; }
    else if (i < 131072) { src = (const float4*)Wk; off = i - 65536; }
    else if (i < 196608) { src = (const float4*)Wv; off = i - 131072; }
    else if (i < 262144) { src = (const float4*)Wp; off = i - 196608; }
    else if (i < 524288) { src = (const float4*)W1; off = i - 262144; }
    else                 { src = (const float4*)W2; off = i - 524288; }
    float4 v = src[off];
    uint2 p;
    p.x = pack_f16x2(v.x, v.y);
    p.y = pack_f16x2(v.z, v.w);
    ((uint2*)dst)[i] = p;
}

// ---------------- LayerNorm: one block per row of 512, fp16 out -------------
__global__ __launch_bounds__(128) void ln_kernel(
    const float* __restrict__ x, const float* __restrict__ g,
    const float* __restrict__ b, __half* __restrict__ out)
{
    const int row = blockIdx.x;
    const int tid = threadIdx.x;                 // 128 threads * float4 = 512
    float4 v = ((const float4*)(x + (size_t)row * D_))[tid];
    float s  = v.x + v.y + v.z + v.w;
    float ss = v.x * v.x + v.y * v.y + v.z * v.z + v.w * v.w;
    #pragma unroll
    for (int o = 16; o > 0; o >>= 1) {
        s  += __shfl_xor_sync(0xffffffffu, s,  o);
        ss += __shfl_xor_sync(0xffffffffu, ss, o);
    }
    __shared__ float sh_s[4], sh_ss[4];
    if ((tid & 31) == 0) { sh_s[tid >> 5] = s; sh_ss[tid >> 5] = ss; }
    __syncthreads();
    const float tot  = sh_s[0] + sh_s[1] + sh_s[2] + sh_s[3];
    const float tots = sh_ss[0] + sh_ss[1] + sh_ss[2] + sh_ss[3];
    const float mu   = tot  * (1.0f / D_);
    const float var  = tots * (1.0f / D_) - mu * mu;
    const float rstd = rsqrtf(var + 1e-5f);
    float4 gv = ((const float4*)g)[tid];
    float4 bv = ((const float4*)b)[tid];
    uint2 p;
    p.x = pack_f16x2((v.x - mu) * rstd * gv.x + bv.x,
                     (v.y - mu) * rstd * gv.y + bv.y);
    p.y = pack_f16x2((v.z - mu) * rstd * gv.z + bv.z,
                     (v.w - mu) * rstd * gv.w + bv.w);
    ((uint2*)(out + (size_t)row * D_))[tid] = p;
}

// ---------------- fp16 tensor-core GEMM, 128x128 tile, BK=64, 2-stage -------
// C[row, col] = sum_k A[row, k] * B(k, col) (+bias[col]) (+res[row,col])
//               (relu). Output: fp32 to C, or fp16 to Hout (stride ldc).
// mma m16n8k16, ldmatrix operand loads, cp.async double buffer.
// A tile 128x64 fp16 rows padded to 144B; B tile 64x128 fp16 rows 272B.
#define AROWB 144
#define BROWB 272
#define ASTAGEB (128 * AROWB)               // 18432 bytes
#define BSTAGEB (64 * BROWB)                // 17408 bytes
#define STAGEB  (ASTAGEB + BSTAGEB)         // 35840 bytes
#define GEMM_SMEM (2 * STAGEB)              // 71680 bytes

__global__ __launch_bounds__(256, 2) void gemm_kernel(
    const __half* __restrict__ A, int lda,
    const __half* __restrict__ W0, const __half* __restrict__ W1g,
    const __half* __restrict__ W2g, int cstride, int ldb,
    const float* __restrict__ b0, const float* __restrict__ b1g,
    const float* __restrict__ b2g,
    const float* __restrict__ res,
    float* __restrict__ C, int ldc,
    int K, int relu, int qkv,
    __half* __restrict__ Hout)
{
    extern __shared__ float smg[];
    const uint32_t sbase = (uint32_t)__cvta_generic_to_shared(smg);

    const int tid  = threadIdx.x;
    const int lane = tid & 31;
    const int wid  = tid >> 5;
    const int wm   = wid & 1;        // row block of 64
    const int wn   = wid >> 1;       // col block of 32
    const int row0 = blockIdx.y * 128;
    const int col0 = blockIdx.x * 128;

    const int grp = qkv ? (col0 >> 9) : 0;
    const __half* Wsel = (grp == 0) ? W0 : ((grp == 1) ? W1g : W2g);
    const float*  bsel = (grp == 0) ? b0 : ((grp == 1) ? b1g : b2g);
    const int col0g = qkv ? (col0 & 511) : col0;
    const __half* B0 = Wsel + (size_t)(col0g >> 6) * cstride; // cols [col0,+64)
    const __half* B1 = B0 + cstride;                          // cols [+64,+128)

    const int r = lane >> 2;         // 0..7
    const int c = lane & 3;          // 0..3

    float acc[4][4][4];
    #pragma unroll
    for (int mi = 0; mi < 4; mi++)
        #pragma unroll
        for (int ni = 0; ni < 4; ni++)
            acc[mi][ni][0] = acc[mi][ni][1] = acc[mi][ni][2] = acc[mi][ni][3] = 0.f;

    const int niter = K >> 6;        // BK = 64

    auto issue_stage = [&](int it) {
        const int k0 = it * 64;
        const uint32_t ab = sbase + (uint32_t)((it & 1) * STAGEB);
        const uint32_t bb = ab + ASTAGEB;
        #pragma unroll
        for (int i = 0; i < 4; i++) {
            int idx = tid + i * 256;            // A: 0..1023 16B chunks
            int m   = idx >> 3;                 // 0..127
            int ch  = idx & 7;                  // 8 fp16 per chunk
            cp16(ab + (uint32_t)(m * AROWB + ch * 16),
                 A + (size_t)(row0 + m) * lda + k0 + ch * 8);
        }
        #pragma unroll
        for (int i = 0; i < 4; i++) {
            int idx = tid + i * 256;            // B: 0..1023 16B chunks
            int kk  = idx >> 4;                 // 0..63
            int ch  = idx & 15;                 // col chunk
            const __half* src = (ch < 8)
                ? (B0 + (size_t)(k0 + kk) * ldb + ch * 8)
                : (B1 + (size_t)(k0 + kk) * ldb + (ch - 8) * 8);
            cp16(bb + (uint32_t)(kk * BROWB + ch * 16), src);
        }
        CP_COMMIT();
    };

    issue_stage(0);

    // ldmatrix per-thread offsets
    const int g8 = lane >> 3;
    const uint32_t apat = (uint32_t)(((lane & 7) + ((lane >> 3) & 1) * 8) * AROWB
                                     + (lane >> 4) * 16);
    const uint32_t bpat = (uint32_t)(((g8 & 1) * 8 + (lane & 7)) * BROWB
                                     + (g8 >> 1) * 16);

    for (int it = 0; it < niter; it++) {
        asm volatile("cp.async.wait_group 0;" ::: "memory");
        __syncthreads();
        if (it + 1 < niter) issue_stage(it + 1);

        const uint32_t acb = sbase + (uint32_t)((it & 1) * STAGEB);
        const uint32_t bcb = acb + ASTAGEB;

        #pragma unroll
        for (int ks = 0; ks < 4; ks++) {            // four k16 blocks
            uint32_t af[4][4];
            #pragma unroll
            for (int mi = 0; mi < 4; mi++) {
                const uint32_t addr = acb + apat
                    + (uint32_t)((wm * 64 + mi * 16) * AROWB + ks * 32);
                LDMX4(af[mi][0], af[mi][1], af[mi][2], af[mi][3], addr);
            }
            #pragma unroll
            for (int ni2 = 0; ni2 < 2; ni2++) {     // two n16 blocks
                uint32_t m0, m1, m2, m3;
                const uint32_t addr = bcb + bpat
                    + (uint32_t)(ks * 16 * BROWB + wn * 64 + ni2 * 32);
                LDMX4T(m0, m1, m2, m3, addr);
                #pragma unroll
                for (int mi = 0; mi < 4; mi++) {
                    mma_f16(acc[mi][ni2 * 2 + 0], af[mi], m0, m1);
                    mma_f16(acc[mi][ni2 * 2 + 1], af[mi], m2, m3);
                }
            }
        }
    }

    // --- epilogue: bias (+res) (relu); fp16 (Hout) or fp32 (C) stores ---
    #pragma unroll
    for (int mi = 0; mi < 4; mi++) {
        const int row_a = row0 + wm * 64 + mi * 16 + r;
        const size_t ro0 = (size_t)row_a * ldc;
        const size_t ro1 = (size_t)(row_a + 8) * ldc;
        #pragma unroll
        for (int ni = 0; ni < 4; ni++) {
            const int col_a = col0 + wn * 32 + ni * 8 + 2 * c;
            const int col_b = qkv ? (col_a & 511) : col_a;
            float2 bb = *(const float2*)(bsel + col_b);
            float v0 = acc[mi][ni][0] + bb.x;
            float v1 = acc[mi][ni][1] + bb.y;
            float v2 = acc[mi][ni][2] + bb.x;
            float v3 = acc[mi][ni][3] + bb.y;
            if (res) {
                float2 r0v = *(const float2*)(res + ro0 + col_a);
                float2 r1v = *(const float2*)(res + ro1 + col_a);
                v0 += r0v.x; v1 += r0v.y; v2 += r1v.x; v3 += r1v.y;
            }
            if (relu) {
                v0 = fmaxf(v0, 0.f); v1 = fmaxf(v1, 0.f);
                v2 = fmaxf(v2, 0.f); v3 = fmaxf(v3, 0.f);
            }
            if (Hout) {
                *(uint32_t*)(Hout + ro0 + col_a) = pack_f16x2(v0, v1);
                *(uint32_t*)(Hout + ro1 + col_a) = pack_f16x2(v2, v3);
            } else {
                *(float2*)(C + ro0 + col_a) = make_float2(v0, v1);
                *(float2*)(C + ro1 + col_a) = make_float2(v2, v3);
            }
        }
    }
}

// ---------------- fp16 tensor-core causal flash attention -------------------
// 128-key tiles (two 64-key halves per sync round). All mma fp16 m16n8k16
// (fp32 accum). Q frags in regs via ldmatrix; K via ldmatrix.x4, V via
// ldmatrix.x4.trans, P packed from softmax registers. 144B smem rows.
#define KROWB 144
#define KTILEB  (128 * KROWB)                    // K region bytes per stage
#define KVBYTES (2 * KTILEB)                     // K + V per stage = 36864
#define VOFF    KTILEB
#define ATTN_SMEM (2 * KVBYTES)                  // 73728 bytes

__global__ __launch_bounds__(256, 2) void attn_kernel(
    const __half* __restrict__ QKV, __half* __restrict__ O)
{
    extern __shared__ float sm[];
    char* smb = (char*)sm;
    const uint32_t sbase = (uint32_t)__cvta_generic_to_shared(sm);

    const int tid  = threadIdx.x;
    const int lane = tid & 31;
    const int w    = tid >> 5;       // warp id: query rows w*16..w*16+15
    const int r    = lane >> 2;      // 0..7
    const int c    = lane & 3;       // 0..3
    const int qt   = (gridDim.x - 1) - blockIdx.x;   // big tiles first
    const int bh   = blockIdx.y;
    const int b    = bh >> 3, h = bh & 7;
    const int q0   = qt * 128;
    const size_t base  = ((size_t)b * T_) * LDQ + h * DK_;
    const size_t obase = ((size_t)b * T_) * D_  + h * DK_;
    const __half* Qg = QKV + base;
    const __half* Kg = QKV + base + 512;
    const __half* Vg = QKV + base + 1024;

    auto issue_kv = [&](int kt) {       // kt indexes 128-key tiles
        const int j0 = kt * 128;
        const uint32_t kb = sbase + (uint32_t)(kt & 1) * KVBYTES;
        const uint32_t vb = kb + VOFF;
        #pragma unroll
        for (int i = 0; i < 4; i++) {
            int idx = tid + i * 256;           // 0..1023 16B chunks each
            int s   = idx >> 3;                // 0..127
            int ch  = idx & 7;
            cp16(kb + (uint32_t)(s * KROWB + ch * 16),
                 Kg + (size_t)(j0 + s) * LDQ + ch * 8);
            cp16(vb + (uint32_t)(s * KROWB + ch * 16),
                 Vg + (size_t)(j0 + s) * LDQ + ch * 8);
        }
        CP_COMMIT();
    };

    // ---- stage Q tile (fp16, 144B rows; fits in stage-0 K region) ----
    #pragma unroll
    for (int i = 0; i < 4; i++) {
        int idx = tid + i * 256;             // 0..1023 16B chunks
        int row = idx >> 3;                  // 0..127
        int ch  = idx & 7;
        uint4 qv = *(const uint4*)(Qg + (size_t)(q0 + row) * LDQ + ch * 8);
        *(uint4*)(smb + row * KROWB + ch * 16) = qv;
    }
    __syncthreads();
    // Q A-fragments: 4 k16-blocks via ldmatrix.x4 (non-trans)
    uint32_t qf[4][4];
    {
        const int qrow = w * 16 + (lane & 7) + ((lane >> 3) & 1) * 8;
        const uint32_t qoff = (uint32_t)(qrow * KROWB + (lane >> 4) * 16);
        #pragma unroll
        for (int kb4 = 0; kb4 < 4; kb4++) {
            const uint32_t addr = sbase + qoff + kb4 * 32;
            LDMX4(qf[kb4][0], qf[kb4][1], qf[kb4][2], qf[kb4][3], addr);
        }
    }
    __syncthreads();                      // all warps done reading Q
    issue_kv(0);

    // per-thread ldmatrix address patterns (within a tile region)
    const int g8 = lane >> 3;             // matrix group 0..3
    const uint32_t kpat = (uint32_t)(((lane & 7) + ((lane >> 3) & 1) * 8) * KROWB
                                     + (lane >> 4) * 16);
    const uint32_t vpat = (uint32_t)(((g8 & 1) * 8 + (lane & 7)) * KROWB
                                     + (g8 >> 1) * 16);

    // online-softmax state (m in raw score units)
    float m_[2] = {-1e30f, -1e30f};
    float l_[2] = {0.0f, 0.0f};
    float oacc[8][4];
    #pragma unroll
    for (int ni = 0; ni < 8; ni++)
        oacc[ni][0] = oacc[ni][1] = oacc[ni][2] = oacc[ni][3] = 0.0f;

    const int ntile = qt + 1;            // 128-key tiles 0..qt (causal)

    for (int kt = 0; kt < ntile; kt++) {
        asm volatile("cp.async.wait_group 0;" ::: "memory");
        __syncthreads();                      // tile kt visible to all
        if (kt + 1 < ntile) issue_kv(kt + 1); // prefetch (buffer safe: its
                                              // readers finished pre-sync)

        #pragma unroll
        for (int half = 0; half < 2; half++) {
            const int j0 = kt * 128 + half * 64;
            const uint32_t kaddr0 = sbase + (uint32_t)(kt & 1) * KVBYTES
                                  + (uint32_t)(half * 64 * KROWB) + kpat;
            const uint32_t vaddr0 = sbase + (uint32_t)(kt & 1) * KVBYTES + VOFF
                                  + (uint32_t)(half * 64 * KROWB) + vpat;

            // ---- S = Q K^T : fp16 m16n8k16, K B-frags via ldmatrix.x4 ----
            float sacc[8][4];
            #pragma unroll
            for (int ni = 0; ni < 8; ni++)
                sacc[ni][0] = sacc[ni][1] = sacc[ni][2] = sacc[ni][3] = 0.0f;
            #pragma unroll
            for (int kb4 = 0; kb4 < 4; kb4++) {
                #pragma unroll
                for (int ni2 = 0; ni2 < 4; ni2++) {
                    uint32_t k0r, k1r, k2r, k3r;
                    const uint32_t addr = kaddr0
                        + (uint32_t)(ni2 * 16 * KROWB + kb4 * 32);
                    LDMX4(k0r, k1r, k2r, k3r, addr);
                    mma_f16(sacc[2 * ni2],     qf[kb4], k0r, k2r);
                    mma_f16(sacc[2 * ni2 + 1], qf[kb4], k1r, k3r);
                }
            }

            // ---- causal mask (raw units) + online softmax (base-2) ----
            const bool full = (j0 + 64 <= q0 + w * 16);   // warp-uniform
            if (!full) {
                #pragma unroll
                for (int ri = 0; ri < 2; ri++) {
                    const int tg = q0 + w * 16 + r + ri * 8;
                    #pragma unroll
                    for (int ni = 0; ni < 8; ni++)
                        #pragma unroll
                        for (int jj = 0; jj < 2; jj++) {
                            int sg = j0 + ni * 8 + 2 * c + jj;
                            if (sg > tg) sacc[ni][ri * 2 + jj] = -1e30f;
                        }
                }
            }
            #pragma unroll
            for (int ri = 0; ri < 2; ri++) {
                float rm = -1e30f;
                #pragma unroll
                for (int ni = 0; ni < 8; ni++) {
                    rm = fmaxf(rm, sacc[ni][ri * 2 + 0]);
                    rm = fmaxf(rm, sacc[ni][ri * 2 + 1]);
                }
                rm = fmaxf(rm, __shfl_xor_sync(0xffffffffu, rm, 1));
                rm = fmaxf(rm, __shfl_xor_sync(0xffffffffu, rm, 2));
                const float mn  = fmaxf(m_[ri], rm);
                const float mnC = mn * SCL2;
                const unsigned upd = __ballot_sync(0xffffffffu, mn != m_[ri]);
                if (upd) {
                    const float alpha = exp2f((m_[ri] - mn) * SCL2);
                    #pragma unroll
                    for (int ni = 0; ni < 8; ni++) {
                        oacc[ni][ri * 2 + 0] *= alpha;
                        oacc[ni][ri * 2 + 1] *= alpha;
                    }
                    l_[ri] *= alpha;
                    m_[ri] = mn;
                }
                float ps = 0.0f;
                #pragma unroll
                for (int ni = 0; ni < 8; ni++) {
                    #pragma unroll
                    for (int jj = 0; jj < 2; jj++) {
                        float p = exp2f(fmaf(sacc[ni][ri * 2 + jj], SCL2, -mnC));
                        ps += p;
                        sacc[ni][ri * 2 + jj] = p;
                    }
                }
                ps += __shfl_xor_sync(0xffffffffu, ps, 1);
                ps += __shfl_xor_sync(0xffffffffu, ps, 2);
                l_[ri] += ps;
            }

            // ---- O += P V : P packed from registers, V via ldmatrix.trans --
            #pragma unroll
            for (int k4 = 0; k4 < 4; k4++) {
                uint32_t a[4];
                a[0] = pack_f16x2(sacc[2 * k4][0],     sacc[2 * k4][1]);
                a[1] = pack_f16x2(sacc[2 * k4][2],     sacc[2 * k4][3]);
                a[2] = pack_f16x2(sacc[2 * k4 + 1][0], sacc[2 * k4 + 1][1]);
                a[3] = pack_f16x2(sacc[2 * k4 + 1][2], sacc[2 * k4 + 1][3]);
                #pragma unroll
                for (int dp = 0; dp < 4; dp++) {
                    uint32_t m0, m1, m2, m3;
                    const uint32_t addr = vaddr0
                        + (uint32_t)(k4 * 16 * KROWB + dp * 32);
                    LDMX4T(m0, m1, m2, m3, addr);
                    mma_f16(oacc[2 * dp],     a, m0, m1);
                    mma_f16(oacc[2 * dp + 1], a, m2, m3);
                }
            }
        }
    }

    // ---- normalize, write out as fp16 (consumed by proj GEMM) ----
    const float inv0 = 1.0f / l_[0];
    const float inv1 = 1.0f / l_[1];
    const int row0g = q0 + w * 16 + r;
    #pragma unroll
    for (int ni = 0; ni < 8; ni++) {
        const int col = ni * 8 + 2 * c;
        *(uint32_t*)(O + obase + (size_t)row0g * D_ + col) =
            pack_f16x2(oacc[ni][0] * inv0, oacc[ni][1] * inv0);
        *(uint32_t*)(O + obase + (size_t)(row0g + 8) * D_ + col) =
            pack_f16x2(oacc[ni][2] * inv1, oacc[ni][3] * inv1);
    }
}

// ---------------- launcher ---------------------------------------------------
extern "C" void kernel_launch(void* const* d_in, const int* in_sizes, int n_in,
                              void* d_out, int out_size)
{
    const float* x   = (const float*)d_in[0];
    const float* Wq  = (const float*)d_in[1];
    const float* bq  = (const float*)d_in[2];
    const float* Wk  = (const float*)d_in[3];
    const float* bk  = (const float*)d_in[4];
    const float* Wv  = (const float*)d_in[5];
    const float* bv  = (const float*)d_in[6];
    const float* Wp  = (const float*)d_in[7];
    const float* bp  = (const float*)d_in[8];
    const float* W1  = (const float*)d_in[9];
    const float* b1  = (const float*)d_in[10];
    const float* W2  = (const float*)d_in[11];
    const float* b2  = (const float*)d_in[12];
    const float* g1  = (const float*)d_in[13];
    const float* be1 = (const float*)d_in[14];
    const float* g2  = (const float*)d_in[15];
    const float* be2 = (const float*)d_in[16];
    float* out = (float*)d_out;

    __half *h, *qkvb, *o, *h2, *ff, *wh;
    float *x1;
    cudaGetSymbolAddress((void**)&h,    g_h);
    cudaGetSymbolAddress((void**)&qkvb, g_qkvb);
    cudaGetSymbolAddress((void**)&o,    g_o);
    cudaGetSymbolAddress((void**)&x1,   g_x1);
    cudaGetSymbolAddress((void**)&h2,   g_h2);
    cudaGetSymbolAddress((void**)&ff,   g_ff);
    cudaGetSymbolAddress((void**)&wh,   g_wh);

    __half* wq = wh;                    // 262144 each
    __half* wk = wh + 262144;
    __half* wv = wh + 524288;
    __half* wp = wh + 786432;
    __half* w1 = wh + 1048576;          // 1048576 each
    __half* w2 = wh + 2097152;

    cudaFuncSetAttribute(attn_kernel,
                         cudaFuncAttributeMaxDynamicSharedMemorySize, ATTN_SMEM);
    cudaFuncSetAttribute(gemm_kernel,
                         cudaFuncAttributeMaxDynamicSharedMemorySize, GEMM_SMEM);

    // convert all weights to fp16 in one launch
    round_all_kernel<<<3072, 256>>>(Wq, Wk, Wv, Wp, W1, W2, wh);

    // LN1 (fp16 output)
    ln_kernel<<<BT_, 128>>>(x, g1, be1, h);

    // fused QKV projection -> fp16 buffer (head-stacked weights)
    gemm_kernel<<<dim3(LDQ / 128, BT_ / 128), 256, GEMM_SMEM>>>(
        h, D_, wq, wk, wv, D_ * DK_, DK_, bq, bk, bv,
        nullptr, nullptr, LDQ, D_, 0, 1, qkvb);

    // causal attention (all-fp16 mma, 128-key tiles, cp.async double-buffered)
    attn_kernel<<<dim3(T_ / 128, B_ * H_), 256, ATTN_SMEM>>>(qkvb, o);

    // output projection + residual (fp32 out to x1)
    dim3 g512(D_ / 128, BT_ / 128);
    gemm_kernel<<<g512, 256, GEMM_SMEM>>>(o, D_, wp, wp, wp, 64, D_,
                                          bp, bp, bp, x, x1, D_, D_, 0, 0,
                                          nullptr);

    // LN2 (fp16 output)
    ln_kernel<<<BT_, 128>>>(x1, g2, be2, h2);

    // FFN1 (relu, fp16 out) ; FFN2 (fp32 out + residual)
    gemm_kernel<<<dim3(DFF_ / 128, BT_ / 128), 256, GEMM_SMEM>>>(
        h2, D_, w1, w1, w1, 64, DFF_, b1, b1, b1,
        nullptr, nullptr, DFF_, D_, 1, 0, ff);
    gemm_kernel<<<g512, 256, GEMM_SMEM>>>(ff, DFF_, w2, w2, w2, 64, D_,
                                          b2, b2, b2, x1, out, D_, DFF_, 0, 0,
                                          nullptr);
}

// round 16
// speedup vs baseline: 2.4287x; 1.0075x over previous
#include <cuda_runtime.h>
#include <cuda_fp16.h>
#include <cstdint>

#define B_   4
#define T_   2048
#define D_   512
#define H_   8
#define DK_  64
#define BT_  (B_ * T_)
#define DFF_ 2048
#define LDQ  1536      // fused QKV col count (fp16 buffer)

// 0.125 * log2(e): folds the 1/sqrt(64) scale and base-e->base-2 conversion
#define SCL2 0.18033688011111772f

// ---------------- scratch (static device globals; no allocations) ----------
__device__ __half g_h  [BT_ * D_];          // LN1 out (fp16)
__device__ __half g_qkvb[BT_ * LDQ];        // fp16: Q | K | V each 512 cols
__device__ __half g_o  [BT_ * D_];          // attention out (fp16)
__device__ float  g_x1 [BT_ * D_];          // residual stream (fp32)
__device__ __half g_h2 [BT_ * D_];          // LN2 out (fp16)
__device__ __half g_ff [BT_ * DFF_];        // FFN1 out (fp16)
__device__ __half g_wh [4 * 1048576 + 2 * 4194304 / 2]; // fp16 weights (3.1M)

// ---------------- fp16 helpers ----------------------------------------------
// pack two floats into f16x2: lo <- x, hi <- y
__device__ __forceinline__ uint32_t pack_f16x2(float x, float y) {
    uint32_t u;
    asm("cvt.rn.f16x2.f32 %0, %1, %2;" : "=r"(u) : "f"(y), "f"(x));
    return u;
}

__device__ __forceinline__ void mma_f16(float* d, const uint32_t* a,
                                        uint32_t b0, uint32_t b1) {
    asm volatile(
        "mma.sync.aligned.m16n8k16.row.col.f32.f16.f16.f32 "
        "{%0,%1,%2,%3}, {%4,%5,%6,%7}, {%8,%9}, {%0,%1,%2,%3};"
        : "+f"(d[0]), "+f"(d[1]), "+f"(d[2]), "+f"(d[3])
        : "r"(a[0]), "r"(a[1]), "r"(a[2]), "r"(a[3]),
          "r"(b0), "r"(b1));
}

__device__ __forceinline__ void cp16(uint32_t dst_smem, const void* src) {
    asm volatile("cp.async.cg.shared.global [%0], [%1], 16;"
                 :: "r"(dst_smem), "l"(src) : "memory");
}
#define CP_COMMIT() asm volatile("cp.async.commit_group;" ::: "memory")

#define LDMX4(r0, r1, r2, r3, addr) \
    asm volatile("ldmatrix.sync.aligned.m8n8.x4.shared.b16 {%0,%1,%2,%3}, [%4];" \
        : "=r"(r0), "=r"(r1), "=r"(r2), "=r"(r3) : "r"(addr))
#define LDMX4T(r0, r1, r2, r3, addr) \
    asm volatile("ldmatrix.sync.aligned.m8n8.x4.trans.shared.b16 {%0,%1,%2,%3}, [%4];" \
        : "=r"(r0), "=r"(r1), "=r"(r2), "=r"(r3) : "r"(addr))

// ---------------- fused weight conversion to fp16 ---------------------------
__global__ __launch_bounds__(256) void round_all_kernel(
    const float* __restrict__ Wq, const float* __restrict__ Wk,
    const float* __restrict__ Wv, const float* __restrict__ Wp,
    const float* __restrict__ W1, const float* __restrict__ W2,
    __half* __restrict__ dst)
{
    const int i = blockIdx.x * 256 + threadIdx.x;   // float4 index, 0..786431
    const float4* src;
    int off;
    if      (i <  65536) { src = (const float4*)Wq; off = i; }
    else if (i < 131072) { src = (const float4*)Wk; off = i - 65536; }
    else if (i < 196608) { src = (const float4*)Wv; off = i - 131072; }
    else if (i < 262144) { src = (const float4*)Wp; off = i - 196608; }
    else if (i < 524288) { src = (const float4*)W1; off = i - 262144; }
    else                 { src = (const float4*)W2; off = i - 524288; }
    float4 v = src[off];
    uint2 p;
    p.x = pack_f16x2(v.x, v.y);
    p.y = pack_f16x2(v.z, v.w);
    ((uint2*)dst)[i] = p;
}

// ---------------- LayerNorm: one block per row of 512, fp16 out -------------
__global__ __launch_bounds__(128) void ln_kernel(
    const float* __restrict__ x, const float* __restrict__ g,
    const float* __restrict__ b, __half* __restrict__ out)
{
    const int row = blockIdx.x;
    const int tid = threadIdx.x;                 // 128 threads * float4 = 512
    float4 v = ((const float4*)(x + (size_t)row * D_))[tid];
    float s  = v.x + v.y + v.z + v.w;
    float ss = v.x * v.x + v.y * v.y + v.z * v.z + v.w * v.w;
    #pragma unroll
    for (int o = 16; o > 0; o >>= 1) {
        s  += __shfl_xor_sync(0xffffffffu, s,  o);
        ss += __shfl_xor_sync(0xffffffffu, ss, o);
    }
    __shared__ float sh_s[4], sh_ss[4];
    if ((tid & 31) == 0) { sh_s[tid >> 5] = s; sh_ss[tid >> 5] = ss; }
    __syncthreads();
    const float tot  = sh_s[0] + sh_s[1] + sh_s[2] + sh_s[3];
    const float tots = sh_ss[0] + sh_ss[1] + sh_ss[2] + sh_ss[3];
    const float mu   = tot  * (1.0f / D_);
    const float var  = tots * (1.0f / D_) - mu * mu;
    const float rstd = rsqrtf(var + 1e-5f);
    float4 gv = ((const float4*)g)[tid];
    float4 bv = ((const float4*)b)[tid];
    uint2 p;
    p.x = pack_f16x2((v.x - mu) * rstd * gv.x + bv.x,
                     (v.y - mu) * rstd * gv.y + bv.y);
    p.y = pack_f16x2((v.z - mu) * rstd * gv.z + bv.z,
                     (v.w - mu) * rstd * gv.w + bv.w);
    ((uint2*)(out + (size_t)row * D_))[tid] = p;
}

// ---------------- fp16 tensor-core GEMM, 128x128 tile, BK=64, 3-stage -------
// C[row, col] = sum_k A[row, k] * B(k, col) (+bias[col]) (+res[row,col])
//               (relu). Output: fp32 to C, or fp16 to Hout (stride ldc).
// mma m16n8k16, ldmatrix operand loads, cp.async 3-stage pipeline.
// A tile 128x64 fp16 rows padded to 144B; B tile 64x128 fp16 rows 272B.
#define AROWB 144
#define BROWB 272
#define ASTAGEB (128 * AROWB)               // 18432 bytes
#define BSTAGEB (64 * BROWB)                // 17408 bytes
#define STAGEB  (ASTAGEB + BSTAGEB)         // 35840 bytes
#define GEMM_SMEM (3 * STAGEB)              // 107520 bytes

__global__ __launch_bounds__(256, 2) void gemm_kernel(
    const __half* __restrict__ A, int lda,
    const __half* __restrict__ W0, const __half* __restrict__ W1g,
    const __half* __restrict__ W2g, int cstride, int ldb,
    const float* __restrict__ b0, const float* __restrict__ b1g,
    const float* __restrict__ b2g,
    const float* __restrict__ res,
    float* __restrict__ C, int ldc,
    int K, int relu, int qkv,
    __half* __restrict__ Hout)
{
    extern __shared__ float smg[];
    const uint32_t sbase = (uint32_t)__cvta_generic_to_shared(smg);

    const int tid  = threadIdx.x;
    const int lane = tid & 31;
    const int wid  = tid >> 5;
    const int wm   = wid & 1;        // row block of 64
    const int wn   = wid >> 1;       // col block of 32
    const int row0 = blockIdx.y * 128;
    const int col0 = blockIdx.x * 128;

    const int grp = qkv ? (col0 >> 9) : 0;
    const __half* Wsel = (grp == 0) ? W0 : ((grp == 1) ? W1g : W2g);
    const float*  bsel = (grp == 0) ? b0 : ((grp == 1) ? b1g : b2g);
    const int col0g = qkv ? (col0 & 511) : col0;
    const __half* B0 = Wsel + (size_t)(col0g >> 6) * cstride; // cols [col0,+64)
    const __half* B1 = B0 + cstride;                          // cols [+64,+128)

    const int r = lane >> 2;         // 0..7
    const int c = lane & 3;          // 0..3

    float acc[4][4][4];
    #pragma unroll
    for (int mi = 0; mi < 4; mi++)
        #pragma unroll
        for (int ni = 0; ni < 4; ni++)
            acc[mi][ni][0] = acc[mi][ni][1] = acc[mi][ni][2] = acc[mi][ni][3] = 0.f;

    const int niter = K >> 6;        // BK = 64

    auto issue_stage = [&](int it) {
        const int k0 = it * 64;
        const uint32_t ab = sbase + (uint32_t)((it % 3) * STAGEB);
        const uint32_t bb = ab + ASTAGEB;
        #pragma unroll
        for (int i = 0; i < 4; i++) {
            int idx = tid + i * 256;            // A: 0..1023 16B chunks
            int m   = idx >> 3;                 // 0..127
            int ch  = idx & 7;                  // 8 fp16 per chunk
            cp16(ab + (uint32_t)(m * AROWB + ch * 16),
                 A + (size_t)(row0 + m) * lda + k0 + ch * 8);
        }
        #pragma unroll
        for (int i = 0; i < 4; i++) {
            int idx = tid + i * 256;            // B: 0..1023 16B chunks
            int kk  = idx >> 4;                 // 0..63
            int ch  = idx & 15;                 // col chunk
            const __half* src = (ch < 8)
                ? (B0 + (size_t)(k0 + kk) * ldb + ch * 8)
                : (B1 + (size_t)(k0 + kk) * ldb + (ch - 8) * 8);
            cp16(bb + (uint32_t)(kk * BROWB + ch * 16), src);
        }
        CP_COMMIT();
    };

    issue_stage(0);
    if (niter > 1) issue_stage(1);

    // ldmatrix per-thread offsets
    const int g8 = lane >> 3;
    const uint32_t apat = (uint32_t)(((lane & 7) + ((lane >> 3) & 1) * 8) * AROWB
                                     + (lane >> 4) * 16);
    const uint32_t bpat = (uint32_t)(((g8 & 1) * 8 + (lane & 7)) * BROWB
                                     + (g8 >> 1) * 16);

    for (int it = 0; it < niter; it++) {
        if (it < niter - 1)
            asm volatile("cp.async.wait_group 1;" ::: "memory");
        else
            asm volatile("cp.async.wait_group 0;" ::: "memory");
        __syncthreads();
        if (it + 2 < niter) issue_stage(it + 2);

        const uint32_t acb = sbase + (uint32_t)((it % 3) * STAGEB);
        const uint32_t bcb = acb + ASTAGEB;

        #pragma unroll
        for (int ks = 0; ks < 4; ks++) {            // four k16 blocks
            uint32_t af[4][4];
            #pragma unroll
            for (int mi = 0; mi < 4; mi++) {
                const uint32_t addr = acb + apat
                    + (uint32_t)((wm * 64 + mi * 16) * AROWB + ks * 32);
                LDMX4(af[mi][0], af[mi][1], af[mi][2], af[mi][3], addr);
            }
            #pragma unroll
            for (int ni2 = 0; ni2 < 2; ni2++) {     // two n16 blocks
                uint32_t m0, m1, m2, m3;
                const uint32_t addr = bcb + bpat
                    + (uint32_t)(ks * 16 * BROWB + wn * 64 + ni2 * 32);
                LDMX4T(m0, m1, m2, m3, addr);
                #pragma unroll
                for (int mi = 0; mi < 4; mi++) {
                    mma_f16(acc[mi][ni2 * 2 + 0], af[mi], m0, m1);
                    mma_f16(acc[mi][ni2 * 2 + 1], af[mi], m2, m3);
                }
            }
        }
    }

    // --- epilogue: bias (+res) (relu); fp16 (Hout) or fp32 (C) stores ---
    #pragma unroll
    for (int mi = 0; mi < 4; mi++) {
        const int row_a = row0 + wm * 64 + mi * 16 + r;
        const size_t ro0 = (size_t)row_a * ldc;
        const size_t ro1 = (size_t)(row_a + 8) * ldc;
        #pragma unroll
        for (int ni = 0; ni < 4; ni++) {
            const int col_a = col0 + wn * 32 + ni * 8 + 2 * c;
            const int col_b = qkv ? (col_a & 511) : col_a;
            float2 bb = *(const float2*)(bsel + col_b);
            float v0 = acc[mi][ni][0] + bb.x;
            float v1 = acc[mi][ni][1] + bb.y;
            float v2 = acc[mi][ni][2] + bb.x;
            float v3 = acc[mi][ni][3] + bb.y;
            if (res) {
                float2 r0v = *(const float2*)(res + ro0 + col_a);
                float2 r1v = *(const float2*)(res + ro1 + col_a);
                v0 += r0v.x; v1 += r0v.y; v2 += r1v.x; v3 += r1v.y;
            }
            if (relu) {
                v0 = fmaxf(v0, 0.f); v1 = fmaxf(v1, 0.f);
                v2 = fmaxf(v2, 0.f); v3 = fmaxf(v3, 0.f);
            }
            if (Hout) {
                *(uint32_t*)(Hout + ro0 + col_a) = pack_f16x2(v0, v1);
                *(uint32_t*)(Hout + ro1 + col_a) = pack_f16x2(v2, v3);
            } else {
                *(float2*)(C + ro0 + col_a) = make_float2(v0, v1);
                *(float2*)(C + ro1 + col_a) = make_float2(v2, v3);
            }
        }
    }
}

// ---------------- fp16 tensor-core causal flash attention -------------------
// 128-key tiles (two 64-key halves per sync round). All mma fp16 m16n8k16
// (fp32 accum). Q frags in regs via ldmatrix; K via ldmatrix.x4, V via
// ldmatrix.x4.trans, P packed from softmax registers. l (softmax denom) is
// computed on the tensor pipe via a P x ones mma (constant B fragment, no
// ldmatrix): every output column equals the row sum, so no shuffles.
#define KROWB 144
#define KTILEB  (128 * KROWB)                    // K region bytes per stage
#define KVBYTES (2 * KTILEB)                     // K + V per stage = 36864
#define VOFF    KTILEB
#define ATTN_SMEM (2 * KVBYTES)                  // 73728 bytes

__global__ __launch_bounds__(256, 2) void attn_kernel(
    const __half* __restrict__ QKV, __half* __restrict__ O)
{
    extern __shared__ float sm[];
    char* smb = (char*)sm;
    const uint32_t sbase = (uint32_t)__cvta_generic_to_shared(sm);

    const int tid  = threadIdx.x;
    const int lane = tid & 31;
    const int w    = tid >> 5;       // warp id: query rows w*16..w*16+15
    const int r    = lane >> 2;      // 0..7
    const int c    = lane & 3;       // 0..3
    const int qt   = (gridDim.x - 1) - blockIdx.x;   // big tiles first
    const int bh   = blockIdx.y;
    const int b    = bh >> 3, h = bh & 7;
    const int q0   = qt * 128;
    const size_t base  = ((size_t)b * T_) * LDQ + h * DK_;
    const size_t obase = ((size_t)b * T_) * D_  + h * DK_;
    const __half* Qg = QKV + base;
    const __half* Kg = QKV + base + 512;
    const __half* Vg = QKV + base + 1024;
    const uint32_t ONES = 0x3C003C00u;   // fp16 {1.0, 1.0}

    auto issue_kv = [&](int kt) {       // kt indexes 128-key tiles
        const int j0 = kt * 128;
        const uint32_t kb = sbase + (uint32_t)(kt & 1) * KVBYTES;
        const uint32_t vb = kb + VOFF;
        #pragma unroll
        for (int i = 0; i < 4; i++) {
            int idx = tid + i * 256;           // 0..1023 16B chunks each
            int s   = idx >> 3;                // 0..127
            int ch  = idx & 7;
            cp16(kb + (uint32_t)(s * KROWB + ch * 16),
                 Kg + (size_t)(j0 + s) * LDQ + ch * 8);
            cp16(vb + (uint32_t)(s * KROWB + ch * 16),
                 Vg + (size_t)(j0 + s) * LDQ + ch * 8);
        }
        CP_COMMIT();
    };

    // ---- stage Q tile (fp16, 144B rows; fits in stage-0 K region) ----
    #pragma unroll
    for (int i = 0; i < 4; i++) {
        int idx = tid + i * 256;             // 0..1023 16B chunks
        int row = idx >> 3;                  // 0..127
        int ch  = idx & 7;
        uint4 qv = *(const uint4*)(Qg + (size_t)(q0 + row) * LDQ + ch * 8);
        *(uint4*)(smb + row * KROWB + ch * 16) = qv;
    }
    __syncthreads();
    // Q A-fragments: 4 k16-blocks via ldmatrix.x4 (non-trans)
    uint32_t qf[4][4];
    {
        const int qrow = w * 16 + (lane & 7) + ((lane >> 3) & 1) * 8;
        const uint32_t qoff = (uint32_t)(qrow * KROWB + (lane >> 4) * 16);
        #pragma unroll
        for (int kb4 = 0; kb4 < 4; kb4++) {
            const uint32_t addr = sbase + qoff + kb4 * 32;
            LDMX4(qf[kb4][0], qf[kb4][1], qf[kb4][2], qf[kb4][3], addr);
        }
    }
    __syncthreads();                      // all warps done reading Q
    issue_kv(0);

    // per-thread ldmatrix address patterns (within a tile region)
    const int g8 = lane >> 3;             // matrix group 0..3
    const uint32_t kpat = (uint32_t)(((lane & 7) + ((lane >> 3) & 1) * 8) * KROWB
                                     + (lane >> 4) * 16);
    const uint32_t vpat = (uint32_t)(((g8 & 1) * 8 + (lane & 7)) * KROWB
                                     + (g8 >> 1) * 16);

    // online-softmax state (m in raw score units)
    float m_[2] = {-1e30f, -1e30f};
    float l_[2] = {0.0f, 0.0f};
    float oacc[8][4];
    #pragma unroll
    for (int ni = 0; ni < 8; ni++)
        oacc[ni][0] = oacc[ni][1] = oacc[ni][2] = oacc[ni][3] = 0.0f;

    const int ntile = qt + 1;            // 128-key tiles 0..qt (causal)

    for (int kt = 0; kt < ntile; kt++) {
        asm volatile("cp.async.wait_group 0;" ::: "memory");
        __syncthreads();                      // tile kt visible to all
        if (kt + 1 < ntile) issue_kv(kt + 1); // prefetch (buffer safe: its
                                              // readers finished pre-sync)

        #pragma unroll
        for (int half = 0; half < 2; half++) {
            const int j0 = kt * 128 + half * 64;
            const uint32_t kaddr0 = sbase + (uint32_t)(kt & 1) * KVBYTES
                                  + (uint32_t)(half * 64 * KROWB) + kpat;
            const uint32_t vaddr0 = sbase + (uint32_t)(kt & 1) * KVBYTES + VOFF
                                  + (uint32_t)(half * 64 * KROWB) + vpat;

            // ---- S = Q K^T : fp16 m16n8k16, K B-frags via ldmatrix.x4 ----
            float sacc[8][4];
            #pragma unroll
            for (int ni = 0; ni < 8; ni++)
                sacc[ni][0] = sacc[ni][1] = sacc[ni][2] = sacc[ni][3] = 0.0f;
            #pragma unroll
            for (int kb4 = 0; kb4 < 4; kb4++) {
                #pragma unroll
                for (int ni2 = 0; ni2 < 4; ni2++) {
                    uint32_t k0r, k1r, k2r, k3r;
                    const uint32_t addr = kaddr0
                        + (uint32_t)(ni2 * 16 * KROWB + kb4 * 32);
                    LDMX4(k0r, k1r, k2r, k3r, addr);
                    mma_f16(sacc[2 * ni2],     qf[kb4], k0r, k2r);
                    mma_f16(sacc[2 * ni2 + 1], qf[kb4], k1r, k3r);
                }
            }

            // ---- causal mask (raw units) + online softmax (base-2) ----
            const bool full = (j0 + 64 <= q0 + w * 16);   // warp-uniform
            if (!full) {
                #pragma unroll
                for (int ri = 0; ri < 2; ri++) {
                    const int tg = q0 + w * 16 + r + ri * 8;
                    #pragma unroll
                    for (int ni = 0; ni < 8; ni++)
                        #pragma unroll
                        for (int jj = 0; jj < 2; jj++) {
                            int sg = j0 + ni * 8 + 2 * c + jj;
                            if (sg > tg) sacc[ni][ri * 2 + jj] = -1e30f;
                        }
                }
            }
            #pragma unroll
            for (int ri = 0; ri < 2; ri++) {
                float rm = -1e30f;
                #pragma unroll
                for (int ni = 0; ni < 8; ni++) {
                    rm = fmaxf(rm, sacc[ni][ri * 2 + 0]);
                    rm = fmaxf(rm, sacc[ni][ri * 2 + 1]);
                }
                rm = fmaxf(rm, __shfl_xor_sync(0xffffffffu, rm, 1));
                rm = fmaxf(rm, __shfl_xor_sync(0xffffffffu, rm, 2));
                const float mn  = fmaxf(m_[ri], rm);
                const float mnC = mn * SCL2;
                const unsigned upd = __ballot_sync(0xffffffffu, mn != m_[ri]);
                if (upd) {
                    const float alpha = exp2f((m_[ri] - mn) * SCL2);
                    #pragma unroll
                    for (int ni = 0; ni < 8; ni++) {
                        oacc[ni][ri * 2 + 0] *= alpha;
                        oacc[ni][ri * 2 + 1] *= alpha;
                    }
                    l_[ri] *= alpha;
                    m_[ri] = mn;
                }
                #pragma unroll
                for (int ni = 0; ni < 8; ni++) {
                    #pragma unroll
                    for (int jj = 0; jj < 2; jj++) {
                        sacc[ni][ri * 2 + jj] =
                            exp2f(fmaf(sacc[ni][ri * 2 + jj], SCL2, -mnC));
                    }
                }
            }

            // ---- O += P V ; l += P*ones (tensor pipe, no shuffles) --------
            float lacc[4] = {0.f, 0.f, 0.f, 0.f};
            #pragma unroll
            for (int k4 = 0; k4 < 4; k4++) {
                uint32_t a[4];
                a[0] = pack_f16x2(sacc[2 * k4][0],     sacc[2 * k4][1]);
                a[1] = pack_f16x2(sacc[2 * k4][2],     sacc[2 * k4][3]);
                a[2] = pack_f16x2(sacc[2 * k4 + 1][0], sacc[2 * k4 + 1][1]);
                a[3] = pack_f16x2(sacc[2 * k4 + 1][2], sacc[2 * k4 + 1][3]);
                mma_f16(lacc, a, ONES, ONES);
                #pragma unroll
                for (int dp = 0; dp < 4; dp++) {
                    uint32_t m0, m1, m2, m3;
                    const uint32_t addr = vaddr0
                        + (uint32_t)(k4 * 16 * KROWB + dp * 32);
                    LDMX4T(m0, m1, m2, m3, addr);
                    mma_f16(oacc[2 * dp],     a, m0, m1);
                    mma_f16(oacc[2 * dp + 1], a, m2, m3);
                }
            }
            l_[0] += lacc[0];
            l_[1] += lacc[2];
        }
    }

    // ---- normalize, write out as fp16 (consumed by proj GEMM) ----
    const float inv0 = 1.0f / l_[0];
    const float inv1 = 1.0f / l_[1];
    const int row0g = q0 + w * 16 + r;
    #pragma unroll
    for (int ni = 0; ni < 8; ni++) {
        const int col = ni * 8 + 2 * c;
        *(uint32_t*)(O + obase + (size_t)row0g * D_ + col) =
            pack_f16x2(oacc[ni][0] * inv0, oacc[ni][1] * inv0);
        *(uint32_t*)(O + obase + (size_t)(row0g + 8) * D_ + col) =
            pack_f16x2(oacc[ni][2] * inv1, oacc[ni][3] * inv1);
    }
}

// ---------------- launcher ---------------------------------------------------
extern "C" void kernel_launch(void* const* d_in, const int* in_sizes, int n_in,
                              void* d_out, int out_size)
{
    const float* x   = (const float*)d_in[0];
    const float* Wq  = (const float*)d_in[1];
    const float* bq  = (const float*)d_in[2];
    const float* Wk  = (const float*)d_in[3];
    const float* bk  = (const float*)d_in[4];
    const float* Wv  = (const float*)d_in[5];
    const float* bv  = (const float*)d_in[6];
    const float* Wp  = (const float*)d_in[7];
    const float* bp  = (const float*)d_in[8];
    const float* W1  = (const float*)d_in[9];
    const float* b1  = (const float*)d_in[10];
    const float* W2  = (const float*)d_in[11];
    const float* b2  = (const float*)d_in[12];
    const float* g1  = (const float*)d_in[13];
    const float* be1 = (const float*)d_in[14];
    const float* g2  = (const float*)d_in[15];
    const float* be2 = (const float*)d_in[16];
    float* out = (float*)d_out;

    __half *h, *qkvb, *o, *h2, *ff, *wh;
    float *x1;
    cudaGetSymbolAddress((void**)&h,    g_h);
    cudaGetSymbolAddress((void**)&qkvb, g_qkvb);
    cudaGetSymbolAddress((void**)&o,    g_o);
    cudaGetSymbolAddress((void**)&x1,   g_x1);
    cudaGetSymbolAddress((void**)&h2,   g_h2);
    cudaGetSymbolAddress((void**)&ff,   g_ff);
    cudaGetSymbolAddress((void**)&wh,   g_wh);

    __half* wq = wh;                    // 262144 each
    __half* wk = wh + 262144;
    __half* wv = wh + 524288;
    __half* wp = wh + 786432;
    __half* w1 = wh + 1048576;          // 1048576 each
    __half* w2 = wh + 2097152;

    cudaFuncSetAttribute(attn_kernel,
                         cudaFuncAttributeMaxDynamicSharedMemorySize, ATTN_SMEM);
    cudaFuncSetAttribute(gemm_kernel,
                         cudaFuncAttributeMaxDynamicSharedMemorySize, GEMM_SMEM);

    // convert all weights to fp16 in one launch
    round_all_kernel<<<3072, 256>>>(Wq, Wk, Wv, Wp, W1, W2, wh);

    // LN1 (fp16 output)
    ln_kernel<<<BT_, 128>>>(x, g1, be1, h);

    // fused QKV projection -> fp16 buffer (head-stacked weights)
    gemm_kernel<<<dim3(LDQ / 128, BT_ / 128), 256, GEMM_SMEM>>>(
        h, D_, wq, wk, wv, D_ * DK_, DK_, bq, bk, bv,
        nullptr, nullptr, LDQ, D_, 0, 1, qkvb);

    // causal attention (all-fp16 mma, 128-key tiles, cp.async double-buffered)
    attn_kernel<<<dim3(T_ / 128, B_ * H_), 256, ATTN_SMEM>>>(qkvb, o);

    // output projection + residual (fp32 out to x1)
    dim3 g512(D_ / 128, BT_ / 128);
    gemm_kernel<<<g512, 256, GEMM_SMEM>>>(o, D_, wp, wp, wp, 64, D_,
                                          bp, bp, bp, x, x1, D_, D_, 0, 0,
                                          nullptr);

    // LN2 (fp16 output)
    ln_kernel<<<BT_, 128>>>(x1, g2, be2, h2);

    // FFN1 (relu, fp16 out) ; FFN2 (fp32 out + residual)
    gemm_kernel<<<dim3(DFF_ / 128, BT_ / 128), 256, GEMM_SMEM>>>(
        h2, D_, w1, w1, w1, 64, DFF_, b1, b1, b1,
        nullptr, nullptr, DFF_, D_, 1, 0, ff);
    gemm_kernel<<<g512, 256, GEMM_SMEM>>>(ff, DFF_, w2, w2, w2, 64, D_,
                                          b2, b2, b2, x1, out, D_, DFF_, 0, 0,
                                          nullptr);
}